// round 10
// baseline (speedup 1.0000x reference)
#include <cuda_runtime.h>
#include <math.h>
#include <stdint.h>

#define BSZ 512
#define ENT 512
#define SEQN 64
#define DK 32
#define DF 256
#define DIN 1024
#define NGATE 128
#define ENP1 513

// ----------------------------- static scratch --------------------------------
__device__ float g_key[(size_t)BSZ * ENT * DK];
__device__ int   g_removed[(size_t)BSZ * ENP1];
__device__ float g_selemb[(size_t)SEQN * BSZ * DK];
__device__ float g_base[(size_t)BSZ * DF];
__device__ float g_W2[(size_t)DF * DF];      // tf32 BITS
__device__ float g_c2[DF];
__device__ uint32_t g_e1t[32 * 256];         // e1w tf32 bits
__device__ uint32_t g_q2t[256 * 32];         // q2w tf32 bits
__device__ float g_gx[(size_t)SEQN * BSZ * NGATE];

// ----------------------------- helpers ---------------------------------------
__device__ __forceinline__ float wredsum(float v) {
#pragma unroll
    for (int o = 16; o; o >>= 1) v += __shfl_xor_sync(0xffffffffu, v, o);
    return v;
}
__device__ __forceinline__ uint32_t f2tf(float f) {
    uint32_t r;
    asm("cvt.rna.tf32.f32 %0, %1;" : "=r"(r) : "f"(f));
    return r;
}
__device__ __forceinline__ void mma_tf32(float* c, uint32_t a0, uint32_t a1, uint32_t a2,
                                         uint32_t a3, uint32_t b0, uint32_t b1) {
    asm volatile(
        "mma.sync.aligned.m16n8k8.row.col.f32.tf32.tf32.f32 "
        "{%0,%1,%2,%3},{%4,%5,%6,%7},{%8,%9},{%0,%1,%2,%3};"
        : "+f"(c[0]), "+f"(c[1]), "+f"(c[2]), "+f"(c[3])
        : "r"(a0), "r"(a1), "r"(a2), "r"(a3), "r"(b0), "r"(b1));
}

// --------------- k_pre: merged [ar;e2w;e2b] @ q1w -----------------------------
// rows <512 -> g_base (+q1b) ; rows 512..767 -> g_W2 tf32 bits ; row 768 -> g_c2
__global__ void __launch_bounds__(256) k_pre(const float* __restrict__ ar,
                                             const float* __restrict__ e2w,
                                             const float* __restrict__ e2b,
                                             const float* __restrict__ q1w,
                                             const float* __restrict__ q1b) {
    __shared__ uint32_t As[64][36];
    __shared__ uint32_t Bs[32][68];
    const int t = threadIdx.x;
    const int wid = t >> 5, lane = t & 31;
    const int gid = lane >> 2, tig = lane & 3;
    const int warpM = wid & 3, warpN = wid >> 2;
    const int m0 = blockIdx.x * 64;
    const int n0 = blockIdx.y * 64;

    auto ldA = [&](int r, int kof) -> float4 {
        if (r < 512) return *(const float4*)&ar[(size_t)r * 1024 + kof];
        if (r < 768) return *(const float4*)&e2w[(size_t)(r - 512) * 1024 + kof];
        if (r == 768) return *(const float4*)&e2b[kof];
        return make_float4(0.f, 0.f, 0.f, 0.f);
    };
    const int ar0 = t >> 3;
    const int ak = (t & 7) * 4;
    const int br0 = t >> 4;
    const int bn = (t & 15) * 4;

    float4 pa0 = ldA(m0 + ar0, ak);
    float4 pa1 = ldA(m0 + ar0 + 32, ak);
    float4 pb0 = *(const float4*)&q1w[(size_t)br0 * 256 + n0 + bn];
    float4 pb1 = *(const float4*)&q1w[(size_t)(br0 + 16) * 256 + n0 + bn];

    float acc[4][4];
#pragma unroll
    for (int j = 0; j < 4; j++) {
        acc[j][0] = 0.f; acc[j][1] = 0.f; acc[j][2] = 0.f; acc[j][3] = 0.f;
    }

    for (int ch = 0; ch < 32; ch++) {
        __syncthreads();
        As[ar0][ak + 0] = f2tf(pa0.x); As[ar0][ak + 1] = f2tf(pa0.y);
        As[ar0][ak + 2] = f2tf(pa0.z); As[ar0][ak + 3] = f2tf(pa0.w);
        As[ar0 + 32][ak + 0] = f2tf(pa1.x); As[ar0 + 32][ak + 1] = f2tf(pa1.y);
        As[ar0 + 32][ak + 2] = f2tf(pa1.z); As[ar0 + 32][ak + 3] = f2tf(pa1.w);
        Bs[br0][bn + 0] = f2tf(pb0.x); Bs[br0][bn + 1] = f2tf(pb0.y);
        Bs[br0][bn + 2] = f2tf(pb0.z); Bs[br0][bn + 3] = f2tf(pb0.w);
        Bs[br0 + 16][bn + 0] = f2tf(pb1.x); Bs[br0 + 16][bn + 1] = f2tf(pb1.y);
        Bs[br0 + 16][bn + 2] = f2tf(pb1.z); Bs[br0 + 16][bn + 3] = f2tf(pb1.w);
        if (ch + 1 < 32) {
            int k0 = (ch + 1) * 32;
            pa0 = ldA(m0 + ar0, k0 + ak);
            pa1 = ldA(m0 + ar0 + 32, k0 + ak);
            pb0 = *(const float4*)&q1w[(size_t)(k0 + br0) * 256 + n0 + bn];
            pb1 = *(const float4*)&q1w[(size_t)(k0 + br0 + 16) * 256 + n0 + bn];
        }
        __syncthreads();
#pragma unroll
        for (int kk = 0; kk < 32; kk += 8) {
            uint32_t a0 = As[warpM * 16 + gid][kk + tig];
            uint32_t a1 = As[warpM * 16 + gid + 8][kk + tig];
            uint32_t a2 = As[warpM * 16 + gid][kk + tig + 4];
            uint32_t a3 = As[warpM * 16 + gid + 8][kk + tig + 4];
#pragma unroll
            for (int j = 0; j < 4; j++) {
                int nb = warpN * 32 + j * 8;
                uint32_t b0 = Bs[kk + tig][nb + gid];
                uint32_t b1 = Bs[kk + tig + 4][nb + gid];
                mma_tf32(acc[j], a0, a1, a2, a3, b0, b1);
            }
        }
    }
#pragma unroll
    for (int j = 0; j < 4; j++) {
        int cb = n0 + warpN * 32 + j * 8 + tig * 2;
#pragma unroll
        for (int h = 0; h < 2; h++) {
            int m = m0 + warpM * 16 + gid + h * 8;
            float v0 = acc[j][h * 2], v1 = acc[j][h * 2 + 1];
            if (m < 512) {
                g_base[(size_t)m * 256 + cb] = v0 + q1b[cb];
                g_base[(size_t)m * 256 + cb + 1] = v1 + q1b[cb + 1];
            } else if (m < 768) {
                ((uint32_t*)g_W2)[(size_t)(m - 512) * 256 + cb] = f2tf(v0);
                ((uint32_t*)g_W2)[(size_t)(m - 512) * 256 + cb + 1] = f2tf(v1);
            } else if (m == 768) {
                g_c2[cb] = v0;
                g_c2[cb + 1] = v1;
            }
        }
    }
}

// --------------- k_key: full key GEMM, B staged once --------------------------
#define KEY_SMEM (128 * 68 * 4 + 256 * 36 * 4)
__global__ void __launch_bounds__(256) k_key(const float* __restrict__ ent,
                                             const float* __restrict__ kw,
                                             const float* __restrict__ kb,
                                             const float* __restrict__ endv,
                                             const int* __restrict__ en_arr) {
    extern __shared__ uint32_t dsm[];
    uint32_t* As = dsm;               // [128][68]
    uint32_t* Bsm = dsm + 128 * 68;   // [256][36]
    const int t = threadIdx.x;
    const int wid = t >> 5, lane = t & 31;
    const int gid = lane >> 2, tig = lane & 3;
    const size_t m0 = (size_t)blockIdx.x * 128;
    const int en = en_arr[m0 >> 9];

#pragma unroll
    for (int p = 0; p < 8; p++) {
        int idx = t + p * 256;
        int r = idx >> 3, c4 = (idx & 7) * 4;
        float4 v = *(const float4*)&kw[(size_t)r * 32 + c4];
        Bsm[r * 36 + c4 + 0] = f2tf(v.x); Bsm[r * 36 + c4 + 1] = f2tf(v.y);
        Bsm[r * 36 + c4 + 2] = f2tf(v.z); Bsm[r * 36 + c4 + 3] = f2tf(v.w);
    }
    float4 pa[8];
#pragma unroll
    for (int p = 0; p < 8; p++) {
        int idx = t + p * 256;
        int r = idx >> 4, c4 = (idx & 15) * 4;
        pa[p] = *(const float4*)&ent[(m0 + r) * 256 + c4];
    }
    float acc[4][4];
#pragma unroll
    for (int j = 0; j < 4; j++) {
        acc[j][0] = 0.f; acc[j][1] = 0.f; acc[j][2] = 0.f; acc[j][3] = 0.f;
    }
    for (int ch = 0; ch < 4; ch++) {
        __syncthreads();
#pragma unroll
        for (int p = 0; p < 8; p++) {
            int idx = t + p * 256;
            int r = idx >> 4, c4 = (idx & 15) * 4;
            As[r * 68 + c4 + 0] = f2tf(pa[p].x); As[r * 68 + c4 + 1] = f2tf(pa[p].y);
            As[r * 68 + c4 + 2] = f2tf(pa[p].z); As[r * 68 + c4 + 3] = f2tf(pa[p].w);
        }
        if (ch + 1 < 4) {
#pragma unroll
            for (int p = 0; p < 8; p++) {
                int idx = t + p * 256;
                int r = idx >> 4, c4 = (idx & 15) * 4;
                pa[p] = *(const float4*)&ent[(m0 + r) * 256 + (ch + 1) * 64 + c4];
            }
        }
        __syncthreads();
#pragma unroll
        for (int kk = 0; kk < 64; kk += 8) {
            int kg = ch * 64 + kk;
            uint32_t a0 = As[(wid * 16 + gid) * 68 + kk + tig];
            uint32_t a1 = As[(wid * 16 + gid + 8) * 68 + kk + tig];
            uint32_t a2 = As[(wid * 16 + gid) * 68 + kk + tig + 4];
            uint32_t a3 = As[(wid * 16 + gid + 8) * 68 + kk + tig + 4];
#pragma unroll
            for (int j = 0; j < 4; j++) {
                uint32_t b0 = Bsm[(kg + tig) * 36 + j * 8 + gid];
                uint32_t b1 = Bsm[(kg + tig + 4) * 36 + j * 8 + gid];
                mma_tf32(acc[j], a0, a1, a2, a3, b0, b1);
            }
        }
    }
#pragma unroll
    for (int j = 0; j < 4; j++) {
        int cb = j * 8 + tig * 2;
        float b0 = kb[cb], b1 = kb[cb + 1];
        float e0 = endv[cb], e1 = endv[cb + 1];
#pragma unroll
        for (int h = 0; h < 2; h++) {
            size_t m = m0 + wid * 16 + gid + h * 8;
            if ((int)(m & 511) == en) {
                g_key[m * 32 + cb] = e0;
                g_key[m * 32 + cb + 1] = e1;
            } else {
                g_key[m * 32 + cb] = acc[j][h * 2] + b0;
                g_key[m * 32 + cb + 1] = acc[j][h * 2 + 1] + b1;
            }
        }
    }
}

// --------------- selkey gathered GEMM + removed scatter + pooled-emb scan ------
__global__ void __launch_bounds__(256) k_selkey(const float* __restrict__ ent,
                                                const float* __restrict__ kw,
                                                const float* __restrict__ kb,
                                                const int* __restrict__ sel,
                                                const int* __restrict__ en_arr,
                                                const int* __restrict__ selnum) {
    __shared__ uint32_t AS[64 * 68];
    __shared__ uint32_t BS[64 * 36];
    __shared__ int ssh[64];
    __shared__ int inc[64];
    const int t = threadIdx.x;
    const int b = blockIdx.x;
    const int wid = t >> 5, lane = t & 31;
    const int gid = lane >> 2, tig = lane & 3;
    const int warpM = wid & 3, warpN = wid >> 2;
    const int en = en_arr[b];

    if (t < 64) ssh[t] = sel[b * SEQN + t];
    for (int n = t; n < ENP1; n += 256) g_removed[(size_t)b * ENP1 + n] = 65;
    __syncthreads();
    if (t < 64) atomicMin(&g_removed[(size_t)b * ENP1 + ssh[t]], t + 1);
    if (t < 64) {
        int sj = ssh[t];
        bool first = true, endf = (sj == en);
        for (int k = 0; k < t; k++) {
            int sk = ssh[k];
            if (sk == sj) first = false;
            if (sk == en) endf = true;
        }
        inc[t] = (first && !endf) ? 1 : 0;
    }

    float acc[2][4];
    acc[0][0] = acc[0][1] = acc[0][2] = acc[0][3] = 0.f;
    acc[1][0] = acc[1][1] = acc[1][2] = acc[1][3] = 0.f;

    for (int ch = 0; ch < 4; ch++) {
        int k0 = ch * 64;
        __syncthreads();
#pragma unroll
        for (int p = 0; p < 4; p++) {
            int idx = t + p * 256;
            int r = idx >> 4, c4 = (idx & 15) * 4;
            float4 v = *(const float4*)&ent[((size_t)b * ENT + ssh[r]) * 256 + k0 + c4];
            AS[r * 68 + c4 + 0] = f2tf(v.x);
            AS[r * 68 + c4 + 1] = f2tf(v.y);
            AS[r * 68 + c4 + 2] = f2tf(v.z);
            AS[r * 68 + c4 + 3] = f2tf(v.w);
        }
#pragma unroll
        for (int p = 0; p < 2; p++) {
            int idx = t + p * 256;
            int r = idx >> 3, c4 = (idx & 7) * 4;
            float4 v = *(const float4*)&kw[(size_t)(k0 + r) * 32 + c4];
            BS[r * 36 + c4 + 0] = f2tf(v.x);
            BS[r * 36 + c4 + 1] = f2tf(v.y);
            BS[r * 36 + c4 + 2] = f2tf(v.z);
            BS[r * 36 + c4 + 3] = f2tf(v.w);
        }
        __syncthreads();
#pragma unroll
        for (int kk = 0; kk < 64; kk += 8) {
            uint32_t a0 = AS[(warpM * 16 + gid) * 68 + kk + tig];
            uint32_t a1 = AS[(warpM * 16 + gid + 8) * 68 + kk + tig];
            uint32_t a2 = AS[(warpM * 16 + gid) * 68 + kk + tig + 4];
            uint32_t a3 = AS[(warpM * 16 + gid + 8) * 68 + kk + tig + 4];
#pragma unroll
            for (int j = 0; j < 2; j++) {
                int nb = warpN * 16 + j * 8;
                uint32_t b0 = BS[(kk + tig) * 36 + nb + gid];
                uint32_t b1 = BS[(kk + tig + 4) * 36 + nb + gid];
                mma_tf32(acc[j], a0, a1, a2, a3, b0, b1);
            }
        }
    }
    __syncthreads();
    float* SK = (float*)BS;
#pragma unroll
    for (int j = 0; j < 2; j++) {
        int cb = warpN * 16 + j * 8 + tig * 2;
        float b0 = kb[cb], b1 = kb[cb + 1];
#pragma unroll
        for (int h = 0; h < 2; h++) {
            int r = warpM * 16 + gid + h * 8;
            SK[r * 33 + cb] = acc[j][h * 2] + b0;
            SK[r * 33 + cb + 1] = acc[j][h * 2 + 1] + b1;
        }
    }
    __syncthreads();
    if (t < 32) {
        int sn = selnum[b];
        float sum = 0.f;
        int cnt = 0;
        for (int j = 0; j < SEQN; j++) {
            if (inc[j]) {
                sum += SK[j * 33 + t];
                cnt++;
            }
            float denom = (sn != 0 && cnt > 0) ? (float)cnt : 1.f;
            g_selemb[((size_t)j * BSZ + b) * DK + t] = sum / denom;
        }
    }
}

// --------------- tiny converter ------------------------------------------------
__global__ void k_cvt(const float* __restrict__ e1w, const float* __restrict__ q2w) {
    int i = blockIdx.x * 256 + threadIdx.x;
    if (i < 8192) g_e1t[i] = f2tf(e1w[i]);
    else g_q2t[i - 8192] = f2tf(q2w[i - 8192]);
}

// --------------- mega-fused (BM=128): u -> P -> relu -> x -> LN gates ----------
#define SMF_FLOATS 52224
__global__ void __launch_bounds__(256, 1)
k_fused(const float* __restrict__ e1b, const float* __restrict__ q2b,
        const float* __restrict__ wih, const float* __restrict__ ln_ig,
        const float* __restrict__ ln_ib) {
    extern __shared__ float sm[];
    uint32_t* U = (uint32_t*)sm;
    uint32_t* BS = (uint32_t*)(sm + 33280);
    uint32_t* SEL = (uint32_t*)(sm + 43520);
    float* xsh = sm + 43520;
    float* wsh = sm + 48128;

    const int t = threadIdx.x;
    const int wid = t >> 5, lane = t & 31;
    const int gid = lane >> 2, tig = lane & 3;
    const int warpM = wid & 3, warpN = wid >> 2;
    const int m0 = blockIdx.x * 128;
    const int step = m0 >> 9;
    const int b0 = m0 & 511;

    if (step == 0) {
#pragma unroll 4
        for (int p = 0; p < 32; p++) {
            int idx = t + p * 256;
            int r = idx >> 6, c4 = (idx & 63) * 4;
            float4 v = *(const float4*)&g_base[(size_t)(b0 + r) * 256 + c4];
            uint4 q;
            q.x = f2tf(fmaxf(v.x, 0.f)); q.y = f2tf(fmaxf(v.y, 0.f));
            q.z = f2tf(fmaxf(v.z, 0.f)); q.w = f2tf(fmaxf(v.w, 0.f));
            *(uint4*)&U[r * 260 + c4] = q;
        }
    } else {
#pragma unroll
        for (int p = 0; p < 4; p++) {
            int idx = t + p * 256;
            int r = idx >> 3, c4 = (idx & 7) * 4;
            float4 v = *(const float4*)&g_selemb[(size_t)(m0 - 512 + r) * 32 + c4];
            uint4 q;
            q.x = f2tf(v.x); q.y = f2tf(v.y); q.z = f2tf(v.z); q.w = f2tf(v.w);
            *(uint4*)&SEL[r * 36 + c4] = q;
        }
#pragma unroll
        for (int p = 0; p < 8; p++) {
            int q = t + p * 256;
            int r = q >> 6, c4 = (q & 63) * 4;
            *(uint4*)&BS[r * 264 + c4] = ((const uint4*)g_e1t)[q];
        }
        __syncthreads();

        float acc[2][16][4];
#pragma unroll
        for (int mt = 0; mt < 2; mt++)
#pragma unroll
            for (int j = 0; j < 16; j++) {
                acc[mt][j][0] = 0.f; acc[mt][j][1] = 0.f;
                acc[mt][j][2] = 0.f; acc[mt][j][3] = 0.f;
            }
#pragma unroll
        for (int kk = 0; kk < 32; kk += 8) {
#pragma unroll
            for (int mt = 0; mt < 2; mt++) {
                int rbase = warpM * 32 + mt * 16 + gid;
                uint32_t a0 = SEL[rbase * 36 + kk + tig];
                uint32_t a1 = SEL[(rbase + 8) * 36 + kk + tig];
                uint32_t a2 = SEL[rbase * 36 + kk + tig + 4];
                uint32_t a3 = SEL[(rbase + 8) * 36 + kk + tig + 4];
#pragma unroll
                for (int j = 0; j < 16; j++) {
                    int nb = warpN * 128 + j * 8;
                    uint32_t b0 = BS[(kk + tig) * 264 + nb + gid];
                    uint32_t b1 = BS[(kk + tig + 4) * 264 + nb + gid];
                    mma_tf32(acc[mt][j], a0, a1, a2, a3, b0, b1);
                }
            }
        }
#pragma unroll
        for (int mt = 0; mt < 2; mt++)
#pragma unroll
            for (int j = 0; j < 16; j++) {
                int cb = warpN * 128 + j * 8 + tig * 2;
                float bb0 = e1b[cb], bb1 = e1b[cb + 1];
#pragma unroll
                for (int h = 0; h < 2; h++) {
                    int r = warpM * 32 + mt * 16 + gid + h * 8;
                    U[r * 260 + cb] = f2tf(fmaxf(acc[mt][j][h * 2] + bb0, 0.f));
                    U[r * 260 + cb + 1] = f2tf(fmaxf(acc[mt][j][h * 2 + 1] + bb1, 0.f));
                }
            }
#pragma unroll
        for (int mt = 0; mt < 2; mt++)
#pragma unroll
            for (int j = 0; j < 16; j++) {
                acc[mt][j][0] = 0.f; acc[mt][j][1] = 0.f;
                acc[mt][j][2] = 0.f; acc[mt][j][3] = 0.f;
            }
        uint4 pw[8];
        const uint4* W2v = (const uint4*)g_W2;
#pragma unroll
        for (int p = 0; p < 8; p++) pw[p] = W2v[t + p * 256];
        for (int ch = 0; ch < 8; ch++) {
            __syncthreads();
#pragma unroll
            for (int p = 0; p < 8; p++) {
                int q = t + p * 256;
                int r = q >> 6, c4 = (q & 63) * 4;
                *(uint4*)&BS[r * 264 + c4] = pw[p];
            }
            if (ch + 1 < 8) {
#pragma unroll
                for (int p = 0; p < 8; p++) pw[p] = W2v[(ch + 1) * 2048 + t + p * 256];
            }
            __syncthreads();
#pragma unroll
            for (int kk = 0; kk < 32; kk += 8) {
                int kg = ch * 32 + kk;
#pragma unroll
                for (int mt = 0; mt < 2; mt++) {
                    int rbase = warpM * 32 + mt * 16 + gid;
                    uint32_t a0 = U[rbase * 260 + kg + tig];
                    uint32_t a1 = U[(rbase + 8) * 260 + kg + tig];
                    uint32_t a2 = U[rbase * 260 + kg + tig + 4];
                    uint32_t a3 = U[(rbase + 8) * 260 + kg + tig + 4];
#pragma unroll
                    for (int j = 0; j < 16; j++) {
                        int nb = warpN * 128 + j * 8;
                        uint32_t b0 = BS[(kk + tig) * 264 + nb + gid];
                        uint32_t b1 = BS[(kk + tig + 4) * 264 + nb + gid];
                        mma_tf32(acc[mt][j], a0, a1, a2, a3, b0, b1);
                    }
                }
            }
        }
        __syncthreads();
#pragma unroll
        for (int mt = 0; mt < 2; mt++)
#pragma unroll
            for (int j = 0; j < 16; j++) {
                int cb = warpN * 128 + j * 8 + tig * 2;
                float c20 = g_c2[cb], c21 = g_c2[cb + 1];
#pragma unroll
                for (int h = 0; h < 2; h++) {
                    int r = warpM * 32 + mt * 16 + gid + h * 8;
                    float2 bc = *(const float2*)&g_base[(size_t)(b0 + r) * 256 + cb];
                    U[r * 260 + cb] = f2tf(fmaxf(acc[mt][j][h * 2] + bc.x + c20, 0.f));
                    U[r * 260 + cb + 1] =
                        f2tf(fmaxf(acc[mt][j][h * 2 + 1] + bc.y + c21, 0.f));
                }
            }
    }
    __syncthreads();

#pragma unroll
    for (int p = 0; p < 8; p++) {
        int q = t + p * 256;
        int r = q >> 3, c4 = (q & 7) * 4;
        *(uint4*)&BS[r * 40 + c4] = ((const uint4*)g_q2t)[q];
    }
    for (int idx = t; idx < 4096; idx += 256) wsh[idx] = wih[idx];
    __syncthreads();

    {
        float ax[2][2][4];
#pragma unroll
        for (int mt = 0; mt < 2; mt++)
#pragma unroll
            for (int j = 0; j < 2; j++) {
                ax[mt][j][0] = 0.f; ax[mt][j][1] = 0.f;
                ax[mt][j][2] = 0.f; ax[mt][j][3] = 0.f;
            }
#pragma unroll 4
        for (int kk = 0; kk < 256; kk += 8) {
#pragma unroll
            for (int mt = 0; mt < 2; mt++) {
                int rbase = warpM * 32 + mt * 16 + gid;
                uint32_t a0 = U[rbase * 260 + kk + tig];
                uint32_t a1 = U[(rbase + 8) * 260 + kk + tig];
                uint32_t a2 = U[rbase * 260 + kk + tig + 4];
                uint32_t a3 = U[(rbase + 8) * 260 + kk + tig + 4];
#pragma unroll
                for (int j = 0; j < 2; j++) {
                    int nb = warpN * 16 + j * 8;
                    uint32_t b0 = BS[(kk + tig) * 40 + nb + gid];
                    uint32_t b1 = BS[(kk + tig + 4) * 40 + nb + gid];
                    mma_tf32(ax[mt][j], a0, a1, a2, a3, b0, b1);
                }
            }
        }
        __syncthreads();
#pragma unroll
        for (int mt = 0; mt < 2; mt++)
#pragma unroll
            for (int j = 0; j < 2; j++) {
                int cb = warpN * 16 + j * 8 + tig * 2;
                float qb0 = q2b[cb], qb1 = q2b[cb + 1];
#pragma unroll
                for (int h = 0; h < 2; h++) {
                    int r = warpM * 32 + mt * 16 + gid + h * 8;
                    xsh[r * 33 + cb] = ax[mt][j][h * 2] + qb0;
                    xsh[r * 33 + cb + 1] = ax[mt][j][h * 2 + 1] + qb1;
                }
            }
    }
    __syncthreads();

    {
        float lg[4], lb[4];
#pragma unroll
        for (int g = 0; g < 4; g++) {
            lg[g] = ln_ig[g * 32 + lane];
            lb[g] = ln_ib[g * 32 + lane];
        }
        for (int rr = 0; rr < 16; rr++) {
            int row = wid * 16 + rr;
            float xv = xsh[row * 33 + lane];
            float acg[4] = {0.f, 0.f, 0.f, 0.f};
#pragma unroll
            for (int k = 0; k < 32; k++) {
                float xk = __shfl_sync(0xffffffffu, xv, k);
#pragma unroll
                for (int g = 0; g < 4; g++) acg[g] += xk * wsh[k * 128 + g * 32 + lane];
            }
            float s = acg[0] + acg[1] + acg[2] + acg[3];
            float m = wredsum(s) * (1.f / 128.f);
            float vs = 0.f;
#pragma unroll
            for (int g = 0; g < 4; g++) {
                float d = acg[g] - m;
                vs += d * d;
            }
            float v = wredsum(vs) * (1.f / 128.f);
            float rs = rsqrtf(v + 1e-5f);
#pragma unroll
            for (int g = 0; g < 4; g++)
                g_gx[(size_t)(m0 + row) * 128 + g * 32 + lane] =
                    (acg[g] - m) * rs * lg[g] + lb[g];
        }
    }
}

// --------------- k_tail: fused LSTM + logits (1 batch / block) ------------------
__global__ void __launch_bounds__(544) k_tail(const float* __restrict__ whh,
                                              const float* __restrict__ ln_hg,
                                              const float* __restrict__ ln_hb,
                                              const float* __restrict__ ln_cg,
                                              const float* __restrict__ ln_cb,
                                              const int* __restrict__ en_arr,
                                              float* __restrict__ out) {
    __shared__ float wsh[4096];
    __shared__ float hsh[2][32];
    const int t = threadIdx.x;
    const int b = blockIdx.x;
    const int wid = t >> 5, lane = t & 31;
    const int en = en_arr[b];

    for (int idx = t; idx < 4096; idx += 544) wsh[idx] = whh[idx];
    if (t < SEQN) out[((size_t)b * SEQN + t) * ENP1 + 512] = -1e9f;

    // logits thread state (warps 1..16): one key row in regs
    float kreg[32];
    int rstep = 0, n = 0;
    if (wid >= 1) {
        n = t - 32;  // 0..511
        rstep = g_removed[(size_t)b * ENP1 + n];
        const float4* kp = (const float4*)&g_key[((size_t)b * ENT + n) * DK];
#pragma unroll
        for (int p = 0; p < 8; p++) {
            float4 v = kp[p];
            kreg[p * 4 + 0] = v.x; kreg[p * 4 + 1] = v.y;
            kreg[p * 4 + 2] = v.z; kreg[p * 4 + 3] = v.w;
        }
    }

    // warp0 LSTM state
    float h = 0.f, c = 0.f;
    float hg[4], hb[4], cgm = 0.f, cbm = 0.f;
    float gxr[4], gq[4];
    if (wid == 0) {
#pragma unroll
        for (int g = 0; g < 4; g++) {
            hg[g] = ln_hg[g * 32 + lane];
            hb[g] = ln_hb[g * 32 + lane];
        }
        cgm = ln_cg[lane];
        cbm = ln_cb[lane];
#pragma unroll
        for (int g = 0; g < 4; g++) gxr[g] = g_gx[(size_t)b * 128 + g * 32 + lane];
#pragma unroll
        for (int g = 0; g < 4; g++)
            gq[g] = g_gx[((size_t)1 * BSZ + b) * 128 + g * 32 + lane];
    }

    auto lstm_step = [&](int i) {
        float gxn2[4] = {0.f, 0.f, 0.f, 0.f};
        if (i + 2 < SEQN) {
            size_t rn = (size_t)(i + 2) * BSZ + b;
#pragma unroll
            for (int g = 0; g < 4; g++) gxn2[g] = g_gx[rn * 128 + g * 32 + lane];
        }
        float acc[4] = {0.f, 0.f, 0.f, 0.f};
#pragma unroll
        for (int k = 0; k < 32; k++) {
            float hk = __shfl_sync(0xffffffffu, h, k);
#pragma unroll
            for (int g = 0; g < 4; g++) acc[g] += hk * wsh[k * 128 + g * 32 + lane];
        }
        float s = acc[0] + acc[1] + acc[2] + acc[3];
        float m = wredsum(s) * (1.f / 128.f);
        float vs = 0.f;
#pragma unroll
        for (int g = 0; g < 4; g++) {
            float d = acc[g] - m;
            vs += d * d;
        }
        float v = wredsum(vs) * (1.f / 128.f);
        float rs = rsqrtf(v + 1e-5f);
        float gate[4];
#pragma unroll
        for (int g = 0; g < 4; g++) gate[g] = gxr[g] + (acc[g] - m) * rs * hg[g] + hb[g];
        float ii = 1.f / (1.f + __expf(-gate[0]));
        float ff = 1.f / (1.f + __expf(-gate[1]));
        float gg = tanhf(gate[2]);
        float oo = 1.f / (1.f + __expf(-gate[3]));
        float cn = ff * c + ii * gg;
        float mc = wredsum(cn) * (1.f / 32.f);
        float dc = cn - mc;
        float vc = wredsum(dc * dc) * (1.f / 32.f);
        c = dc * rsqrtf(vc + 1e-5f) * cgm + cbm;
        h = oo * tanhf(c);
        hsh[i & 1][lane] = h;
#pragma unroll
        for (int g = 0; g < 4; g++) {
            gxr[g] = gq[g];
            gq[g] = gxn2[g];
        }
    };

    __syncthreads();
    if (wid == 0) lstm_step(0);
    __syncthreads();
    for (int i = 0; i < SEQN; i++) {
        int cur = i & 1;
        if (wid == 0) {
            if (i + 1 < SEQN) lstm_step(i + 1);
        } else {
            float dot = 0.f;
#pragma unroll
            for (int k = 0; k < 32; k++) dot += hsh[cur][k] * kreg[k];
            bool keep = (n < en) ? (rstep > i) : ((n == en) ? (i >= 1 && rstep > i) : false);
            out[((size_t)b * SEQN + i) * ENP1 + n] = keep ? dot : -1e9f;
        }
        __syncthreads();
    }
}

// ------------------------------- launch ----------------------------------------
extern "C" void kernel_launch(void* const* d_in, const int* in_sizes, int n_in,
                              void* d_out, int out_size) {
    const float* ent = (const float*)d_in[0];
    const float* ar = (const float*)d_in[1];
    const int* entity_num = (const int*)d_in[2];
    const int* sel = (const int*)d_in[3];
    const int* selnum = (const int*)d_in[4];
    const float* key_w = (const float*)d_in[5];
    const float* key_b = (const float*)d_in[6];
    const float* q1w = (const float*)d_in[7];
    const float* q1b = (const float*)d_in[8];
    const float* q2w = (const float*)d_in[9];
    const float* q2b = (const float*)d_in[10];
    const float* e1w = (const float*)d_in[11];
    const float* e1b = (const float*)d_in[12];
    const float* e2w = (const float*)d_in[13];
    const float* e2b = (const float*)d_in[14];
    const float* endv = (const float*)d_in[15];
    const float* wih = (const float*)d_in[16];
    const float* whh = (const float*)d_in[17];
    const float* ln_ig = (const float*)d_in[18];
    const float* ln_ib = (const float*)d_in[19];
    const float* ln_hg = (const float*)d_in[20];
    const float* ln_hb = (const float*)d_in[21];
    const float* ln_cg = (const float*)d_in[22];
    const float* ln_cb = (const float*)d_in[23];
    float* out = (float*)d_out;

    static cudaStream_t sB = 0, sD = 0;
    static cudaEvent_t eFork = 0, ePre = 0, eKey = 0;
    if (!sB) {
        cudaStreamCreateWithFlags(&sB, cudaStreamNonBlocking);
        cudaStreamCreateWithFlags(&sD, cudaStreamNonBlocking);
        cudaEventCreateWithFlags(&eFork, cudaEventDisableTiming);
        cudaEventCreateWithFlags(&ePre, cudaEventDisableTiming);
        cudaEventCreateWithFlags(&eKey, cudaEventDisableTiming);
        cudaFuncSetAttribute(k_fused, cudaFuncAttributeMaxDynamicSharedMemorySize,
                             SMF_FLOATS * 4);
        cudaFuncSetAttribute(k_key, cudaFuncAttributeMaxDynamicSharedMemorySize,
                             KEY_SMEM);
    }

    cudaEventRecord(eFork, 0);
    cudaStreamWaitEvent(sB, eFork, 0);
    cudaStreamWaitEvent(sD, eFork, 0);

    // side B: tf32 weight conversions + merged pre-GEMM (base, W2, c2)
    k_cvt<<<64, 256, 0, sB>>>(e1w, q2w);
    k_pre<<<dim3(13, 4), 256, 0, sB>>>(ar, e2w, e2b, q1w, q1b);
    cudaEventRecord(ePre, sB);

    // side D: full key GEMM (only tail needs it)
    k_key<<<2048, 256, KEY_SMEM, sD>>>(ent, key_w, key_b, endv, entity_num);
    cudaEventRecord(eKey, sD);

    // main: selkey(+removed+emb) -> fused -> tail
    k_selkey<<<BSZ, 256>>>(ent, key_w, key_b, sel, entity_num, selnum);
    cudaStreamWaitEvent(0, ePre, 0);
    k_fused<<<SEQN * BSZ / 128, 256, SMF_FLOATS * 4>>>(e1b, q2b, wih, ln_ig, ln_ib);
    cudaStreamWaitEvent(0, eKey, 0);
    k_tail<<<BSZ, 544>>>(whh, ln_hg, ln_hb, ln_cg, ln_cb, entity_num, out);
    (void)in_sizes;
    (void)n_in;
    (void)out_size;
}

// round 12
// speedup vs baseline: 1.5572x; 1.5572x over previous
#include <cuda_runtime.h>
#include <math.h>
#include <stdint.h>

#define BSZ 512
#define ENT 512
#define SEQN 64
#define DK 32
#define DF 256
#define DIN 1024
#define NGATE 128
#define ENP1 513

typedef unsigned long long u64;

// ----------------------------- static scratch --------------------------------
__device__ float g_key[(size_t)BSZ * ENT * DK];
__device__ int   g_removed[(size_t)BSZ * ENP1];
__device__ float g_selemb[(size_t)SEQN * BSZ * DK];
__device__ float g_base[(size_t)BSZ * DF];
__device__ float g_basec[(size_t)BSZ * DF];   // base + c2
__device__ float g_W2[(size_t)DF * DF];       // tf32 BITS
__device__ float g_c2[DF];
__device__ uint32_t g_e1t[32 * 256];          // e1w tf32 bits
__device__ uint32_t g_q2t[256 * 32];          // q2w tf32 bits
__device__ float g_gx[(size_t)SEQN * BSZ * NGATE];
__device__ float g_q[(size_t)SEQN * BSZ * DK];

// ----------------------------- helpers ---------------------------------------
__device__ __forceinline__ float wredsum(float v) {
#pragma unroll
    for (int o = 16; o; o >>= 1) v += __shfl_xor_sync(0xffffffffu, v, o);
    return v;
}
__device__ __forceinline__ void fma2(u64& d, u64 a, u64 b) {
    asm("fma.rn.f32x2 %0,%1,%2,%0;" : "+l"(d) : "l"(a), "l"(b));
}
__device__ __forceinline__ float2 up2(u64 v) {
    float2 f;
    asm("mov.b64 {%0,%1},%2;" : "=f"(f.x), "=f"(f.y) : "l"(v));
    return f;
}
__device__ __forceinline__ uint32_t f2tf(float f) {
    uint32_t r;
    asm("cvt.rna.tf32.f32 %0, %1;" : "=r"(r) : "f"(f));
    return r;
}
__device__ __forceinline__ void mma_tf32(float* c, uint32_t a0, uint32_t a1, uint32_t a2,
                                         uint32_t a3, uint32_t b0, uint32_t b1) {
    asm volatile(
        "mma.sync.aligned.m16n8k8.row.col.f32.tf32.tf32.f32 "
        "{%0,%1,%2,%3},{%4,%5,%6,%7},{%8,%9},{%0,%1,%2,%3};"
        : "+f"(c[0]), "+f"(c[1]), "+f"(c[2]), "+f"(c[3])
        : "r"(a0), "r"(a1), "r"(a2), "r"(a3), "r"(b0), "r"(b1));
}

// --------------- tf32 tensor-core GEMM (standalone) ---------------------------
// EPI: 2 +bias & end-scatter (key) | 6 plain -> C as tf32 BITS | 7 +bias -> C, +xb -> C2
template <int BN, int EPI>
__global__ void k_mma(const float* __restrict__ A, const float* __restrict__ B,
                      const float* __restrict__ bias, float* __restrict__ C,
                      int K, int N, const float* __restrict__ xb,
                      const int* __restrict__ xi, float* __restrict__ C2) {
    constexpr int BM = 64, KC = 32;
    constexpr int NBLD = (KC * BN) / 1024;
    constexpr int NT = BN / 16;
    __shared__ uint32_t As[BM][KC + 4];
    __shared__ uint32_t Bs[KC][BN + 4];
    const int t = threadIdx.x;
    const int wid = t >> 5, lane = t & 31;
    const int gid = lane >> 2, tig = lane & 3;
    const int warpM = wid & 3, warpN = wid >> 2;
    const int m0 = blockIdx.x * BM;
    const int n0 = blockIdx.y * BN;

    float cr[NT][4];
#pragma unroll
    for (int j = 0; j < NT; j++) {
        cr[j][0] = 0.f; cr[j][1] = 0.f; cr[j][2] = 0.f; cr[j][3] = 0.f;
    }

    const int ar0 = t >> 3;
    const int ak = (t & 7) * 4;
    constexpr int BQ = BN / 4;
    const int br0 = t / BQ;
    const int bn = (t % BQ) * 4;

    float4 pa0, pa1, pb[NBLD];
    pa0 = *(const float4*)&A[(size_t)(m0 + ar0) * K + ak];
    pa1 = *(const float4*)&A[(size_t)(m0 + ar0 + 32) * K + ak];
#pragma unroll
    for (int i = 0; i < NBLD; i++) {
        int kr = br0 + i * (256 / BQ);
        pb[i] = *(const float4*)&B[(size_t)kr * N + n0 + bn];
    }

    const int nch = K / KC;
    for (int ch = 0; ch < nch; ch++) {
        __syncthreads();
        {
            uint4 q;
            q.x = f2tf(pa0.x); q.y = f2tf(pa0.y); q.z = f2tf(pa0.z); q.w = f2tf(pa0.w);
            *(uint4*)&As[ar0][ak] = q;
            q.x = f2tf(pa1.x); q.y = f2tf(pa1.y); q.z = f2tf(pa1.z); q.w = f2tf(pa1.w);
            *(uint4*)&As[ar0 + 32][ak] = q;
#pragma unroll
            for (int i = 0; i < NBLD; i++) {
                int kr = br0 + i * (256 / BQ);
                q.x = f2tf(pb[i].x); q.y = f2tf(pb[i].y);
                q.z = f2tf(pb[i].z); q.w = f2tf(pb[i].w);
                *(uint4*)&Bs[kr][bn] = q;
            }
        }
        if (ch + 1 < nch) {
            int k0 = (ch + 1) * KC;
            pa0 = *(const float4*)&A[(size_t)(m0 + ar0) * K + k0 + ak];
            pa1 = *(const float4*)&A[(size_t)(m0 + ar0 + 32) * K + k0 + ak];
#pragma unroll
            for (int i = 0; i < NBLD; i++) {
                int kr = k0 + br0 + i * (256 / BQ);
                pb[i] = *(const float4*)&B[(size_t)kr * N + n0 + bn];
            }
        }
        __syncthreads();
#pragma unroll
        for (int kk = 0; kk < KC; kk += 8) {
            uint32_t a0 = As[warpM * 16 + gid][kk + tig];
            uint32_t a1 = As[warpM * 16 + gid + 8][kk + tig];
            uint32_t a2 = As[warpM * 16 + gid][kk + tig + 4];
            uint32_t a3 = As[warpM * 16 + gid + 8][kk + tig + 4];
#pragma unroll
            for (int j = 0; j < NT; j++) {
                int nb = warpN * (BN / 2) + j * 8;
                uint32_t b0 = Bs[kk + tig][nb + gid];
                uint32_t b1 = Bs[kk + tig + 4][nb + gid];
                mma_tf32(cr[j], a0, a1, a2, a3, b0, b1);
            }
        }
    }

    const int rb = m0 + warpM * 16 + gid;
#pragma unroll
    for (int j = 0; j < NT; j++) {
        int cb = n0 + warpN * (BN / 2) + j * 8 + tig * 2;
#pragma unroll
        for (int h = 0; h < 2; h++) {
            int m = rb + h * 8;
            float v0 = cr[j][h * 2 + 0];
            float v1 = cr[j][h * 2 + 1];
            if (EPI == 2) {
                int en = xi[m0 >> 9];
                if ((m & 511) == en) {
                    C[(size_t)m * N + cb] = xb[cb];
                    C[(size_t)m * N + cb + 1] = xb[cb + 1];
                } else {
                    C[(size_t)m * N + cb] = v0 + bias[cb];
                    C[(size_t)m * N + cb + 1] = v1 + bias[cb + 1];
                }
            } else if (EPI == 6) {
                ((uint32_t*)C)[(size_t)m * N + cb] = f2tf(v0);
                ((uint32_t*)C)[(size_t)m * N + cb + 1] = f2tf(v1);
            } else if (EPI == 7) {
                float o0 = v0 + bias[cb], o1 = v1 + bias[cb + 1];
                C[(size_t)m * N + cb] = o0;
                C[(size_t)m * N + cb + 1] = o1;
                C2[(size_t)m * N + cb] = o0 + xb[cb];
                C2[(size_t)m * N + cb + 1] = o1 + xb[cb + 1];
            }
        }
    }
}

// --------------- selkey gathered GEMM + removed scatter + pooled-emb scan ------
// register-prefetched gathered A / B chunks
__global__ void __launch_bounds__(256) k_selkey(const float* __restrict__ ent,
                                                const float* __restrict__ kw,
                                                const float* __restrict__ kb,
                                                const int* __restrict__ sel,
                                                const int* __restrict__ en_arr,
                                                const int* __restrict__ selnum) {
    __shared__ uint32_t AS[64 * 68];
    __shared__ uint32_t BS[64 * 36];
    __shared__ int ssh[64];
    __shared__ int inc[64];
    const int t = threadIdx.x;
    const int b = blockIdx.x;
    const int wid = t >> 5, lane = t & 31;
    const int gid = lane >> 2, tig = lane & 3;
    const int warpM = wid & 3, warpN = wid >> 2;
    const int en = en_arr[b];

    if (t < 64) ssh[t] = sel[b * SEQN + t];
    for (int n = t; n < ENP1; n += 256) g_removed[(size_t)b * ENP1 + n] = 65;
    __syncthreads();
    if (t < 64) atomicMin(&g_removed[(size_t)b * ENP1 + ssh[t]], t + 1);
    if (t < 64) {
        int sj = ssh[t];
        bool first = true, endf = (sj == en);
        for (int k = 0; k < t; k++) {
            int sk = ssh[k];
            if (sk == sj) first = false;
            if (sk == en) endf = true;
        }
        inc[t] = (first && !endf) ? 1 : 0;
    }

    float4 pa[4], pb[2];
#pragma unroll
    for (int p = 0; p < 4; p++) {
        int idx = t + p * 256;
        int r = idx >> 4, c4 = (idx & 15) * 4;
        pa[p] = *(const float4*)&ent[((size_t)b * ENT + ssh[r]) * 256 + c4];
    }
#pragma unroll
    for (int p = 0; p < 2; p++) {
        int idx = t + p * 256;
        int r = idx >> 3, c4 = (idx & 7) * 4;
        pb[p] = *(const float4*)&kw[(size_t)r * 32 + c4];
    }

    float acc[2][4];
    acc[0][0] = acc[0][1] = acc[0][2] = acc[0][3] = 0.f;
    acc[1][0] = acc[1][1] = acc[1][2] = acc[1][3] = 0.f;

    for (int ch = 0; ch < 4; ch++) {
        __syncthreads();
#pragma unroll
        for (int p = 0; p < 4; p++) {
            int idx = t + p * 256;
            int r = idx >> 4, c4 = (idx & 15) * 4;
            AS[r * 68 + c4 + 0] = f2tf(pa[p].x);
            AS[r * 68 + c4 + 1] = f2tf(pa[p].y);
            AS[r * 68 + c4 + 2] = f2tf(pa[p].z);
            AS[r * 68 + c4 + 3] = f2tf(pa[p].w);
        }
#pragma unroll
        for (int p = 0; p < 2; p++) {
            int idx = t + p * 256;
            int r = idx >> 3, c4 = (idx & 7) * 4;
            BS[r * 36 + c4 + 0] = f2tf(pb[p].x);
            BS[r * 36 + c4 + 1] = f2tf(pb[p].y);
            BS[r * 36 + c4 + 2] = f2tf(pb[p].z);
            BS[r * 36 + c4 + 3] = f2tf(pb[p].w);
        }
        if (ch + 1 < 4) {
            int k0 = (ch + 1) * 64;
#pragma unroll
            for (int p = 0; p < 4; p++) {
                int idx = t + p * 256;
                int r = idx >> 4, c4 = (idx & 15) * 4;
                pa[p] = *(const float4*)&ent[((size_t)b * ENT + ssh[r]) * 256 + k0 + c4];
            }
#pragma unroll
            for (int p = 0; p < 2; p++) {
                int idx = t + p * 256;
                int r = idx >> 3, c4 = (idx & 7) * 4;
                pb[p] = *(const float4*)&kw[(size_t)(k0 + r) * 32 + c4];
            }
        }
        __syncthreads();
#pragma unroll
        for (int kk = 0; kk < 64; kk += 8) {
            uint32_t a0 = AS[(warpM * 16 + gid) * 68 + kk + tig];
            uint32_t a1 = AS[(warpM * 16 + gid + 8) * 68 + kk + tig];
            uint32_t a2 = AS[(warpM * 16 + gid) * 68 + kk + tig + 4];
            uint32_t a3 = AS[(warpM * 16 + gid + 8) * 68 + kk + tig + 4];
#pragma unroll
            for (int j = 0; j < 2; j++) {
                int nb = warpN * 16 + j * 8;
                uint32_t b0 = BS[(kk + tig) * 36 + nb + gid];
                uint32_t b1 = BS[(kk + tig + 4) * 36 + nb + gid];
                mma_tf32(acc[j], a0, a1, a2, a3, b0, b1);
            }
        }
    }
    __syncthreads();
    float* SK = (float*)BS;
#pragma unroll
    for (int j = 0; j < 2; j++) {
        int cb = warpN * 16 + j * 8 + tig * 2;
        float b0 = kb[cb], b1 = kb[cb + 1];
#pragma unroll
        for (int h = 0; h < 2; h++) {
            int r = warpM * 16 + gid + h * 8;
            SK[r * 33 + cb] = acc[j][h * 2] + b0;
            SK[r * 33 + cb + 1] = acc[j][h * 2 + 1] + b1;
        }
    }
    __syncthreads();
    if (t < 32) {
        int sn = selnum[b];
        float sum = 0.f;
        int cnt = 0;
        for (int j = 0; j < SEQN; j++) {
            if (inc[j]) {
                sum += SK[j * 33 + t];
                cnt++;
            }
            float denom = (sn != 0 && cnt > 0) ? (float)cnt : 1.f;
            g_selemb[((size_t)j * BSZ + b) * DK + t] = sum / denom;
        }
    }
}

// --------------- tiny converter ------------------------------------------------
__global__ void k_cvt(const float* __restrict__ e1w, const float* __restrict__ q2w) {
    int i = blockIdx.x * 256 + threadIdx.x;
    if (i < 8192) g_e1t[i] = f2tf(e1w[i]);
    else g_q2t[i - 8192] = f2tf(q2w[i - 8192]);
}

// c2 = e2_b @ q1_w (8 blocks x 8 k-slices)
__global__ void k_c2(const float* __restrict__ e2b, const float* __restrict__ q1w) {
    __shared__ float part[8][32];
    int t = threadIdx.x;
    int col = blockIdx.x * 32 + (t & 31);
    int ks = t >> 5;
    float acc = 0.f;
    for (int k = ks * 128; k < ks * 128 + 128; k++) acc += e2b[k] * q1w[(size_t)k * DF + col];
    part[ks][t & 31] = acc;
    __syncthreads();
    if (t < 32) {
        float s = 0.f;
#pragma unroll
        for (int p = 0; p < 8; p++) s += part[p][t];
        g_c2[blockIdx.x * 32 + t] = s;
    }
}

// --------------- mega-fused (BM=128): u -> P -> relu -> x -> LN gates ----------
#define SMF_FLOATS 52224
__global__ void __launch_bounds__(256, 1)
k_fused(const float* __restrict__ e1b, const float* __restrict__ q2b,
        const float* __restrict__ wih, const float* __restrict__ ln_ig,
        const float* __restrict__ ln_ib) {
    extern __shared__ float sm[];
    uint32_t* U = (uint32_t*)sm;
    uint32_t* BS = (uint32_t*)(sm + 33280);
    uint32_t* SEL = (uint32_t*)(sm + 43520);
    float* xsh = sm + 43520;
    float* wsh = sm + 48128;

    const int t = threadIdx.x;
    const int wid = t >> 5, lane = t & 31;
    const int gid = lane >> 2, tig = lane & 3;
    const int warpM = wid & 3, warpN = wid >> 2;
    const int m0 = blockIdx.x * 128;
    const int step = m0 >> 9;
    const int b0 = m0 & 511;

    if (step == 0) {
#pragma unroll 4
        for (int p = 0; p < 32; p++) {
            int idx = t + p * 256;
            int r = idx >> 6, c4 = (idx & 63) * 4;
            float4 v = *(const float4*)&g_base[(size_t)(b0 + r) * 256 + c4];
            uint4 q;
            q.x = f2tf(fmaxf(v.x, 0.f)); q.y = f2tf(fmaxf(v.y, 0.f));
            q.z = f2tf(fmaxf(v.z, 0.f)); q.w = f2tf(fmaxf(v.w, 0.f));
            *(uint4*)&U[r * 260 + c4] = q;
        }
    } else {
#pragma unroll
        for (int p = 0; p < 4; p++) {
            int idx = t + p * 256;
            int r = idx >> 3, c4 = (idx & 7) * 4;
            float4 v = *(const float4*)&g_selemb[(size_t)(m0 - 512 + r) * 32 + c4];
            uint4 q;
            q.x = f2tf(v.x); q.y = f2tf(v.y); q.z = f2tf(v.z); q.w = f2tf(v.w);
            *(uint4*)&SEL[r * 36 + c4] = q;
        }
#pragma unroll
        for (int p = 0; p < 8; p++) {
            int q = t + p * 256;
            int r = q >> 6, c4 = (q & 63) * 4;
            *(uint4*)&BS[r * 264 + c4] = ((const uint4*)g_e1t)[q];
        }
        __syncthreads();

        float acc[2][16][4];
#pragma unroll
        for (int mt = 0; mt < 2; mt++)
#pragma unroll
            for (int j = 0; j < 16; j++) {
                acc[mt][j][0] = 0.f; acc[mt][j][1] = 0.f;
                acc[mt][j][2] = 0.f; acc[mt][j][3] = 0.f;
            }
#pragma unroll
        for (int kk = 0; kk < 32; kk += 8) {
#pragma unroll
            for (int mt = 0; mt < 2; mt++) {
                int rbase = warpM * 32 + mt * 16 + gid;
                uint32_t a0 = SEL[rbase * 36 + kk + tig];
                uint32_t a1 = SEL[(rbase + 8) * 36 + kk + tig];
                uint32_t a2 = SEL[rbase * 36 + kk + tig + 4];
                uint32_t a3 = SEL[(rbase + 8) * 36 + kk + tig + 4];
#pragma unroll
                for (int j = 0; j < 16; j++) {
                    int nb = warpN * 128 + j * 8;
                    uint32_t b0 = BS[(kk + tig) * 264 + nb + gid];
                    uint32_t b1 = BS[(kk + tig + 4) * 264 + nb + gid];
                    mma_tf32(acc[mt][j], a0, a1, a2, a3, b0, b1);
                }
            }
        }
#pragma unroll
        for (int mt = 0; mt < 2; mt++)
#pragma unroll
            for (int j = 0; j < 16; j++) {
                int cb = warpN * 128 + j * 8 + tig * 2;
                float bb0 = e1b[cb], bb1 = e1b[cb + 1];
#pragma unroll
                for (int h = 0; h < 2; h++) {
                    int r = warpM * 32 + mt * 16 + gid + h * 8;
                    U[r * 260 + cb] = f2tf(fmaxf(acc[mt][j][h * 2] + bb0, 0.f));
                    U[r * 260 + cb + 1] = f2tf(fmaxf(acc[mt][j][h * 2 + 1] + bb1, 0.f));
                }
            }
#pragma unroll
        for (int mt = 0; mt < 2; mt++)
#pragma unroll
            for (int j = 0; j < 16; j++) {
                acc[mt][j][0] = 0.f; acc[mt][j][1] = 0.f;
                acc[mt][j][2] = 0.f; acc[mt][j][3] = 0.f;
            }
        uint4 pw[8];
        const uint4* W2v = (const uint4*)g_W2;
#pragma unroll
        for (int p = 0; p < 8; p++) pw[p] = W2v[t + p * 256];
        for (int ch = 0; ch < 8; ch++) {
            __syncthreads();
#pragma unroll
            for (int p = 0; p < 8; p++) {
                int q = t + p * 256;
                int r = q >> 6, c4 = (q & 63) * 4;
                *(uint4*)&BS[r * 264 + c4] = pw[p];
            }
            if (ch + 1 < 8) {
#pragma unroll
                for (int p = 0; p < 8; p++) pw[p] = W2v[(ch + 1) * 2048 + t + p * 256];
            }
            __syncthreads();
#pragma unroll
            for (int kk = 0; kk < 32; kk += 8) {
                int kg = ch * 32 + kk;
#pragma unroll
                for (int mt = 0; mt < 2; mt++) {
                    int rbase = warpM * 32 + mt * 16 + gid;
                    uint32_t a0 = U[rbase * 260 + kg + tig];
                    uint32_t a1 = U[(rbase + 8) * 260 + kg + tig];
                    uint32_t a2 = U[rbase * 260 + kg + tig + 4];
                    uint32_t a3 = U[(rbase + 8) * 260 + kg + tig + 4];
#pragma unroll
                    for (int j = 0; j < 16; j++) {
                        int nb = warpN * 128 + j * 8;
                        uint32_t b0 = BS[(kk + tig) * 264 + nb + gid];
                        uint32_t b1 = BS[(kk + tig + 4) * 264 + nb + gid];
                        mma_tf32(acc[mt][j], a0, a1, a2, a3, b0, b1);
                    }
                }
            }
        }
        __syncthreads();
#pragma unroll
        for (int mt = 0; mt < 2; mt++)
#pragma unroll
            for (int j = 0; j < 16; j++) {
                int cb = warpN * 128 + j * 8 + tig * 2;
#pragma unroll
                for (int h = 0; h < 2; h++) {
                    int r = warpM * 32 + mt * 16 + gid + h * 8;
                    float2 bc = *(const float2*)&g_basec[(size_t)(b0 + r) * 256 + cb];
                    U[r * 260 + cb] = f2tf(fmaxf(acc[mt][j][h * 2] + bc.x, 0.f));
                    U[r * 260 + cb + 1] =
                        f2tf(fmaxf(acc[mt][j][h * 2 + 1] + bc.y, 0.f));
                }
            }
    }
    __syncthreads();

#pragma unroll
    for (int p = 0; p < 8; p++) {
        int q = t + p * 256;
        int r = q >> 3, c4 = (q & 7) * 4;
        *(uint4*)&BS[r * 40 + c4] = ((const uint4*)g_q2t)[q];
    }
    for (int idx = t; idx < 4096; idx += 256) wsh[idx] = wih[idx];
    __syncthreads();

    {
        float ax[2][2][4];
#pragma unroll
        for (int mt = 0; mt < 2; mt++)
#pragma unroll
            for (int j = 0; j < 2; j++) {
                ax[mt][j][0] = 0.f; ax[mt][j][1] = 0.f;
                ax[mt][j][2] = 0.f; ax[mt][j][3] = 0.f;
            }
#pragma unroll 4
        for (int kk = 0; kk < 256; kk += 8) {
#pragma unroll
            for (int mt = 0; mt < 2; mt++) {
                int rbase = warpM * 32 + mt * 16 + gid;
                uint32_t a0 = U[rbase * 260 + kk + tig];
                uint32_t a1 = U[(rbase + 8) * 260 + kk + tig];
                uint32_t a2 = U[rbase * 260 + kk + tig + 4];
                uint32_t a3 = U[(rbase + 8) * 260 + kk + tig + 4];
#pragma unroll
                for (int j = 0; j < 2; j++) {
                    int nb = warpN * 16 + j * 8;
                    uint32_t b0 = BS[(kk + tig) * 40 + nb + gid];
                    uint32_t b1 = BS[(kk + tig + 4) * 40 + nb + gid];
                    mma_tf32(ax[mt][j], a0, a1, a2, a3, b0, b1);
                }
            }
        }
        __syncthreads();
#pragma unroll
        for (int mt = 0; mt < 2; mt++)
#pragma unroll
            for (int j = 0; j < 2; j++) {
                int cb = warpN * 16 + j * 8 + tig * 2;
                float qb0 = q2b[cb], qb1 = q2b[cb + 1];
#pragma unroll
                for (int h = 0; h < 2; h++) {
                    int r = warpM * 32 + mt * 16 + gid + h * 8;
                    xsh[r * 33 + cb] = ax[mt][j][h * 2] + qb0;
                    xsh[r * 33 + cb + 1] = ax[mt][j][h * 2 + 1] + qb1;
                }
            }
    }
    __syncthreads();

    {
        float lg[4], lb[4];
#pragma unroll
        for (int g = 0; g < 4; g++) {
            lg[g] = ln_ig[g * 32 + lane];
            lb[g] = ln_ib[g * 32 + lane];
        }
        for (int rr = 0; rr < 16; rr++) {
            int row = wid * 16 + rr;
            float xv = xsh[row * 33 + lane];
            float acg[4] = {0.f, 0.f, 0.f, 0.f};
#pragma unroll
            for (int k = 0; k < 32; k++) {
                float xk = __shfl_sync(0xffffffffu, xv, k);
#pragma unroll
                for (int g = 0; g < 4; g++) acg[g] += xk * wsh[k * 128 + g * 32 + lane];
            }
            float s = acg[0] + acg[1] + acg[2] + acg[3];
            float m = wredsum(s) * (1.f / 128.f);
            float vs = 0.f;
#pragma unroll
            for (int g = 0; g < 4; g++) {
                float d = acg[g] - m;
                vs += d * d;
            }
            float v = wredsum(vs) * (1.f / 128.f);
            float rs = rsqrtf(v + 1e-5f);
#pragma unroll
            for (int g = 0; g < 4; g++)
                g_gx[(size_t)(m0 + row) * 128 + g * 32 + lane] =
                    (acg[g] - m) * rs * lg[g] + lb[g];
        }
    }
}

// ------------------- sequential LN-LSTM (warp/batch) ---------------------------
__global__ void k_lstm(const float* __restrict__ whh, const float* __restrict__ ln_hg,
                       const float* __restrict__ ln_hb, const float* __restrict__ ln_cg,
                       const float* __restrict__ ln_cb) {
    __shared__ float wsh[32 * 128];
    int t = threadIdx.x;
    for (int idx = t; idx < 4096; idx += 256) wsh[idx] = whh[idx];
    __syncthreads();
    int lane = t & 31, w = t >> 5;
    int b = blockIdx.x * 8 + w;
    float h = 0.f, c = 0.f;
    float hg[4], hb[4];
#pragma unroll
    for (int g = 0; g < 4; g++) {
        int cc = g * 32 + lane;
        hg[g] = ln_hg[cc];
        hb[g] = ln_hb[cc];
    }
    float cgm = ln_cg[lane], cbm = ln_cb[lane];
    float gxr[4];
#pragma unroll
    for (int g = 0; g < 4; g++) gxr[g] = g_gx[(size_t)b * 128 + g * 32 + lane];
    for (int i = 0; i < SEQN; i++) {
        float gxn[4];
        if (i + 1 < SEQN) {
            size_t rn = (size_t)(i + 1) * BSZ + b;
#pragma unroll
            for (int g = 0; g < 4; g++) gxn[g] = g_gx[rn * 128 + g * 32 + lane];
        }
        float acc[4] = {0.f, 0.f, 0.f, 0.f};
#pragma unroll
        for (int k = 0; k < 32; k++) {
            float hk = __shfl_sync(0xffffffffu, h, k);
#pragma unroll
            for (int g = 0; g < 4; g++) acc[g] += hk * wsh[k * 128 + g * 32 + lane];
        }
        float s = acc[0] + acc[1] + acc[2] + acc[3];
        float m = wredsum(s) * (1.f / 128.f);
        float vs = 0.f;
#pragma unroll
        for (int g = 0; g < 4; g++) {
            float d = acc[g] - m;
            vs += d * d;
        }
        float v = wredsum(vs) * (1.f / 128.f);
        float rs = rsqrtf(v + 1e-5f);
        float gate[4];
#pragma unroll
        for (int g = 0; g < 4; g++) gate[g] = gxr[g] + (acc[g] - m) * rs * hg[g] + hb[g];
        float ii = 1.f / (1.f + __expf(-gate[0]));
        float ff = 1.f / (1.f + __expf(-gate[1]));
        float gg = tanhf(gate[2]);
        float oo = 1.f / (1.f + __expf(-gate[3]));
        float cn = ff * c + ii * gg;
        float mc = wredsum(cn) * (1.f / 32.f);
        float dc = cn - mc;
        float vc = wredsum(dc * dc) * (1.f / 32.f);
        c = dc * rsqrtf(vc + 1e-5f) * cgm + cbm;
        h = oo * tanhf(c);
        g_q[((size_t)i * BSZ + b) * DK + lane] = h;
#pragma unroll
        for (int g = 0; g < 4; g++) gxr[g] = gxn[g];
    }
}

// ------------------- logits + mask (grid BSZ x 2) -------------------------------
__global__ void k_logits(const int* __restrict__ en_arr, float* __restrict__ out) {
    __shared__ float Qsh[64 * 32];
    __shared__ float Ksh[256 * 34];
    __shared__ int rsh[256];
    int t = threadIdx.x;
    int b = blockIdx.x;
    int tile = blockIdx.y;
    int en = en_arr[b];
    for (int idx = t; idx < 2048; idx += 256) {
        int s = idx >> 5, k = idx & 31;
        Qsh[idx] = g_q[((size_t)s * BSZ + b) * 32 + k];
    }
    const u64* Q2 = (const u64*)Qsh;
    int n0 = tile * 256;
    for (int idx = t; idx < 8192; idx += 256) {
        int n = idx >> 5, k = idx & 31;
        Ksh[n * 34 + k] = g_key[((size_t)b * ENT + n0 + n) * 32 + k];
    }
    rsh[t] = g_removed[(size_t)b * ENP1 + n0 + t];
    __syncthreads();
    u64 kreg[16];
#pragma unroll
    for (int kp = 0; kp < 16; kp++) {
        float2 kk = *(const float2*)&Ksh[t * 34 + kp * 2];
        asm("mov.b64 %0,{%1,%2};" : "=l"(kreg[kp]) : "f"(kk.x), "f"(kk.y));
    }
    int rstep = rsh[t];
    int n = n0 + t;
    for (int s = 0; s < SEQN; s++) {
        u64 a0 = 0ull, a1 = 0ull;
#pragma unroll
        for (int kp = 0; kp < 16; kp += 2) {
            fma2(a0, kreg[kp], Q2[s * 16 + kp]);
            fma2(a1, kreg[kp + 1], Q2[s * 16 + kp + 1]);
        }
        float2 f0 = up2(a0), f1 = up2(a1);
        float dot = (f0.x + f0.y) + (f1.x + f1.y);
        bool keep = (n < en) ? (rstep > s) : ((n == en) ? (s >= 1 && rstep > s) : false);
        out[((size_t)b * SEQN + s) * ENP1 + n] = keep ? dot : -1e9f;
    }
    if (tile == 1 && t < SEQN) out[((size_t)b * SEQN + t) * ENP1 + 512] = -1e9f;
}

// ------------------------------- launch ----------------------------------------
extern "C" void kernel_launch(void* const* d_in, const int* in_sizes, int n_in,
                              void* d_out, int out_size) {
    const float* ent = (const float*)d_in[0];
    const float* ar = (const float*)d_in[1];
    const int* entity_num = (const int*)d_in[2];
    const int* sel = (const int*)d_in[3];
    const int* selnum = (const int*)d_in[4];
    const float* key_w = (const float*)d_in[5];
    const float* key_b = (const float*)d_in[6];
    const float* q1w = (const float*)d_in[7];
    const float* q1b = (const float*)d_in[8];
    const float* q2w = (const float*)d_in[9];
    const float* q2b = (const float*)d_in[10];
    const float* e1w = (const float*)d_in[11];
    const float* e1b = (const float*)d_in[12];
    const float* e2w = (const float*)d_in[13];
    const float* e2b = (const float*)d_in[14];
    const float* endv = (const float*)d_in[15];
    const float* wih = (const float*)d_in[16];
    const float* whh = (const float*)d_in[17];
    const float* ln_ig = (const float*)d_in[18];
    const float* ln_ib = (const float*)d_in[19];
    const float* ln_hg = (const float*)d_in[20];
    const float* ln_hb = (const float*)d_in[21];
    const float* ln_cg = (const float*)d_in[22];
    const float* ln_cb = (const float*)d_in[23];
    float* out = (float*)d_out;

    void *pKey, *pBase, *pBasec, *pW2, *pC2;
    cudaGetSymbolAddress(&pKey, g_key);
    cudaGetSymbolAddress(&pBase, g_base);
    cudaGetSymbolAddress(&pBasec, g_basec);
    cudaGetSymbolAddress(&pW2, g_W2);
    cudaGetSymbolAddress(&pC2, g_c2);

    static cudaStream_t sB = 0, sC = 0, sD = 0;
    static cudaEvent_t eFork = 0, eB = 0, eW2 = 0, eKey = 0;
    if (!sB) {
        int lo, hi;
        cudaDeviceGetStreamPriorityRange(&lo, &hi);
        cudaStreamCreateWithFlags(&sB, cudaStreamNonBlocking);
        cudaStreamCreateWithFlags(&sC, cudaStreamNonBlocking);
        cudaStreamCreateWithPriority(&sD, cudaStreamNonBlocking, lo);
        cudaEventCreateWithFlags(&eFork, cudaEventDisableTiming);
        cudaEventCreateWithFlags(&eB, cudaEventDisableTiming);
        cudaEventCreateWithFlags(&eW2, cudaEventDisableTiming);
        cudaEventCreateWithFlags(&eKey, cudaEventDisableTiming);
        cudaFuncSetAttribute(k_fused, cudaFuncAttributeMaxDynamicSharedMemorySize,
                             SMF_FLOATS * 4);
    }

    cudaEventRecord(eFork, 0);
    cudaStreamWaitEvent(sB, eFork, 0);
    cudaStreamWaitEvent(sC, eFork, 0);
    cudaStreamWaitEvent(sD, eFork, 0);

    // side B: c2 then base (+basec)
    k_c2<<<8, 256, 0, sB>>>(e2b, q1w);
    k_mma<64, 7><<<dim3(BSZ / 64, DF / 64), 256, 0, sB>>>(
        ar, q1w, q1b, (float*)pBase, DIN, DF, (const float*)pC2, nullptr, (float*)pBasec);
    cudaEventRecord(eB, sB);

    // side C: weight tf32 conversions + W2 (tf32 bits out)
    k_cvt<<<64, 256, 0, sC>>>(e1w, q2w);
    k_mma<64, 6><<<dim3(DF / 64, DF / 64), 256, 0, sC>>>(
        e2w, q1w, nullptr, (float*)pW2, DIN, DF, nullptr, nullptr, nullptr);
    cudaEventRecord(eW2, sC);

    // side D (low priority): full key GEMM (only logits needs it)
    k_mma<32, 2><<<dim3(BSZ * ENT / 64, 1), 256, 0, sD>>>(
        ent, key_w, key_b, (float*)pKey, DF, DK, endv, entity_num, nullptr);
    cudaEventRecord(eKey, sD);

    // main: selkey(+removed+emb) -> fused -> lstm -> logits
    k_selkey<<<BSZ, 256>>>(ent, key_w, key_b, sel, entity_num, selnum);
    cudaStreamWaitEvent(0, eB, 0);
    cudaStreamWaitEvent(0, eW2, 0);
    k_fused<<<SEQN * BSZ / 128, 256, SMF_FLOATS * 4>>>(e1b, q2b, wih, ln_ig, ln_ib);
    k_lstm<<<BSZ / 8, 256>>>(whh, ln_hg, ln_hb, ln_cg, ln_cb);
    cudaStreamWaitEvent(0, eKey, 0);
    k_logits<<<dim3(BSZ, 2), 256>>>(entity_num, out);
    (void)in_sizes;
    (void)n_in;
    (void)out_size;
}

// round 13
// speedup vs baseline: 1.5919x; 1.0223x over previous
#include <cuda_runtime.h>
#include <math.h>
#include <stdint.h>

#define BSZ 512
#define ENT 512
#define SEQN 64
#define DK 32
#define DF 256
#define DIN 1024
#define NGATE 128
#define ENP1 513

typedef unsigned long long u64;

// ----------------------------- static scratch --------------------------------
__device__ float g_key[(size_t)BSZ * ENT * DK];
__device__ int   g_removed[(size_t)BSZ * ENP1];
__device__ float g_selemb[(size_t)SEQN * BSZ * DK];
__device__ float g_base[(size_t)BSZ * DF];
__device__ float g_basec[(size_t)BSZ * DF];   // base + c2
__device__ float g_W2[(size_t)DF * DF];       // tf32 BITS
__device__ float g_c2[DF];
__device__ uint32_t g_e1t[32 * 256];          // e1w tf32 bits
__device__ uint32_t g_q2t[256 * 32];          // q2w tf32 bits
__device__ float g_gram[32 * 32];             // whh @ whh^T
__device__ float g_rm[32];                    // row-mean of whh (/128 folded)
__device__ float g_gx[(size_t)SEQN * BSZ * NGATE];
__device__ float g_q[(size_t)SEQN * BSZ * DK];

// ----------------------------- helpers ---------------------------------------
__device__ __forceinline__ float wredsum(float v) {
#pragma unroll
    for (int o = 16; o; o >>= 1) v += __shfl_xor_sync(0xffffffffu, v, o);
    return v;
}
__device__ __forceinline__ void fma2(u64& d, u64 a, u64 b) {
    asm("fma.rn.f32x2 %0,%1,%2,%0;" : "+l"(d) : "l"(a), "l"(b));
}
__device__ __forceinline__ float2 up2(u64 v) {
    float2 f;
    asm("mov.b64 {%0,%1},%2;" : "=f"(f.x), "=f"(f.y) : "l"(v));
    return f;
}
__device__ __forceinline__ uint32_t f2tf(float f) {
    uint32_t r;
    asm("cvt.rna.tf32.f32 %0, %1;" : "=r"(r) : "f"(f));
    return r;
}
__device__ __forceinline__ float tanha(float x) {
    float y;
    asm("tanh.approx.f32 %0, %1;" : "=f"(y) : "f"(x));
    return y;
}
__device__ __forceinline__ float siga(float x) {
    return 0.5f * tanha(0.5f * x) + 0.5f;
}
__device__ __forceinline__ void mma_tf32(float* c, uint32_t a0, uint32_t a1, uint32_t a2,
                                         uint32_t a3, uint32_t b0, uint32_t b1) {
    asm volatile(
        "mma.sync.aligned.m16n8k8.row.col.f32.tf32.tf32.f32 "
        "{%0,%1,%2,%3},{%4,%5,%6,%7},{%8,%9},{%0,%1,%2,%3};"
        : "+f"(c[0]), "+f"(c[1]), "+f"(c[2]), "+f"(c[3])
        : "r"(a0), "r"(a1), "r"(a2), "r"(a3), "r"(b0), "r"(b1));
}

// --------------- tf32 tensor-core GEMM (standalone) ---------------------------
// EPI: 2 +bias & end-scatter (key) | 6 plain -> C as tf32 BITS | 7 +bias -> C, +xb -> C2
template <int BN, int EPI>
__global__ void k_mma(const float* __restrict__ A, const float* __restrict__ B,
                      const float* __restrict__ bias, float* __restrict__ C,
                      int K, int N, const float* __restrict__ xb,
                      const int* __restrict__ xi, float* __restrict__ C2) {
    constexpr int BM = 64, KC = 32;
    constexpr int NBLD = (KC * BN) / 1024;
    constexpr int NT = BN / 16;
    __shared__ uint32_t As[BM][KC + 4];
    __shared__ uint32_t Bs[KC][BN + 4];
    const int t = threadIdx.x;
    const int wid = t >> 5, lane = t & 31;
    const int gid = lane >> 2, tig = lane & 3;
    const int warpM = wid & 3, warpN = wid >> 2;
    const int m0 = blockIdx.x * BM;
    const int n0 = blockIdx.y * BN;

    float cr[NT][4];
#pragma unroll
    for (int j = 0; j < NT; j++) {
        cr[j][0] = 0.f; cr[j][1] = 0.f; cr[j][2] = 0.f; cr[j][3] = 0.f;
    }

    const int ar0 = t >> 3;
    const int ak = (t & 7) * 4;
    constexpr int BQ = BN / 4;
    const int br0 = t / BQ;
    const int bn = (t % BQ) * 4;

    float4 pa0, pa1, pb[NBLD];
    pa0 = *(const float4*)&A[(size_t)(m0 + ar0) * K + ak];
    pa1 = *(const float4*)&A[(size_t)(m0 + ar0 + 32) * K + ak];
#pragma unroll
    for (int i = 0; i < NBLD; i++) {
        int kr = br0 + i * (256 / BQ);
        pb[i] = *(const float4*)&B[(size_t)kr * N + n0 + bn];
    }

    const int nch = K / KC;
    for (int ch = 0; ch < nch; ch++) {
        __syncthreads();
        {
            uint4 q;
            q.x = f2tf(pa0.x); q.y = f2tf(pa0.y); q.z = f2tf(pa0.z); q.w = f2tf(pa0.w);
            *(uint4*)&As[ar0][ak] = q;
            q.x = f2tf(pa1.x); q.y = f2tf(pa1.y); q.z = f2tf(pa1.z); q.w = f2tf(pa1.w);
            *(uint4*)&As[ar0 + 32][ak] = q;
#pragma unroll
            for (int i = 0; i < NBLD; i++) {
                int kr = br0 + i * (256 / BQ);
                q.x = f2tf(pb[i].x); q.y = f2tf(pb[i].y);
                q.z = f2tf(pb[i].z); q.w = f2tf(pb[i].w);
                *(uint4*)&Bs[kr][bn] = q;
            }
        }
        if (ch + 1 < nch) {
            int k0 = (ch + 1) * KC;
            pa0 = *(const float4*)&A[(size_t)(m0 + ar0) * K + k0 + ak];
            pa1 = *(const float4*)&A[(size_t)(m0 + ar0 + 32) * K + k0 + ak];
#pragma unroll
            for (int i = 0; i < NBLD; i++) {
                int kr = k0 + br0 + i * (256 / BQ);
                pb[i] = *(const float4*)&B[(size_t)kr * N + n0 + bn];
            }
        }
        __syncthreads();
#pragma unroll
        for (int kk = 0; kk < KC; kk += 8) {
            uint32_t a0 = As[warpM * 16 + gid][kk + tig];
            uint32_t a1 = As[warpM * 16 + gid + 8][kk + tig];
            uint32_t a2 = As[warpM * 16 + gid][kk + tig + 4];
            uint32_t a3 = As[warpM * 16 + gid + 8][kk + tig + 4];
#pragma unroll
            for (int j = 0; j < NT; j++) {
                int nb = warpN * (BN / 2) + j * 8;
                uint32_t b0 = Bs[kk + tig][nb + gid];
                uint32_t b1 = Bs[kk + tig + 4][nb + gid];
                mma_tf32(cr[j], a0, a1, a2, a3, b0, b1);
            }
        }
    }

    const int rb = m0 + warpM * 16 + gid;
#pragma unroll
    for (int j = 0; j < NT; j++) {
        int cb = n0 + warpN * (BN / 2) + j * 8 + tig * 2;
#pragma unroll
        for (int h = 0; h < 2; h++) {
            int m = rb + h * 8;
            float v0 = cr[j][h * 2 + 0];
            float v1 = cr[j][h * 2 + 1];
            if (EPI == 2) {
                int en = xi[m0 >> 9];
                if ((m & 511) == en) {
                    C[(size_t)m * N + cb] = xb[cb];
                    C[(size_t)m * N + cb + 1] = xb[cb + 1];
                } else {
                    C[(size_t)m * N + cb] = v0 + bias[cb];
                    C[(size_t)m * N + cb + 1] = v1 + bias[cb + 1];
                }
            } else if (EPI == 6) {
                ((uint32_t*)C)[(size_t)m * N + cb] = f2tf(v0);
                ((uint32_t*)C)[(size_t)m * N + cb + 1] = f2tf(v1);
            } else if (EPI == 7) {
                float o0 = v0 + bias[cb], o1 = v1 + bias[cb + 1];
                C[(size_t)m * N + cb] = o0;
                C[(size_t)m * N + cb + 1] = o1;
                C2[(size_t)m * N + cb] = o0 + xb[cb];
                C2[(size_t)m * N + cb + 1] = o1 + xb[cb + 1];
            }
        }
    }
}

// --------------- selkey gathered GEMM + removed scatter + pooled-emb scan ------
__global__ void __launch_bounds__(256) k_selkey(const float* __restrict__ ent,
                                                const float* __restrict__ kw,
                                                const float* __restrict__ kb,
                                                const int* __restrict__ sel,
                                                const int* __restrict__ en_arr,
                                                const int* __restrict__ selnum) {
    __shared__ uint32_t AS[64 * 68];
    __shared__ uint32_t BS[64 * 36];
    __shared__ int ssh[64];
    __shared__ int inc[64];
    const int t = threadIdx.x;
    const int b = blockIdx.x;
    const int wid = t >> 5, lane = t & 31;
    const int gid = lane >> 2, tig = lane & 3;
    const int warpM = wid & 3, warpN = wid >> 2;
    const int en = en_arr[b];

    if (t < 64) ssh[t] = sel[b * SEQN + t];
    for (int n = t; n < ENP1; n += 256) g_removed[(size_t)b * ENP1 + n] = 65;
    __syncthreads();
    if (t < 64) atomicMin(&g_removed[(size_t)b * ENP1 + ssh[t]], t + 1);
    if (t < 64) {
        int sj = ssh[t];
        bool first = true, endf = (sj == en);
        for (int k = 0; k < t; k++) {
            int sk = ssh[k];
            if (sk == sj) first = false;
            if (sk == en) endf = true;
        }
        inc[t] = (first && !endf) ? 1 : 0;
    }

    float4 pa[4], pb[2];
#pragma unroll
    for (int p = 0; p < 4; p++) {
        int idx = t + p * 256;
        int r = idx >> 4, c4 = (idx & 15) * 4;
        pa[p] = *(const float4*)&ent[((size_t)b * ENT + ssh[r]) * 256 + c4];
    }
#pragma unroll
    for (int p = 0; p < 2; p++) {
        int idx = t + p * 256;
        int r = idx >> 3, c4 = (idx & 7) * 4;
        pb[p] = *(const float4*)&kw[(size_t)r * 32 + c4];
    }

    float acc[2][4];
    acc[0][0] = acc[0][1] = acc[0][2] = acc[0][3] = 0.f;
    acc[1][0] = acc[1][1] = acc[1][2] = acc[1][3] = 0.f;

    for (int ch = 0; ch < 4; ch++) {
        __syncthreads();
#pragma unroll
        for (int p = 0; p < 4; p++) {
            int idx = t + p * 256;
            int r = idx >> 4, c4 = (idx & 15) * 4;
            AS[r * 68 + c4 + 0] = f2tf(pa[p].x);
            AS[r * 68 + c4 + 1] = f2tf(pa[p].y);
            AS[r * 68 + c4 + 2] = f2tf(pa[p].z);
            AS[r * 68 + c4 + 3] = f2tf(pa[p].w);
        }
#pragma unroll
        for (int p = 0; p < 2; p++) {
            int idx = t + p * 256;
            int r = idx >> 3, c4 = (idx & 7) * 4;
            BS[r * 36 + c4 + 0] = f2tf(pb[p].x);
            BS[r * 36 + c4 + 1] = f2tf(pb[p].y);
            BS[r * 36 + c4 + 2] = f2tf(pb[p].z);
            BS[r * 36 + c4 + 3] = f2tf(pb[p].w);
        }
        if (ch + 1 < 4) {
            int k0 = (ch + 1) * 64;
#pragma unroll
            for (int p = 0; p < 4; p++) {
                int idx = t + p * 256;
                int r = idx >> 4, c4 = (idx & 15) * 4;
                pa[p] = *(const float4*)&ent[((size_t)b * ENT + ssh[r]) * 256 + k0 + c4];
            }
#pragma unroll
            for (int p = 0; p < 2; p++) {
                int idx = t + p * 256;
                int r = idx >> 3, c4 = (idx & 7) * 4;
                pb[p] = *(const float4*)&kw[(size_t)(k0 + r) * 32 + c4];
            }
        }
        __syncthreads();
#pragma unroll
        for (int kk = 0; kk < 64; kk += 8) {
            uint32_t a0 = AS[(warpM * 16 + gid) * 68 + kk + tig];
            uint32_t a1 = AS[(warpM * 16 + gid + 8) * 68 + kk + tig];
            uint32_t a2 = AS[(warpM * 16 + gid) * 68 + kk + tig + 4];
            uint32_t a3 = AS[(warpM * 16 + gid + 8) * 68 + kk + tig + 4];
#pragma unroll
            for (int j = 0; j < 2; j++) {
                int nb = warpN * 16 + j * 8;
                uint32_t b0 = BS[(kk + tig) * 36 + nb + gid];
                uint32_t b1 = BS[(kk + tig + 4) * 36 + nb + gid];
                mma_tf32(acc[j], a0, a1, a2, a3, b0, b1);
            }
        }
    }
    __syncthreads();
    float* SK = (float*)BS;
#pragma unroll
    for (int j = 0; j < 2; j++) {
        int cb = warpN * 16 + j * 8 + tig * 2;
        float b0 = kb[cb], b1 = kb[cb + 1];
#pragma unroll
        for (int h = 0; h < 2; h++) {
            int r = warpM * 16 + gid + h * 8;
            SK[r * 33 + cb] = acc[j][h * 2] + b0;
            SK[r * 33 + cb + 1] = acc[j][h * 2 + 1] + b1;
        }
    }
    __syncthreads();
    if (t < 32) {
        int sn = selnum[b];
        float sum = 0.f;
        int cnt = 0;
        for (int j = 0; j < SEQN; j++) {
            if (inc[j]) {
                sum += SK[j * 33 + t];
                cnt++;
            }
            float denom = (sn != 0 && cnt > 0) ? (float)cnt : 1.f;
            g_selemb[((size_t)j * BSZ + b) * DK + t] = sum / denom;
        }
    }
}

// --------------- tiny converters / gram ----------------------------------------
__global__ void k_cvt(const float* __restrict__ e1w, const float* __restrict__ q2w) {
    int i = blockIdx.x * 256 + threadIdx.x;
    if (i < 8192) g_e1t[i] = f2tf(e1w[i]);
    else g_q2t[i - 8192] = f2tf(q2w[i - 8192]);
}

// Gram = whh @ whh^T (32x32) and rowmean/128 (32) of whh [32,128]
__global__ void k_gram(const float* __restrict__ whh) {
    __shared__ float wsh[4096];
    int t = threadIdx.x;
    for (int i = t; i < 4096; i += 256) wsh[i] = whh[i];
    __syncthreads();
    for (int e = t; e < 1024; e += 256) {
        int k = e >> 5, l = e & 31;
        float s = 0.f;
#pragma unroll 8
        for (int g = 0; g < 128; g++) s += wsh[k * 128 + g] * wsh[l * 128 + g];
        g_gram[e] = s;
    }
    if (t < 32) {
        float s = 0.f;
#pragma unroll 8
        for (int g = 0; g < 128; g++) s += wsh[t * 128 + g];
        g_rm[t] = s * (1.f / 128.f);
    }
}

// c2 = e2_b @ q1_w (8 blocks x 8 k-slices)
__global__ void k_c2(const float* __restrict__ e2b, const float* __restrict__ q1w) {
    __shared__ float part[8][32];
    int t = threadIdx.x;
    int col = blockIdx.x * 32 + (t & 31);
    int ks = t >> 5;
    float acc = 0.f;
    for (int k = ks * 128; k < ks * 128 + 128; k++) acc += e2b[k] * q1w[(size_t)k * DF + col];
    part[ks][t & 31] = acc;
    __syncthreads();
    if (t < 32) {
        float s = 0.f;
#pragma unroll
        for (int p = 0; p < 8; p++) s += part[p][t];
        g_c2[blockIdx.x * 32 + t] = s;
    }
}

// --------------- mega-fused (BM=128): u -> P -> relu -> x -> LN gates ----------
#define SMF_FLOATS 52224
__global__ void __launch_bounds__(256, 1)
k_fused(const float* __restrict__ e1b, const float* __restrict__ q2b,
        const float* __restrict__ wih, const float* __restrict__ ln_ig,
        const float* __restrict__ ln_ib) {
    extern __shared__ float sm[];
    uint32_t* U = (uint32_t*)sm;
    uint32_t* BS = (uint32_t*)(sm + 33280);
    uint32_t* SEL = (uint32_t*)(sm + 43520);
    float* xsh = sm + 43520;
    float* wsh = sm + 48128;

    const int t = threadIdx.x;
    const int wid = t >> 5, lane = t & 31;
    const int gid = lane >> 2, tig = lane & 3;
    const int warpM = wid & 3, warpN = wid >> 2;
    const int m0 = blockIdx.x * 128;
    const int step = m0 >> 9;
    const int b0 = m0 & 511;

    if (step == 0) {
#pragma unroll 4
        for (int p = 0; p < 32; p++) {
            int idx = t + p * 256;
            int r = idx >> 6, c4 = (idx & 63) * 4;
            float4 v = *(const float4*)&g_base[(size_t)(b0 + r) * 256 + c4];
            uint4 q;
            q.x = f2tf(fmaxf(v.x, 0.f)); q.y = f2tf(fmaxf(v.y, 0.f));
            q.z = f2tf(fmaxf(v.z, 0.f)); q.w = f2tf(fmaxf(v.w, 0.f));
            *(uint4*)&U[r * 260 + c4] = q;
        }
    } else {
#pragma unroll
        for (int p = 0; p < 4; p++) {
            int idx = t + p * 256;
            int r = idx >> 3, c4 = (idx & 7) * 4;
            float4 v = *(const float4*)&g_selemb[(size_t)(m0 - 512 + r) * 32 + c4];
            uint4 q;
            q.x = f2tf(v.x); q.y = f2tf(v.y); q.z = f2tf(v.z); q.w = f2tf(v.w);
            *(uint4*)&SEL[r * 36 + c4] = q;
        }
#pragma unroll
        for (int p = 0; p < 8; p++) {
            int q = t + p * 256;
            int r = q >> 6, c4 = (q & 63) * 4;
            *(uint4*)&BS[r * 264 + c4] = ((const uint4*)g_e1t)[q];
        }
        __syncthreads();

        float acc[2][16][4];
#pragma unroll
        for (int mt = 0; mt < 2; mt++)
#pragma unroll
            for (int j = 0; j < 16; j++) {
                acc[mt][j][0] = 0.f; acc[mt][j][1] = 0.f;
                acc[mt][j][2] = 0.f; acc[mt][j][3] = 0.f;
            }
#pragma unroll
        for (int kk = 0; kk < 32; kk += 8) {
#pragma unroll
            for (int mt = 0; mt < 2; mt++) {
                int rbase = warpM * 32 + mt * 16 + gid;
                uint32_t a0 = SEL[rbase * 36 + kk + tig];
                uint32_t a1 = SEL[(rbase + 8) * 36 + kk + tig];
                uint32_t a2 = SEL[rbase * 36 + kk + tig + 4];
                uint32_t a3 = SEL[(rbase + 8) * 36 + kk + tig + 4];
#pragma unroll
                for (int j = 0; j < 16; j++) {
                    int nb = warpN * 128 + j * 8;
                    uint32_t b0 = BS[(kk + tig) * 264 + nb + gid];
                    uint32_t b1 = BS[(kk + tig + 4) * 264 + nb + gid];
                    mma_tf32(acc[mt][j], a0, a1, a2, a3, b0, b1);
                }
            }
        }
#pragma unroll
        for (int mt = 0; mt < 2; mt++)
#pragma unroll
            for (int j = 0; j < 16; j++) {
                int cb = warpN * 128 + j * 8 + tig * 2;
                float bb0 = e1b[cb], bb1 = e1b[cb + 1];
#pragma unroll
                for (int h = 0; h < 2; h++) {
                    int r = warpM * 32 + mt * 16 + gid + h * 8;
                    U[r * 260 + cb] = f2tf(fmaxf(acc[mt][j][h * 2] + bb0, 0.f));
                    U[r * 260 + cb + 1] = f2tf(fmaxf(acc[mt][j][h * 2 + 1] + bb1, 0.f));
                }
            }
#pragma unroll
        for (int mt = 0; mt < 2; mt++)
#pragma unroll
            for (int j = 0; j < 16; j++) {
                acc[mt][j][0] = 0.f; acc[mt][j][1] = 0.f;
                acc[mt][j][2] = 0.f; acc[mt][j][3] = 0.f;
            }
        uint4 pw[8];
        const uint4* W2v = (const uint4*)g_W2;
#pragma unroll
        for (int p = 0; p < 8; p++) pw[p] = W2v[t + p * 256];
        for (int ch = 0; ch < 8; ch++) {
            __syncthreads();
#pragma unroll
            for (int p = 0; p < 8; p++) {
                int q = t + p * 256;
                int r = q >> 6, c4 = (q & 63) * 4;
                *(uint4*)&BS[r * 264 + c4] = pw[p];
            }
            if (ch + 1 < 8) {
#pragma unroll
                for (int p = 0; p < 8; p++) pw[p] = W2v[(ch + 1) * 2048 + t + p * 256];
            }
            __syncthreads();
#pragma unroll
            for (int kk = 0; kk < 32; kk += 8) {
                int kg = ch * 32 + kk;
#pragma unroll
                for (int mt = 0; mt < 2; mt++) {
                    int rbase = warpM * 32 + mt * 16 + gid;
                    uint32_t a0 = U[rbase * 260 + kg + tig];
                    uint32_t a1 = U[(rbase + 8) * 260 + kg + tig];
                    uint32_t a2 = U[rbase * 260 + kg + tig + 4];
                    uint32_t a3 = U[(rbase + 8) * 260 + kg + tig + 4];
#pragma unroll
                    for (int j = 0; j < 16; j++) {
                        int nb = warpN * 128 + j * 8;
                        uint32_t b0 = BS[(kk + tig) * 264 + nb + gid];
                        uint32_t b1 = BS[(kk + tig + 4) * 264 + nb + gid];
                        mma_tf32(acc[mt][j], a0, a1, a2, a3, b0, b1);
                    }
                }
            }
        }
        __syncthreads();
#pragma unroll
        for (int mt = 0; mt < 2; mt++)
#pragma unroll
            for (int j = 0; j < 16; j++) {
                int cb = warpN * 128 + j * 8 + tig * 2;
#pragma unroll
                for (int h = 0; h < 2; h++) {
                    int r = warpM * 32 + mt * 16 + gid + h * 8;
                    float2 bc = *(const float2*)&g_basec[(size_t)(b0 + r) * 256 + cb];
                    U[r * 260 + cb] = f2tf(fmaxf(acc[mt][j][h * 2] + bc.x, 0.f));
                    U[r * 260 + cb + 1] =
                        f2tf(fmaxf(acc[mt][j][h * 2 + 1] + bc.y, 0.f));
                }
            }
    }
    __syncthreads();

#pragma unroll
    for (int p = 0; p < 8; p++) {
        int q = t + p * 256;
        int r = q >> 3, c4 = (q & 7) * 4;
        *(uint4*)&BS[r * 40 + c4] = ((const uint4*)g_q2t)[q];
    }
    for (int idx = t; idx < 4096; idx += 256) wsh[idx] = wih[idx];
    __syncthreads();

    {
        float ax[2][2][4];
#pragma unroll
        for (int mt = 0; mt < 2; mt++)
#pragma unroll
            for (int j = 0; j < 2; j++) {
                ax[mt][j][0] = 0.f; ax[mt][j][1] = 0.f;
                ax[mt][j][2] = 0.f; ax[mt][j][3] = 0.f;
            }
#pragma unroll 4
        for (int kk = 0; kk < 256; kk += 8) {
#pragma unroll
            for (int mt = 0; mt < 2; mt++) {
                int rbase = warpM * 32 + mt * 16 + gid;
                uint32_t a0 = U[rbase * 260 + kk + tig];
                uint32_t a1 = U[(rbase + 8) * 260 + kk + tig];
                uint32_t a2 = U[rbase * 260 + kk + tig + 4];
                uint32_t a3 = U[(rbase + 8) * 260 + kk + tig + 4];
#pragma unroll
                for (int j = 0; j < 2; j++) {
                    int nb = warpN * 16 + j * 8;
                    uint32_t b0 = BS[(kk + tig) * 40 + nb + gid];
                    uint32_t b1 = BS[(kk + tig + 4) * 40 + nb + gid];
                    mma_tf32(ax[mt][j], a0, a1, a2, a3, b0, b1);
                }
            }
        }
        __syncthreads();
#pragma unroll
        for (int mt = 0; mt < 2; mt++)
#pragma unroll
            for (int j = 0; j < 2; j++) {
                int cb = warpN * 16 + j * 8 + tig * 2;
                float qb0 = q2b[cb], qb1 = q2b[cb + 1];
#pragma unroll
                for (int h = 0; h < 2; h++) {
                    int r = warpM * 32 + mt * 16 + gid + h * 8;
                    xsh[r * 33 + cb] = ax[mt][j][h * 2] + qb0;
                    xsh[r * 33 + cb + 1] = ax[mt][j][h * 2 + 1] + qb1;
                }
            }
    }
    __syncthreads();

    {
        float lg[4], lb[4];
#pragma unroll
        for (int g = 0; g < 4; g++) {
            lg[g] = ln_ig[g * 32 + lane];
            lb[g] = ln_ib[g * 32 + lane];
        }
        for (int rr = 0; rr < 16; rr++) {
            int row = wid * 16 + rr;
            float xv = xsh[row * 33 + lane];
            float acg[4] = {0.f, 0.f, 0.f, 0.f};
#pragma unroll
            for (int k = 0; k < 32; k++) {
                float xk = __shfl_sync(0xffffffffu, xv, k);
#pragma unroll
                for (int g = 0; g < 4; g++) acg[g] += xk * wsh[k * 128 + g * 32 + lane];
            }
            float s = acg[0] + acg[1] + acg[2] + acg[3];
            float m = wredsum(s) * (1.f / 128.f);
            float vs = 0.f;
#pragma unroll
            for (int g = 0; g < 4; g++) {
                float d = acg[g] - m;
                vs += d * d;
            }
            float v = wredsum(vs) * (1.f / 128.f);
            float rs = rsqrtf(v + 1e-5f);
#pragma unroll
            for (int g = 0; g < 4; g++)
                g_gx[(size_t)(m0 + row) * 128 + g * 32 + lane] =
                    (acg[g] - m) * rs * lg[g] + lb[g];
        }
    }
}

// ------------------- sequential LN-LSTM (warp/batch, Gram-LN) -------------------
__global__ void k_lstm(const float* __restrict__ whh, const float* __restrict__ ln_hg,
                       const float* __restrict__ ln_hb, const float* __restrict__ ln_cg,
                       const float* __restrict__ ln_cb) {
    __shared__ float wsh[32 * 128];
    __shared__ float gsh[32 * 32];
    __shared__ float rmsh[32];
    int t = threadIdx.x;
    for (int idx = t; idx < 4096; idx += 256) wsh[idx] = whh[idx];
    for (int idx = t; idx < 1024; idx += 256) gsh[idx] = g_gram[idx];
    if (t < 32) rmsh[t] = g_rm[t];
    __syncthreads();
    int lane = t & 31, w = t >> 5;
    int b = blockIdx.x * 8 + w;
    float h = 0.f, c = 0.f;
    float hg[4], hb[4];
#pragma unroll
    for (int g = 0; g < 4; g++) {
        int cc = g * 32 + lane;
        hg[g] = ln_hg[cc];
        hb[g] = ln_hb[cc];
    }
    float cgm = ln_cg[lane], cbm = ln_cb[lane];
    float gxr[4];
#pragma unroll
    for (int g = 0; g < 4; g++) gxr[g] = g_gx[(size_t)b * 128 + g * 32 + lane];
    for (int i = 0; i < SEQN; i++) {
        float gxn[4];
        if (i + 1 < SEQN) {
            size_t rn = (size_t)(i + 1) * BSZ + b;
#pragma unroll
            for (int g = 0; g < 4; g++) gxn[g] = g_gx[rn * 128 + g * 32 + lane];
        }
        float acc[4] = {0.f, 0.f, 0.f, 0.f};
        float accM = 0.f, wv = 0.f;
#pragma unroll
        for (int k = 0; k < 32; k++) {
            float hk = __shfl_sync(0xffffffffu, h, k);
#pragma unroll
            for (int g = 0; g < 4; g++) acc[g] += hk * wsh[k * 128 + g * 32 + lane];
            accM = fmaf(hk, rmsh[k], accM);
            wv = fmaf(hk, gsh[k * 32 + lane], wv);
        }
        float m = accM;                            // mean, no reduction
        float q = wredsum(h * wv);                 // sum of acc^2 via Gram
        float v = fmaxf(q * (1.f / 128.f) - m * m, 0.f);
        float rs = rsqrtf(v + 1e-5f);
        float gate[4];
#pragma unroll
        for (int g = 0; g < 4; g++) gate[g] = gxr[g] + (acc[g] - m) * rs * hg[g] + hb[g];
        float ii = siga(gate[0]);
        float ff = siga(gate[1]);
        float gg = tanha(gate[2]);
        float oo = siga(gate[3]);
        float cn = ff * c + ii * gg;
        // paired (independent) reductions for E[c], E[c^2]
        float s1 = cn, s2 = cn * cn;
#pragma unroll
        for (int o = 16; o; o >>= 1) {
            s1 += __shfl_xor_sync(0xffffffffu, s1, o);
            s2 += __shfl_xor_sync(0xffffffffu, s2, o);
        }
        float mc = s1 * (1.f / 32.f);
        float vc = fmaxf(s2 * (1.f / 32.f) - mc * mc, 0.f);
        c = (cn - mc) * rsqrtf(vc + 1e-5f) * cgm + cbm;
        h = oo * tanha(c);
        g_q[((size_t)i * BSZ + b) * DK + lane] = h;
#pragma unroll
        for (int g = 0; g < 4; g++) gxr[g] = gxn[g];
    }
}

// ------------------- logits + mask (grid BSZ x 2) -------------------------------
__global__ void k_logits(const int* __restrict__ en_arr, float* __restrict__ out) {
    __shared__ float Qsh[64 * 32];
    __shared__ float Ksh[256 * 34];
    __shared__ int rsh[256];
    int t = threadIdx.x;
    int b = blockIdx.x;
    int tile = blockIdx.y;
    int en = en_arr[b];
    for (int idx = t; idx < 2048; idx += 256) {
        int s = idx >> 5, k = idx & 31;
        Qsh[idx] = g_q[((size_t)s * BSZ + b) * 32 + k];
    }
    const u64* Q2 = (const u64*)Qsh;
    int n0 = tile * 256;
    for (int idx = t; idx < 8192; idx += 256) {
        int n = idx >> 5, k = idx & 31;
        Ksh[n * 34 + k] = g_key[((size_t)b * ENT + n0 + n) * 32 + k];
    }
    rsh[t] = g_removed[(size_t)b * ENP1 + n0 + t];
    __syncthreads();
    u64 kreg[16];
#pragma unroll
    for (int kp = 0; kp < 16; kp++) {
        float2 kk = *(const float2*)&Ksh[t * 34 + kp * 2];
        asm("mov.b64 %0,{%1,%2};" : "=l"(kreg[kp]) : "f"(kk.x), "f"(kk.y));
    }
    int rstep = rsh[t];
    int n = n0 + t;
    for (int s = 0; s < SEQN; s++) {
        u64 a0 = 0ull, a1 = 0ull;
#pragma unroll
        for (int kp = 0; kp < 16; kp += 2) {
            fma2(a0, kreg[kp], Q2[s * 16 + kp]);
            fma2(a1, kreg[kp + 1], Q2[s * 16 + kp + 1]);
        }
        float2 f0 = up2(a0), f1 = up2(a1);
        float dot = (f0.x + f0.y) + (f1.x + f1.y);
        bool keep = (n < en) ? (rstep > s) : ((n == en) ? (s >= 1 && rstep > s) : false);
        out[((size_t)b * SEQN + s) * ENP1 + n] = keep ? dot : -1e9f;
    }
    if (tile == 1 && t < SEQN) out[((size_t)b * SEQN + t) * ENP1 + 512] = -1e9f;
}

// ------------------------------- launch ----------------------------------------
extern "C" void kernel_launch(void* const* d_in, const int* in_sizes, int n_in,
                              void* d_out, int out_size) {
    const float* ent = (const float*)d_in[0];
    const float* ar = (const float*)d_in[1];
    const int* entity_num = (const int*)d_in[2];
    const int* sel = (const int*)d_in[3];
    const int* selnum = (const int*)d_in[4];
    const float* key_w = (const float*)d_in[5];
    const float* key_b = (const float*)d_in[6];
    const float* q1w = (const float*)d_in[7];
    const float* q1b = (const float*)d_in[8];
    const float* q2w = (const float*)d_in[9];
    const float* q2b = (const float*)d_in[10];
    const float* e1w = (const float*)d_in[11];
    const float* e1b = (const float*)d_in[12];
    const float* e2w = (const float*)d_in[13];
    const float* e2b = (const float*)d_in[14];
    const float* endv = (const float*)d_in[15];
    const float* wih = (const float*)d_in[16];
    const float* whh = (const float*)d_in[17];
    const float* ln_ig = (const float*)d_in[18];
    const float* ln_ib = (const float*)d_in[19];
    const float* ln_hg = (const float*)d_in[20];
    const float* ln_hb = (const float*)d_in[21];
    const float* ln_cg = (const float*)d_in[22];
    const float* ln_cb = (const float*)d_in[23];
    float* out = (float*)d_out;

    void *pKey, *pBase, *pBasec, *pW2, *pC2;
    cudaGetSymbolAddress(&pKey, g_key);
    cudaGetSymbolAddress(&pBase, g_base);
    cudaGetSymbolAddress(&pBasec, g_basec);
    cudaGetSymbolAddress(&pW2, g_W2);
    cudaGetSymbolAddress(&pC2, g_c2);

    static cudaStream_t sB = 0, sC = 0, sD = 0;
    static cudaEvent_t eFork = 0, eB = 0, eW2 = 0, eKey = 0;
    if (!sB) {
        int lo, hi;
        cudaDeviceGetStreamPriorityRange(&lo, &hi);
        cudaStreamCreateWithFlags(&sB, cudaStreamNonBlocking);
        cudaStreamCreateWithFlags(&sC, cudaStreamNonBlocking);
        cudaStreamCreateWithPriority(&sD, cudaStreamNonBlocking, lo);
        cudaEventCreateWithFlags(&eFork, cudaEventDisableTiming);
        cudaEventCreateWithFlags(&eB, cudaEventDisableTiming);
        cudaEventCreateWithFlags(&eW2, cudaEventDisableTiming);
        cudaEventCreateWithFlags(&eKey, cudaEventDisableTiming);
        cudaFuncSetAttribute(k_fused, cudaFuncAttributeMaxDynamicSharedMemorySize,
                             SMF_FLOATS * 4);
    }

    cudaEventRecord(eFork, 0);
    cudaStreamWaitEvent(sB, eFork, 0);
    cudaStreamWaitEvent(sC, eFork, 0);
    cudaStreamWaitEvent(sD, eFork, 0);

    // side B: c2 then base (+basec) — BN=32 for 2x grid
    k_c2<<<8, 256, 0, sB>>>(e2b, q1w);
    k_mma<32, 7><<<dim3(BSZ / 64, DF / 32), 256, 0, sB>>>(
        ar, q1w, q1b, (float*)pBase, DIN, DF, (const float*)pC2, nullptr, (float*)pBasec);
    cudaEventRecord(eB, sB);

    // side C: weight tf32 conversions + W2 (tf32 bits, BN=32) + gram
    k_cvt<<<64, 256, 0, sC>>>(e1w, q2w);
    k_mma<32, 6><<<dim3(DF / 64, DF / 32), 256, 0, sC>>>(
        e2w, q1w, nullptr, (float*)pW2, DIN, DF, nullptr, nullptr, nullptr);
    k_gram<<<1, 256, 0, sC>>>(whh);
    cudaEventRecord(eW2, sC);

    // side D (low priority): full key GEMM (only logits needs it)
    k_mma<32, 2><<<dim3(BSZ * ENT / 64, 1), 256, 0, sD>>>(
        ent, key_w, key_b, (float*)pKey, DF, DK, endv, entity_num, nullptr);
    cudaEventRecord(eKey, sD);

    // main: selkey(+removed+emb) -> fused -> lstm -> logits
    k_selkey<<<BSZ, 256>>>(ent, key_w, key_b, sel, entity_num, selnum);
    cudaStreamWaitEvent(0, eB, 0);
    cudaStreamWaitEvent(0, eW2, 0);
    k_fused<<<SEQN * BSZ / 128, 256, SMF_FLOATS * 4>>>(e1b, q2b, wih, ln_ig, ln_ib);
    k_lstm<<<BSZ / 8, 256>>>(whh, ln_hg, ln_hb, ln_cg, ln_cb);
    cudaStreamWaitEvent(0, eKey, 0);
    k_logits<<<dim3(BSZ, 2), 256>>>(entity_num, out);
    (void)in_sizes;
    (void)n_in;
    (void)out_size;
}

// round 14
// speedup vs baseline: 1.7979x; 1.1294x over previous
#include <cuda_runtime.h>
#include <math.h>
#include <stdint.h>

#define BSZ 512
#define ENT 512
#define SEQN 64
#define DK 32
#define DF 256
#define DIN 1024
#define NGATE 128
#define ENP1 513

typedef unsigned long long u64;

// ----------------------------- static scratch --------------------------------
__device__ float g_key[(size_t)BSZ * ENT * DK];
__device__ int   g_removed[(size_t)BSZ * ENP1];
__device__ float g_selemb[(size_t)SEQN * BSZ * DK];
__device__ float g_base[(size_t)BSZ * DF];
__device__ float g_basec[(size_t)BSZ * DF];   // base + c2
__device__ float g_W2[(size_t)DF * DF];       // tf32 BITS
__device__ float g_c2[DF];
__device__ uint32_t g_e1t[32 * 256];          // e1w tf32 bits
__device__ uint32_t g_q2t[256 * 32];          // q2w tf32 bits
__device__ uint32_t g_wiht[32 * 128];         // wih tf32 bits
__device__ float g_gram[32 * 32];             // whh @ whh^T
__device__ float g_rm[32];                    // row-mean of whh (/128 folded)
__device__ float g_gx[(size_t)SEQN * BSZ * NGATE];
__device__ float g_q[(size_t)SEQN * BSZ * DK];

// ----------------------------- helpers ---------------------------------------
__device__ __forceinline__ float wredsum(float v) {
#pragma unroll
    for (int o = 16; o; o >>= 1) v += __shfl_xor_sync(0xffffffffu, v, o);
    return v;
}
__device__ __forceinline__ void fma2(u64& d, u64 a, u64 b) {
    asm("fma.rn.f32x2 %0,%1,%2,%0;" : "+l"(d) : "l"(a), "l"(b));
}
__device__ __forceinline__ float2 up2(u64 v) {
    float2 f;
    asm("mov.b64 {%0,%1},%2;" : "=f"(f.x), "=f"(f.y) : "l"(v));
    return f;
}
__device__ __forceinline__ uint32_t f2tf(float f) {
    uint32_t r;
    asm("cvt.rna.tf32.f32 %0, %1;" : "=r"(r) : "f"(f));
    return r;
}
__device__ __forceinline__ float tanha(float x) {
    float y;
    asm("tanh.approx.f32 %0, %1;" : "=f"(y) : "f"(x));
    return y;
}
__device__ __forceinline__ float siga(float x) {
    return 0.5f * tanha(0.5f * x) + 0.5f;
}
__device__ __forceinline__ void mma_tf32(float* c, uint32_t a0, uint32_t a1, uint32_t a2,
                                         uint32_t a3, uint32_t b0, uint32_t b1) {
    asm volatile(
        "mma.sync.aligned.m16n8k8.row.col.f32.tf32.tf32.f32 "
        "{%0,%1,%2,%3},{%4,%5,%6,%7},{%8,%9},{%0,%1,%2,%3};"
        : "+f"(c[0]), "+f"(c[1]), "+f"(c[2]), "+f"(c[3])
        : "r"(a0), "r"(a1), "r"(a2), "r"(a3), "r"(b0), "r"(b1));
}

// --------------- tf32 tensor-core GEMM (standalone) ---------------------------
// EPI: 2 +bias & end-scatter (key) | 6 plain -> C as tf32 BITS | 7 +bias -> C, +xb -> C2
template <int BN, int EPI>
__global__ void k_mma(const float* __restrict__ A, const float* __restrict__ B,
                      const float* __restrict__ bias, float* __restrict__ C,
                      int K, int N, const float* __restrict__ xb,
                      const int* __restrict__ xi, float* __restrict__ C2) {
    constexpr int BM = 64, KC = 32;
    constexpr int NBLD = (KC * BN) / 1024;
    constexpr int NT = BN / 16;
    __shared__ uint32_t As[BM][KC + 4];
    __shared__ uint32_t Bs[KC][BN + 4];
    const int t = threadIdx.x;
    const int wid = t >> 5, lane = t & 31;
    const int gid = lane >> 2, tig = lane & 3;
    const int warpM = wid & 3, warpN = wid >> 2;
    const int m0 = blockIdx.x * BM;
    const int n0 = blockIdx.y * BN;

    float cr[NT][4];
#pragma unroll
    for (int j = 0; j < NT; j++) {
        cr[j][0] = 0.f; cr[j][1] = 0.f; cr[j][2] = 0.f; cr[j][3] = 0.f;
    }

    const int ar0 = t >> 3;
    const int ak = (t & 7) * 4;
    constexpr int BQ = BN / 4;
    const int br0 = t / BQ;
    const int bn = (t % BQ) * 4;

    float4 pa0, pa1, pb[NBLD];
    pa0 = *(const float4*)&A[(size_t)(m0 + ar0) * K + ak];
    pa1 = *(const float4*)&A[(size_t)(m0 + ar0 + 32) * K + ak];
#pragma unroll
    for (int i = 0; i < NBLD; i++) {
        int kr = br0 + i * (256 / BQ);
        pb[i] = *(const float4*)&B[(size_t)kr * N + n0 + bn];
    }

    const int nch = K / KC;
    for (int ch = 0; ch < nch; ch++) {
        __syncthreads();
        {
            uint4 q;
            q.x = f2tf(pa0.x); q.y = f2tf(pa0.y); q.z = f2tf(pa0.z); q.w = f2tf(pa0.w);
            *(uint4*)&As[ar0][ak] = q;
            q.x = f2tf(pa1.x); q.y = f2tf(pa1.y); q.z = f2tf(pa1.z); q.w = f2tf(pa1.w);
            *(uint4*)&As[ar0 + 32][ak] = q;
#pragma unroll
            for (int i = 0; i < NBLD; i++) {
                int kr = br0 + i * (256 / BQ);
                q.x = f2tf(pb[i].x); q.y = f2tf(pb[i].y);
                q.z = f2tf(pb[i].z); q.w = f2tf(pb[i].w);
                *(uint4*)&Bs[kr][bn] = q;
            }
        }
        if (ch + 1 < nch) {
            int k0 = (ch + 1) * KC;
            pa0 = *(const float4*)&A[(size_t)(m0 + ar0) * K + k0 + ak];
            pa1 = *(const float4*)&A[(size_t)(m0 + ar0 + 32) * K + k0 + ak];
#pragma unroll
            for (int i = 0; i < NBLD; i++) {
                int kr = k0 + br0 + i * (256 / BQ);
                pb[i] = *(const float4*)&B[(size_t)kr * N + n0 + bn];
            }
        }
        __syncthreads();
#pragma unroll
        for (int kk = 0; kk < KC; kk += 8) {
            uint32_t a0 = As[warpM * 16 + gid][kk + tig];
            uint32_t a1 = As[warpM * 16 + gid + 8][kk + tig];
            uint32_t a2 = As[warpM * 16 + gid][kk + tig + 4];
            uint32_t a3 = As[warpM * 16 + gid + 8][kk + tig + 4];
#pragma unroll
            for (int j = 0; j < NT; j++) {
                int nb = warpN * (BN / 2) + j * 8;
                uint32_t b0 = Bs[kk + tig][nb + gid];
                uint32_t b1 = Bs[kk + tig + 4][nb + gid];
                mma_tf32(cr[j], a0, a1, a2, a3, b0, b1);
            }
        }
    }

    const int rb = m0 + warpM * 16 + gid;
#pragma unroll
    for (int j = 0; j < NT; j++) {
        int cb = n0 + warpN * (BN / 2) + j * 8 + tig * 2;
#pragma unroll
        for (int h = 0; h < 2; h++) {
            int m = rb + h * 8;
            float v0 = cr[j][h * 2 + 0];
            float v1 = cr[j][h * 2 + 1];
            if (EPI == 2) {
                int en = xi[m0 >> 9];
                if ((m & 511) == en) {
                    C[(size_t)m * N + cb] = xb[cb];
                    C[(size_t)m * N + cb + 1] = xb[cb + 1];
                } else {
                    C[(size_t)m * N + cb] = v0 + bias[cb];
                    C[(size_t)m * N + cb + 1] = v1 + bias[cb + 1];
                }
            } else if (EPI == 6) {
                ((uint32_t*)C)[(size_t)m * N + cb] = f2tf(v0);
                ((uint32_t*)C)[(size_t)m * N + cb + 1] = f2tf(v1);
            } else if (EPI == 7) {
                float o0 = v0 + bias[cb], o1 = v1 + bias[cb + 1];
                C[(size_t)m * N + cb] = o0;
                C[(size_t)m * N + cb + 1] = o1;
                C2[(size_t)m * N + cb] = o0 + xb[cb];
                C2[(size_t)m * N + cb + 1] = o1 + xb[cb + 1];
            }
        }
    }
}

// --------------- selkey gathered GEMM + removed scatter + pooled-emb scan ------
__global__ void __launch_bounds__(256) k_selkey(const float* __restrict__ ent,
                                                const float* __restrict__ kw,
                                                const float* __restrict__ kb,
                                                const int* __restrict__ sel,
                                                const int* __restrict__ en_arr,
                                                const int* __restrict__ selnum) {
    __shared__ uint32_t AS[64 * 68];
    __shared__ uint32_t BS[64 * 36];
    __shared__ int ssh[64];
    __shared__ int inc[64];
    const int t = threadIdx.x;
    const int b = blockIdx.x;
    const int wid = t >> 5, lane = t & 31;
    const int gid = lane >> 2, tig = lane & 3;
    const int warpM = wid & 3, warpN = wid >> 2;
    const int en = en_arr[b];

    if (t < 64) ssh[t] = sel[b * SEQN + t];
    for (int n = t; n < ENP1; n += 256) g_removed[(size_t)b * ENP1 + n] = 65;
    __syncthreads();
    if (t < 64) atomicMin(&g_removed[(size_t)b * ENP1 + ssh[t]], t + 1);
    if (t < 64) {
        int sj = ssh[t];
        bool first = true, endf = (sj == en);
        for (int k = 0; k < t; k++) {
            int sk = ssh[k];
            if (sk == sj) first = false;
            if (sk == en) endf = true;
        }
        inc[t] = (first && !endf) ? 1 : 0;
    }

    float4 pa[4], pb[2];
#pragma unroll
    for (int p = 0; p < 4; p++) {
        int idx = t + p * 256;
        int r = idx >> 4, c4 = (idx & 15) * 4;
        pa[p] = *(const float4*)&ent[((size_t)b * ENT + ssh[r]) * 256 + c4];
    }
#pragma unroll
    for (int p = 0; p < 2; p++) {
        int idx = t + p * 256;
        int r = idx >> 3, c4 = (idx & 7) * 4;
        pb[p] = *(const float4*)&kw[(size_t)r * 32 + c4];
    }

    float acc[2][4];
    acc[0][0] = acc[0][1] = acc[0][2] = acc[0][3] = 0.f;
    acc[1][0] = acc[1][1] = acc[1][2] = acc[1][3] = 0.f;

    for (int ch = 0; ch < 4; ch++) {
        __syncthreads();
#pragma unroll
        for (int p = 0; p < 4; p++) {
            int idx = t + p * 256;
            int r = idx >> 4, c4 = (idx & 15) * 4;
            AS[r * 68 + c4 + 0] = f2tf(pa[p].x);
            AS[r * 68 + c4 + 1] = f2tf(pa[p].y);
            AS[r * 68 + c4 + 2] = f2tf(pa[p].z);
            AS[r * 68 + c4 + 3] = f2tf(pa[p].w);
        }
#pragma unroll
        for (int p = 0; p < 2; p++) {
            int idx = t + p * 256;
            int r = idx >> 3, c4 = (idx & 7) * 4;
            BS[r * 36 + c4 + 0] = f2tf(pb[p].x);
            BS[r * 36 + c4 + 1] = f2tf(pb[p].y);
            BS[r * 36 + c4 + 2] = f2tf(pb[p].z);
            BS[r * 36 + c4 + 3] = f2tf(pb[p].w);
        }
        if (ch + 1 < 4) {
            int k0 = (ch + 1) * 64;
#pragma unroll
            for (int p = 0; p < 4; p++) {
                int idx = t + p * 256;
                int r = idx >> 4, c4 = (idx & 15) * 4;
                pa[p] = *(const float4*)&ent[((size_t)b * ENT + ssh[r]) * 256 + k0 + c4];
            }
#pragma unroll
            for (int p = 0; p < 2; p++) {
                int idx = t + p * 256;
                int r = idx >> 3, c4 = (idx & 7) * 4;
                pb[p] = *(const float4*)&kw[(size_t)(k0 + r) * 32 + c4];
            }
        }
        __syncthreads();
#pragma unroll
        for (int kk = 0; kk < 64; kk += 8) {
            uint32_t a0 = AS[(warpM * 16 + gid) * 68 + kk + tig];
            uint32_t a1 = AS[(warpM * 16 + gid + 8) * 68 + kk + tig];
            uint32_t a2 = AS[(warpM * 16 + gid) * 68 + kk + tig + 4];
            uint32_t a3 = AS[(warpM * 16 + gid + 8) * 68 + kk + tig + 4];
#pragma unroll
            for (int j = 0; j < 2; j++) {
                int nb = warpN * 16 + j * 8;
                uint32_t b0 = BS[(kk + tig) * 36 + nb + gid];
                uint32_t b1 = BS[(kk + tig + 4) * 36 + nb + gid];
                mma_tf32(acc[j], a0, a1, a2, a3, b0, b1);
            }
        }
    }
    __syncthreads();
    float* SK = (float*)BS;
#pragma unroll
    for (int j = 0; j < 2; j++) {
        int cb = warpN * 16 + j * 8 + tig * 2;
        float b0 = kb[cb], b1 = kb[cb + 1];
#pragma unroll
        for (int h = 0; h < 2; h++) {
            int r = warpM * 16 + gid + h * 8;
            SK[r * 33 + cb] = acc[j][h * 2] + b0;
            SK[r * 33 + cb + 1] = acc[j][h * 2 + 1] + b1;
        }
    }
    __syncthreads();
    if (t < 32) {
        int sn = selnum[b];
        float sum = 0.f;
        int cnt = 0;
        for (int j = 0; j < SEQN; j++) {
            if (inc[j]) {
                sum += SK[j * 33 + t];
                cnt++;
            }
            float denom = (sn != 0 && cnt > 0) ? (float)cnt : 1.f;
            g_selemb[((size_t)j * BSZ + b) * DK + t] = sum / denom;
        }
    }
}

// --------------- tiny converters / gram ----------------------------------------
__global__ void k_cvt(const float* __restrict__ e1w, const float* __restrict__ q2w,
                      const float* __restrict__ wih) {
    int i = blockIdx.x * 256 + threadIdx.x;
    if (i < 8192) g_e1t[i] = f2tf(e1w[i]);
    else if (i < 16384) g_q2t[i - 8192] = f2tf(q2w[i - 8192]);
    else if (i < 20480) g_wiht[i - 16384] = f2tf(wih[i - 16384]);
}

// Gram = whh @ whh^T (32x32) and rowmean/128 (32) of whh [32,128]
__global__ void k_gram(const float* __restrict__ whh) {
    __shared__ float wsh[4096];
    int t = threadIdx.x;
    for (int i = t; i < 4096; i += 256) wsh[i] = whh[i];
    __syncthreads();
    for (int e = t; e < 1024; e += 256) {
        int k = e >> 5, l = e & 31;
        float s = 0.f;
#pragma unroll 8
        for (int g = 0; g < 128; g++) s += wsh[k * 128 + g] * wsh[l * 128 + g];
        g_gram[e] = s;
    }
    if (t < 32) {
        float s = 0.f;
#pragma unroll 8
        for (int g = 0; g < 128; g++) s += wsh[t * 128 + g];
        g_rm[t] = s * (1.f / 128.f);
    }
}

// c2 = e2_b @ q1_w (8 blocks x 8 k-slices)
__global__ void k_c2(const float* __restrict__ e2b, const float* __restrict__ q1w) {
    __shared__ float part[8][32];
    int t = threadIdx.x;
    int col = blockIdx.x * 32 + (t & 31);
    int ks = t >> 5;
    float acc = 0.f;
    for (int k = ks * 128; k < ks * 128 + 128; k++) acc += e2b[k] * q1w[(size_t)k * DF + col];
    part[ks][t & 31] = acc;
    __syncthreads();
    if (t < 32) {
        float s = 0.f;
#pragma unroll
        for (int p = 0; p < 8; p++) s += part[p][t];
        g_c2[blockIdx.x * 32 + t] = s;
    }
}

// --------------- mega-fused (BM=128): u -> P -> relu -> x -> MMA gates -> LN ---
// smem floats: U u32[128][260] @0 (33280) | BS u32 @33280 (10240)
//              SEL u32[128][36] @43520 (4608) | (wih region unused now)
// tail aliases: XT u32[128][36] = sm[0..4608); GT float[128][132] = sm+8192
#define SMF_FLOATS 52224
__global__ void __launch_bounds__(256, 1)
k_fused(const float* __restrict__ e1b, const float* __restrict__ q2b,
        const float* __restrict__ ln_ig, const float* __restrict__ ln_ib) {
    extern __shared__ float sm[];
    uint32_t* U = (uint32_t*)sm;
    uint32_t* BS = (uint32_t*)(sm + 33280);
    uint32_t* SEL = (uint32_t*)(sm + 43520);
    uint32_t* XT = (uint32_t*)sm;          // [128][36] tf32 x (aliases U rows 0..17)
    float* GT = sm + 8192;                 // [128][132] fp32 gates

    const int t = threadIdx.x;
    const int wid = t >> 5, lane = t & 31;
    const int gid = lane >> 2, tig = lane & 3;
    const int warpM = wid & 3, warpN = wid >> 2;
    const int m0 = blockIdx.x * 128;
    const int step = m0 >> 9;
    const int b0 = m0 & 511;

    if (step == 0) {
#pragma unroll 4
        for (int p = 0; p < 32; p++) {
            int idx = t + p * 256;
            int r = idx >> 6, c4 = (idx & 63) * 4;
            float4 v = *(const float4*)&g_base[(size_t)(b0 + r) * 256 + c4];
            uint4 q;
            q.x = f2tf(fmaxf(v.x, 0.f)); q.y = f2tf(fmaxf(v.y, 0.f));
            q.z = f2tf(fmaxf(v.z, 0.f)); q.w = f2tf(fmaxf(v.w, 0.f));
            *(uint4*)&U[r * 260 + c4] = q;
        }
    } else {
#pragma unroll
        for (int p = 0; p < 4; p++) {
            int idx = t + p * 256;
            int r = idx >> 3, c4 = (idx & 7) * 4;
            float4 v = *(const float4*)&g_selemb[(size_t)(m0 - 512 + r) * 32 + c4];
            uint4 q;
            q.x = f2tf(v.x); q.y = f2tf(v.y); q.z = f2tf(v.z); q.w = f2tf(v.w);
            *(uint4*)&SEL[r * 36 + c4] = q;
        }
#pragma unroll
        for (int p = 0; p < 8; p++) {
            int q = t + p * 256;
            int r = q >> 6, c4 = (q & 63) * 4;
            *(uint4*)&BS[r * 264 + c4] = ((const uint4*)g_e1t)[q];
        }
        __syncthreads();

        float acc[2][16][4];
#pragma unroll
        for (int mt = 0; mt < 2; mt++)
#pragma unroll
            for (int j = 0; j < 16; j++) {
                acc[mt][j][0] = 0.f; acc[mt][j][1] = 0.f;
                acc[mt][j][2] = 0.f; acc[mt][j][3] = 0.f;
            }
#pragma unroll
        for (int kk = 0; kk < 32; kk += 8) {
#pragma unroll
            for (int mt = 0; mt < 2; mt++) {
                int rbase = warpM * 32 + mt * 16 + gid;
                uint32_t a0 = SEL[rbase * 36 + kk + tig];
                uint32_t a1 = SEL[(rbase + 8) * 36 + kk + tig];
                uint32_t a2 = SEL[rbase * 36 + kk + tig + 4];
                uint32_t a3 = SEL[(rbase + 8) * 36 + kk + tig + 4];
#pragma unroll
                for (int j = 0; j < 16; j++) {
                    int nb = warpN * 128 + j * 8;
                    uint32_t b0 = BS[(kk + tig) * 264 + nb + gid];
                    uint32_t b1 = BS[(kk + tig + 4) * 264 + nb + gid];
                    mma_tf32(acc[mt][j], a0, a1, a2, a3, b0, b1);
                }
            }
        }
#pragma unroll
        for (int mt = 0; mt < 2; mt++)
#pragma unroll
            for (int j = 0; j < 16; j++) {
                int cb = warpN * 128 + j * 8 + tig * 2;
                float bb0 = e1b[cb], bb1 = e1b[cb + 1];
#pragma unroll
                for (int h = 0; h < 2; h++) {
                    int r = warpM * 32 + mt * 16 + gid + h * 8;
                    U[r * 260 + cb] = f2tf(fmaxf(acc[mt][j][h * 2] + bb0, 0.f));
                    U[r * 260 + cb + 1] = f2tf(fmaxf(acc[mt][j][h * 2 + 1] + bb1, 0.f));
                }
            }
#pragma unroll
        for (int mt = 0; mt < 2; mt++)
#pragma unroll
            for (int j = 0; j < 16; j++) {
                acc[mt][j][0] = 0.f; acc[mt][j][1] = 0.f;
                acc[mt][j][2] = 0.f; acc[mt][j][3] = 0.f;
            }
        uint4 pw[8];
        const uint4* W2v = (const uint4*)g_W2;
#pragma unroll
        for (int p = 0; p < 8; p++) pw[p] = W2v[t + p * 256];
        for (int ch = 0; ch < 8; ch++) {
            __syncthreads();
#pragma unroll
            for (int p = 0; p < 8; p++) {
                int q = t + p * 256;
                int r = q >> 6, c4 = (q & 63) * 4;
                *(uint4*)&BS[r * 264 + c4] = pw[p];
            }
            if (ch + 1 < 8) {
#pragma unroll
                for (int p = 0; p < 8; p++) pw[p] = W2v[(ch + 1) * 2048 + t + p * 256];
            }
            __syncthreads();
#pragma unroll
            for (int kk = 0; kk < 32; kk += 8) {
                int kg = ch * 32 + kk;
#pragma unroll
                for (int mt = 0; mt < 2; mt++) {
                    int rbase = warpM * 32 + mt * 16 + gid;
                    uint32_t a0 = U[rbase * 260 + kg + tig];
                    uint32_t a1 = U[(rbase + 8) * 260 + kg + tig];
                    uint32_t a2 = U[rbase * 260 + kg + tig + 4];
                    uint32_t a3 = U[(rbase + 8) * 260 + kg + tig + 4];
#pragma unroll
                    for (int j = 0; j < 16; j++) {
                        int nb = warpN * 128 + j * 8;
                        uint32_t b0 = BS[(kk + tig) * 264 + nb + gid];
                        uint32_t b1 = BS[(kk + tig + 4) * 264 + nb + gid];
                        mma_tf32(acc[mt][j], a0, a1, a2, a3, b0, b1);
                    }
                }
            }
        }
        __syncthreads();
#pragma unroll
        for (int mt = 0; mt < 2; mt++)
#pragma unroll
            for (int j = 0; j < 16; j++) {
                int cb = warpN * 128 + j * 8 + tig * 2;
#pragma unroll
                for (int h = 0; h < 2; h++) {
                    int r = warpM * 32 + mt * 16 + gid + h * 8;
                    float2 bc = *(const float2*)&g_basec[(size_t)(b0 + r) * 256 + cb];
                    U[r * 260 + cb] = f2tf(fmaxf(acc[mt][j][h * 2] + bc.x, 0.f));
                    U[r * 260 + cb + 1] =
                        f2tf(fmaxf(acc[mt][j][h * 2 + 1] + bc.y, 0.f));
                }
            }
    }
    __syncthreads();

    // stage q2 (tf32 copy)
#pragma unroll
    for (int p = 0; p < 8; p++) {
        int q = t + p * 256;
        int r = q >> 3, c4 = (q & 7) * 4;
        *(uint4*)&BS[r * 40 + c4] = ((const uint4*)g_q2t)[q];
    }
    __syncthreads();

    // x = U @ q2 -> registers
    float ax[2][2][4];
#pragma unroll
    for (int mt = 0; mt < 2; mt++)
#pragma unroll
        for (int j = 0; j < 2; j++) {
            ax[mt][j][0] = 0.f; ax[mt][j][1] = 0.f;
            ax[mt][j][2] = 0.f; ax[mt][j][3] = 0.f;
        }
#pragma unroll 4
    for (int kk = 0; kk < 256; kk += 8) {
#pragma unroll
        for (int mt = 0; mt < 2; mt++) {
            int rbase = warpM * 32 + mt * 16 + gid;
            uint32_t a0 = U[rbase * 260 + kk + tig];
            uint32_t a1 = U[(rbase + 8) * 260 + kk + tig];
            uint32_t a2 = U[rbase * 260 + kk + tig + 4];
            uint32_t a3 = U[(rbase + 8) * 260 + kk + tig + 4];
#pragma unroll
            for (int j = 0; j < 2; j++) {
                int nb = warpN * 16 + j * 8;
                uint32_t b0 = BS[(kk + tig) * 40 + nb + gid];
                uint32_t b1 = BS[(kk + tig + 4) * 40 + nb + gid];
                mma_tf32(ax[mt][j], a0, a1, a2, a3, b0, b1);
            }
        }
    }
    __syncthreads();   // all U reads done before XT overwrite

    // XT = tf32(x + q2b); stage wih tf32 into BS [32][132]
#pragma unroll
    for (int mt = 0; mt < 2; mt++)
#pragma unroll
        for (int j = 0; j < 2; j++) {
            int cb = warpN * 16 + j * 8 + tig * 2;
            float qb0 = q2b[cb], qb1 = q2b[cb + 1];
#pragma unroll
            for (int h = 0; h < 2; h++) {
                int r = warpM * 32 + mt * 16 + gid + h * 8;
                XT[r * 36 + cb] = f2tf(ax[mt][j][h * 2] + qb0);
                XT[r * 36 + cb + 1] = f2tf(ax[mt][j][h * 2 + 1] + qb1);
            }
        }
#pragma unroll
    for (int p = 0; p < 16; p++) {
        int q = t + p * 256;
        int r = q >> 7, n = q & 127;
        BS[r * 132 + n] = g_wiht[q];
    }
    __syncthreads();

    // gates = XT @ wih  (M=128, N=128, K=32) via MMA -> GT fp32
    {
        float ag[2][8][4];
#pragma unroll
        for (int mt = 0; mt < 2; mt++)
#pragma unroll
            for (int j = 0; j < 8; j++) {
                ag[mt][j][0] = 0.f; ag[mt][j][1] = 0.f;
                ag[mt][j][2] = 0.f; ag[mt][j][3] = 0.f;
            }
#pragma unroll
        for (int kk = 0; kk < 32; kk += 8) {
#pragma unroll
            for (int mt = 0; mt < 2; mt++) {
                int rbase = warpM * 32 + mt * 16 + gid;
                uint32_t a0 = XT[rbase * 36 + kk + tig];
                uint32_t a1 = XT[(rbase + 8) * 36 + kk + tig];
                uint32_t a2 = XT[rbase * 36 + kk + tig + 4];
                uint32_t a3 = XT[(rbase + 8) * 36 + kk + tig + 4];
#pragma unroll
                for (int j = 0; j < 8; j++) {
                    int nb = warpN * 64 + j * 8;
                    uint32_t b0 = BS[(kk + tig) * 132 + nb + gid];
                    uint32_t b1 = BS[(kk + tig + 4) * 132 + nb + gid];
                    mma_tf32(ag[mt][j], a0, a1, a2, a3, b0, b1);
                }
            }
        }
        // GT (disjoint from XT region) — no sync needed before writes
#pragma unroll
        for (int mt = 0; mt < 2; mt++)
#pragma unroll
            for (int j = 0; j < 8; j++) {
                int cb = warpN * 64 + j * 8 + tig * 2;
#pragma unroll
                for (int h = 0; h < 2; h++) {
                    int r = warpM * 32 + mt * 16 + gid + h * 8;
                    GT[r * 132 + cb] = ag[mt][j][h * 2];
                    GT[r * 132 + cb + 1] = ag[mt][j][h * 2 + 1];
                }
            }
    }
    __syncthreads();

    // LN over GT rows -> g_gx
    {
        float lg[4], lb[4];
#pragma unroll
        for (int g = 0; g < 4; g++) {
            lg[g] = ln_ig[g * 32 + lane];
            lb[g] = ln_ib[g * 32 + lane];
        }
        for (int rr = 0; rr < 16; rr++) {
            int row = wid * 16 + rr;
            float acg[4];
#pragma unroll
            for (int g = 0; g < 4; g++) acg[g] = GT[row * 132 + g * 32 + lane];
            float s = acg[0] + acg[1] + acg[2] + acg[3];
            float m = wredsum(s) * (1.f / 128.f);
            float vs = 0.f;
#pragma unroll
            for (int g = 0; g < 4; g++) {
                float d = acg[g] - m;
                vs += d * d;
            }
            float v = wredsum(vs) * (1.f / 128.f);
            float rs = rsqrtf(v + 1e-5f);
#pragma unroll
            for (int g = 0; g < 4; g++)
                g_gx[(size_t)(m0 + row) * 128 + g * 32 + lane] =
                    (acg[g] - m) * rs * lg[g] + lb[g];
        }
    }
}

// ------------------- sequential LN-LSTM (warp/batch, Gram-LN) -------------------
__global__ void k_lstm(const float* __restrict__ whh, const float* __restrict__ ln_hg,
                       const float* __restrict__ ln_hb, const float* __restrict__ ln_cg,
                       const float* __restrict__ ln_cb) {
    __shared__ float wsh[32 * 128];
    __shared__ float gsh[32 * 32];
    __shared__ float rmsh[32];
    int t = threadIdx.x;
    for (int idx = t; idx < 4096; idx += 256) wsh[idx] = whh[idx];
    for (int idx = t; idx < 1024; idx += 256) gsh[idx] = g_gram[idx];
    if (t < 32) rmsh[t] = g_rm[t];
    __syncthreads();
    int lane = t & 31, w = t >> 5;
    int b = blockIdx.x * 8 + w;
    float h = 0.f, c = 0.f;
    float hg[4], hb[4];
#pragma unroll
    for (int g = 0; g < 4; g++) {
        int cc = g * 32 + lane;
        hg[g] = ln_hg[cc];
        hb[g] = ln_hb[cc];
    }
    float cgm = ln_cg[lane], cbm = ln_cb[lane];
    float gxr[4];
#pragma unroll
    for (int g = 0; g < 4; g++) gxr[g] = g_gx[(size_t)b * 128 + g * 32 + lane];
    for (int i = 0; i < SEQN; i++) {
        float gxn[4];
        if (i + 1 < SEQN) {
            size_t rn = (size_t)(i + 1) * BSZ + b;
#pragma unroll
            for (int g = 0; g < 4; g++) gxn[g] = g_gx[rn * 128 + g * 32 + lane];
        }
        float acc[4] = {0.f, 0.f, 0.f, 0.f};
        float accM = 0.f, wv = 0.f;
#pragma unroll
        for (int k = 0; k < 32; k++) {
            float hk = __shfl_sync(0xffffffffu, h, k);
#pragma unroll
            for (int g = 0; g < 4; g++) acc[g] += hk * wsh[k * 128 + g * 32 + lane];
            accM = fmaf(hk, rmsh[k], accM);
            wv = fmaf(hk, gsh[k * 32 + lane], wv);
        }
        float m = accM;
        float q = wredsum(h * wv);
        float v = fmaxf(q * (1.f / 128.f) - m * m, 0.f);
        float rs = rsqrtf(v + 1e-5f);
        float gate[4];
#pragma unroll
        for (int g = 0; g < 4; g++) gate[g] = gxr[g] + (acc[g] - m) * rs * hg[g] + hb[g];
        float ii = siga(gate[0]);
        float ff = siga(gate[1]);
        float gg = tanha(gate[2]);
        float oo = siga(gate[3]);
        float cn = ff * c + ii * gg;
        float s1 = cn, s2 = cn * cn;
#pragma unroll
        for (int o = 16; o; o >>= 1) {
            s1 += __shfl_xor_sync(0xffffffffu, s1, o);
            s2 += __shfl_xor_sync(0xffffffffu, s2, o);
        }
        float mc = s1 * (1.f / 32.f);
        float vc = fmaxf(s2 * (1.f / 32.f) - mc * mc, 0.f);
        c = (cn - mc) * rsqrtf(vc + 1e-5f) * cgm + cbm;
        h = oo * tanha(c);
        g_q[((size_t)i * BSZ + b) * DK + lane] = h;
#pragma unroll
        for (int g = 0; g < 4; g++) gxr[g] = gxn[g];
    }
}

// ------------------- logits + mask (grid BSZ x 2) -------------------------------
__global__ void k_logits(const int* __restrict__ en_arr, float* __restrict__ out) {
    __shared__ float Qsh[64 * 32];
    __shared__ float Ksh[256 * 34];
    __shared__ int rsh[256];
    int t = threadIdx.x;
    int b = blockIdx.x;
    int tile = blockIdx.y;
    int en = en_arr[b];
    for (int idx = t; idx < 2048; idx += 256) {
        int s = idx >> 5, k = idx & 31;
        Qsh[idx] = g_q[((size_t)s * BSZ + b) * 32 + k];
    }
    const u64* Q2 = (const u64*)Qsh;
    int n0 = tile * 256;
    for (int idx = t; idx < 8192; idx += 256) {
        int n = idx >> 5, k = idx & 31;
        Ksh[n * 34 + k] = g_key[((size_t)b * ENT + n0 + n) * 32 + k];
    }
    rsh[t] = g_removed[(size_t)b * ENP1 + n0 + t];
    __syncthreads();
    u64 kreg[16];
#pragma unroll
    for (int kp = 0; kp < 16; kp++) {
        float2 kk = *(const float2*)&Ksh[t * 34 + kp * 2];
        asm("mov.b64 %0,{%1,%2};" : "=l"(kreg[kp]) : "f"(kk.x), "f"(kk.y));
    }
    int rstep = rsh[t];
    int n = n0 + t;
    for (int s = 0; s < SEQN; s++) {
        u64 a0 = 0ull, a1 = 0ull;
#pragma unroll
        for (int kp = 0; kp < 16; kp += 2) {
            fma2(a0, kreg[kp], Q2[s * 16 + kp]);
            fma2(a1, kreg[kp + 1], Q2[s * 16 + kp + 1]);
        }
        float2 f0 = up2(a0), f1 = up2(a1);
        float dot = (f0.x + f0.y) + (f1.x + f1.y);
        bool keep = (n < en) ? (rstep > s) : ((n == en) ? (s >= 1 && rstep > s) : false);
        out[((size_t)b * SEQN + s) * ENP1 + n] = keep ? dot : -1e9f;
    }
    if (tile == 1 && t < SEQN) out[((size_t)b * SEQN + t) * ENP1 + 512] = -1e9f;
}

// ------------------------------- launch ----------------------------------------
extern "C" void kernel_launch(void* const* d_in, const int* in_sizes, int n_in,
                              void* d_out, int out_size) {
    const float* ent = (const float*)d_in[0];
    const float* ar = (const float*)d_in[1];
    const int* entity_num = (const int*)d_in[2];
    const int* sel = (const int*)d_in[3];
    const int* selnum = (const int*)d_in[4];
    const float* key_w = (const float*)d_in[5];
    const float* key_b = (const float*)d_in[6];
    const float* q1w = (const float*)d_in[7];
    const float* q1b = (const float*)d_in[8];
    const float* q2w = (const float*)d_in[9];
    const float* q2b = (const float*)d_in[10];
    const float* e1w = (const float*)d_in[11];
    const float* e1b = (const float*)d_in[12];
    const float* e2w = (const float*)d_in[13];
    const float* e2b = (const float*)d_in[14];
    const float* endv = (const float*)d_in[15];
    const float* wih = (const float*)d_in[16];
    const float* whh = (const float*)d_in[17];
    const float* ln_ig = (const float*)d_in[18];
    const float* ln_ib = (const float*)d_in[19];
    const float* ln_hg = (const float*)d_in[20];
    const float* ln_hb = (const float*)d_in[21];
    const float* ln_cg = (const float*)d_in[22];
    const float* ln_cb = (const float*)d_in[23];
    float* out = (float*)d_out;

    void *pKey, *pBase, *pBasec, *pW2, *pC2;
    cudaGetSymbolAddress(&pKey, g_key);
    cudaGetSymbolAddress(&pBase, g_base);
    cudaGetSymbolAddress(&pBasec, g_basec);
    cudaGetSymbolAddress(&pW2, g_W2);
    cudaGetSymbolAddress(&pC2, g_c2);

    static cudaStream_t sB = 0, sC = 0, sD = 0;
    static cudaEvent_t eFork = 0, eB = 0, eW2 = 0, eKey = 0, eGr = 0;
    if (!sB) {
        int lo, hi;
        cudaDeviceGetStreamPriorityRange(&lo, &hi);
        cudaStreamCreateWithFlags(&sB, cudaStreamNonBlocking);
        cudaStreamCreateWithFlags(&sC, cudaStreamNonBlocking);
        cudaStreamCreateWithPriority(&sD, cudaStreamNonBlocking, lo);
        cudaEventCreateWithFlags(&eFork, cudaEventDisableTiming);
        cudaEventCreateWithFlags(&eB, cudaEventDisableTiming);
        cudaEventCreateWithFlags(&eW2, cudaEventDisableTiming);
        cudaEventCreateWithFlags(&eKey, cudaEventDisableTiming);
        cudaEventCreateWithFlags(&eGr, cudaEventDisableTiming);
        cudaFuncSetAttribute(k_fused, cudaFuncAttributeMaxDynamicSharedMemorySize,
                             SMF_FLOATS * 4);
    }

    cudaEventRecord(eFork, 0);
    cudaStreamWaitEvent(sB, eFork, 0);
    cudaStreamWaitEvent(sC, eFork, 0);
    cudaStreamWaitEvent(sD, eFork, 0);

    // launch order arranged so k_fused is the 6th kernel (ncu -s 5 captures it)
    k_selkey<<<BSZ, 256>>>(ent, key_w, key_b, sel, entity_num, selnum);      // 0
    k_c2<<<8, 256, 0, sB>>>(e2b, q1w);                                        // 1
    k_mma<32, 7><<<dim3(BSZ / 64, DF / 32), 256, 0, sB>>>(                    // 2
        ar, q1w, q1b, (float*)pBase, DIN, DF, (const float*)pC2, nullptr, (float*)pBasec);
    cudaEventRecord(eB, sB);
    k_cvt<<<80, 256, 0, sC>>>(e1w, q2w, wih);                                 // 3
    k_mma<32, 6><<<dim3(DF / 64, DF / 32), 256, 0, sC>>>(                     // 4
        e2w, q1w, nullptr, (float*)pW2, DIN, DF, nullptr, nullptr, nullptr);
    cudaEventRecord(eW2, sC);

    cudaStreamWaitEvent(0, eB, 0);
    cudaStreamWaitEvent(0, eW2, 0);
    k_fused<<<SEQN * BSZ / 128, 256, SMF_FLOATS * 4>>>(e1b, q2b, ln_ig, ln_ib);  // 5

    k_gram<<<1, 256, 0, sC>>>(whh);                                           // 6
    cudaEventRecord(eGr, sC);
    k_mma<32, 2><<<dim3(BSZ * ENT / 64, 1), 256, 0, sD>>>(                    // 7
        ent, key_w, key_b, (float*)pKey, DF, DK, endv, entity_num, nullptr);
    cudaEventRecord(eKey, sD);

    cudaStreamWaitEvent(0, eGr, 0);
    k_lstm<<<BSZ / 8, 256>>>(whh, ln_hg, ln_hb, ln_cg, ln_cb);                // 8
    cudaStreamWaitEvent(0, eKey, 0);
    k_logits<<<dim3(BSZ, 2), 256>>>(entity_num, out);                         // 9
    (void)in_sizes;
    (void)n_in;
    (void)out_size;
}

// round 15
// speedup vs baseline: 1.8416x; 1.0243x over previous
#include <cuda_runtime.h>
#include <cuda_bf16.h>
#include <math.h>
#include <stdint.h>

#define BSZ 512
#define ENT 512
#define SEQN 64
#define DK 32
#define DF 256
#define DIN 1024
#define NGATE 128
#define ENP1 513

typedef unsigned long long u64;

// ----------------------------- static scratch --------------------------------
__device__ __nv_bfloat16 g_key[(size_t)BSZ * ENT * DK];   // keys in bf16
__device__ int   g_removed[(size_t)BSZ * ENP1];
__device__ float g_selemb[(size_t)SEQN * BSZ * DK];
__device__ float g_base[(size_t)BSZ * DF];
__device__ float g_basec[(size_t)BSZ * DF];   // base + c2
__device__ float g_W2[(size_t)DF * DF];       // tf32 BITS
__device__ float g_c2[DF];
__device__ uint32_t g_e1t[32 * 256];          // e1w tf32 bits
__device__ uint32_t g_q2t[256 * 32];          // q2w tf32 bits
__device__ uint32_t g_wiht[32 * 128];         // wih tf32 bits
__device__ float g_gram[32 * 32];             // whh @ whh^T
__device__ float g_rm[32];                    // row-mean of whh (/128 folded)
__device__ float g_gx[(size_t)SEQN * BSZ * NGATE];
__device__ float g_q[(size_t)SEQN * BSZ * DK];

// ----------------------------- helpers ---------------------------------------
__device__ __forceinline__ float wredsum(float v) {
#pragma unroll
    for (int o = 16; o; o >>= 1) v += __shfl_xor_sync(0xffffffffu, v, o);
    return v;
}
__device__ __forceinline__ void fma2(u64& d, u64 a, u64 b) {
    asm("fma.rn.f32x2 %0,%1,%2,%0;" : "+l"(d) : "l"(a), "l"(b));
}
__device__ __forceinline__ float2 up2(u64 v) {
    float2 f;
    asm("mov.b64 {%0,%1},%2;" : "=f"(f.x), "=f"(f.y) : "l"(v));
    return f;
}
__device__ __forceinline__ uint32_t f2tf(float f) {
    uint32_t r;
    asm("cvt.rna.tf32.f32 %0, %1;" : "=r"(r) : "f"(f));
    return r;
}
__device__ __forceinline__ float tanha(float x) {
    float y;
    asm("tanh.approx.f32 %0, %1;" : "=f"(y) : "f"(x));
    return y;
}
__device__ __forceinline__ float siga(float x) {
    return 0.5f * tanha(0.5f * x) + 0.5f;
}
__device__ __forceinline__ void mma_tf32(float* c, uint32_t a0, uint32_t a1, uint32_t a2,
                                         uint32_t a3, uint32_t b0, uint32_t b1) {
    asm volatile(
        "mma.sync.aligned.m16n8k8.row.col.f32.tf32.tf32.f32 "
        "{%0,%1,%2,%3},{%4,%5,%6,%7},{%8,%9},{%0,%1,%2,%3};"
        : "+f"(c[0]), "+f"(c[1]), "+f"(c[2]), "+f"(c[3])
        : "r"(a0), "r"(a1), "r"(a2), "r"(a3), "r"(b0), "r"(b1));
}

// --------------- tf32 tensor-core GEMM (standalone) ---------------------------
// EPI: 2 +bias & end-scatter -> bf16 C (key) | 6 plain -> C tf32 BITS | 7 +bias -> C, +xb -> C2
template <int BN, int EPI>
__global__ void k_mma(const float* __restrict__ A, const float* __restrict__ B,
                      const float* __restrict__ bias, float* __restrict__ C,
                      int K, int N, const float* __restrict__ xb,
                      const int* __restrict__ xi, float* __restrict__ C2) {
    constexpr int BM = 64, KC = 32;
    constexpr int NBLD = (KC * BN) / 1024;
    constexpr int NT = BN / 16;
    __shared__ uint32_t As[BM][KC + 4];
    __shared__ uint32_t Bs[KC][BN + 4];
    const int t = threadIdx.x;
    const int wid = t >> 5, lane = t & 31;
    const int gid = lane >> 2, tig = lane & 3;
    const int warpM = wid & 3, warpN = wid >> 2;
    const int m0 = blockIdx.x * BM;
    const int n0 = blockIdx.y * BN;

    float cr[NT][4];
#pragma unroll
    for (int j = 0; j < NT; j++) {
        cr[j][0] = 0.f; cr[j][1] = 0.f; cr[j][2] = 0.f; cr[j][3] = 0.f;
    }

    const int ar0 = t >> 3;
    const int ak = (t & 7) * 4;
    constexpr int BQ = BN / 4;
    const int br0 = t / BQ;
    const int bn = (t % BQ) * 4;

    float4 pa0, pa1, pb[NBLD];
    pa0 = *(const float4*)&A[(size_t)(m0 + ar0) * K + ak];
    pa1 = *(const float4*)&A[(size_t)(m0 + ar0 + 32) * K + ak];
#pragma unroll
    for (int i = 0; i < NBLD; i++) {
        int kr = br0 + i * (256 / BQ);
        pb[i] = *(const float4*)&B[(size_t)kr * N + n0 + bn];
    }

    const int nch = K / KC;
    for (int ch = 0; ch < nch; ch++) {
        __syncthreads();
        {
            uint4 q;
            q.x = f2tf(pa0.x); q.y = f2tf(pa0.y); q.z = f2tf(pa0.z); q.w = f2tf(pa0.w);
            *(uint4*)&As[ar0][ak] = q;
            q.x = f2tf(pa1.x); q.y = f2tf(pa1.y); q.z = f2tf(pa1.z); q.w = f2tf(pa1.w);
            *(uint4*)&As[ar0 + 32][ak] = q;
#pragma unroll
            for (int i = 0; i < NBLD; i++) {
                int kr = br0 + i * (256 / BQ);
                q.x = f2tf(pb[i].x); q.y = f2tf(pb[i].y);
                q.z = f2tf(pb[i].z); q.w = f2tf(pb[i].w);
                *(uint4*)&Bs[kr][bn] = q;
            }
        }
        if (ch + 1 < nch) {
            int k0 = (ch + 1) * KC;
            pa0 = *(const float4*)&A[(size_t)(m0 + ar0) * K + k0 + ak];
            pa1 = *(const float4*)&A[(size_t)(m0 + ar0 + 32) * K + k0 + ak];
#pragma unroll
            for (int i = 0; i < NBLD; i++) {
                int kr = k0 + br0 + i * (256 / BQ);
                pb[i] = *(const float4*)&B[(size_t)kr * N + n0 + bn];
            }
        }
        __syncthreads();
#pragma unroll
        for (int kk = 0; kk < KC; kk += 8) {
            uint32_t a0 = As[warpM * 16 + gid][kk + tig];
            uint32_t a1 = As[warpM * 16 + gid + 8][kk + tig];
            uint32_t a2 = As[warpM * 16 + gid][kk + tig + 4];
            uint32_t a3 = As[warpM * 16 + gid + 8][kk + tig + 4];
#pragma unroll
            for (int j = 0; j < NT; j++) {
                int nb = warpN * (BN / 2) + j * 8;
                uint32_t b0 = Bs[kk + tig][nb + gid];
                uint32_t b1 = Bs[kk + tig + 4][nb + gid];
                mma_tf32(cr[j], a0, a1, a2, a3, b0, b1);
            }
        }
    }

    const int rb = m0 + warpM * 16 + gid;
#pragma unroll
    for (int j = 0; j < NT; j++) {
        int cb = n0 + warpN * (BN / 2) + j * 8 + tig * 2;
#pragma unroll
        for (int h = 0; h < 2; h++) {
            int m = rb + h * 8;
            float v0 = cr[j][h * 2 + 0];
            float v1 = cr[j][h * 2 + 1];
            if (EPI == 2) {
                int en = xi[m0 >> 9];
                float o0, o1;
                if ((m & 511) == en) {
                    o0 = xb[cb];
                    o1 = xb[cb + 1];
                } else {
                    o0 = v0 + bias[cb];
                    o1 = v1 + bias[cb + 1];
                }
                __nv_bfloat16* kp = (__nv_bfloat16*)C;
                *(__nv_bfloat162*)&kp[(size_t)m * N + cb] =
                    __floats2bfloat162_rn(o0, o1);
            } else if (EPI == 6) {
                ((uint32_t*)C)[(size_t)m * N + cb] = f2tf(v0);
                ((uint32_t*)C)[(size_t)m * N + cb + 1] = f2tf(v1);
            } else if (EPI == 7) {
                float o0 = v0 + bias[cb], o1 = v1 + bias[cb + 1];
                C[(size_t)m * N + cb] = o0;
                C[(size_t)m * N + cb + 1] = o1;
                C2[(size_t)m * N + cb] = o0 + xb[cb];
                C2[(size_t)m * N + cb + 1] = o1 + xb[cb + 1];
            }
        }
    }
}

// --------------- selkey gathered GEMM + removed scatter + pooled-emb scan ------
__global__ void __launch_bounds__(256) k_selkey(const float* __restrict__ ent,
                                                const float* __restrict__ kw,
                                                const float* __restrict__ kb,
                                                const int* __restrict__ sel,
                                                const int* __restrict__ en_arr,
                                                const int* __restrict__ selnum) {
    __shared__ uint32_t AS[64 * 68];
    __shared__ uint32_t BS[64 * 36];
    __shared__ int ssh[64];
    __shared__ int inc[64];
    const int t = threadIdx.x;
    const int b = blockIdx.x;
    const int wid = t >> 5, lane = t & 31;
    const int gid = lane >> 2, tig = lane & 3;
    const int warpM = wid & 3, warpN = wid >> 2;
    const int en = en_arr[b];

    if (t < 64) ssh[t] = sel[b * SEQN + t];
    for (int n = t; n < ENP1; n += 256) g_removed[(size_t)b * ENP1 + n] = 65;
    __syncthreads();
    if (t < 64) atomicMin(&g_removed[(size_t)b * ENP1 + ssh[t]], t + 1);
    if (t < 64) {
        int sj = ssh[t];
        bool first = true, endf = (sj == en);
        for (int k = 0; k < t; k++) {
            int sk = ssh[k];
            if (sk == sj) first = false;
            if (sk == en) endf = true;
        }
        inc[t] = (first && !endf) ? 1 : 0;
    }

    float4 pa[4], pb[2];
#pragma unroll
    for (int p = 0; p < 4; p++) {
        int idx = t + p * 256;
        int r = idx >> 4, c4 = (idx & 15) * 4;
        pa[p] = *(const float4*)&ent[((size_t)b * ENT + ssh[r]) * 256 + c4];
    }
#pragma unroll
    for (int p = 0; p < 2; p++) {
        int idx = t + p * 256;
        int r = idx >> 3, c4 = (idx & 7) * 4;
        pb[p] = *(const float4*)&kw[(size_t)r * 32 + c4];
    }

    float acc[2][4];
    acc[0][0] = acc[0][1] = acc[0][2] = acc[0][3] = 0.f;
    acc[1][0] = acc[1][1] = acc[1][2] = acc[1][3] = 0.f;

    for (int ch = 0; ch < 4; ch++) {
        __syncthreads();
#pragma unroll
        for (int p = 0; p < 4; p++) {
            int idx = t + p * 256;
            int r = idx >> 4, c4 = (idx & 15) * 4;
            AS[r * 68 + c4 + 0] = f2tf(pa[p].x);
            AS[r * 68 + c4 + 1] = f2tf(pa[p].y);
            AS[r * 68 + c4 + 2] = f2tf(pa[p].z);
            AS[r * 68 + c4 + 3] = f2tf(pa[p].w);
        }
#pragma unroll
        for (int p = 0; p < 2; p++) {
            int idx = t + p * 256;
            int r = idx >> 3, c4 = (idx & 7) * 4;
            BS[r * 36 + c4 + 0] = f2tf(pb[p].x);
            BS[r * 36 + c4 + 1] = f2tf(pb[p].y);
            BS[r * 36 + c4 + 2] = f2tf(pb[p].z);
            BS[r * 36 + c4 + 3] = f2tf(pb[p].w);
        }
        if (ch + 1 < 4) {
            int k0 = (ch + 1) * 64;
#pragma unroll
            for (int p = 0; p < 4; p++) {
                int idx = t + p * 256;
                int r = idx >> 4, c4 = (idx & 15) * 4;
                pa[p] = *(const float4*)&ent[((size_t)b * ENT + ssh[r]) * 256 + k0 + c4];
            }
#pragma unroll
            for (int p = 0; p < 2; p++) {
                int idx = t + p * 256;
                int r = idx >> 3, c4 = (idx & 7) * 4;
                pb[p] = *(const float4*)&kw[(size_t)(k0 + r) * 32 + c4];
            }
        }
        __syncthreads();
#pragma unroll
        for (int kk = 0; kk < 64; kk += 8) {
            uint32_t a0 = AS[(warpM * 16 + gid) * 68 + kk + tig];
            uint32_t a1 = AS[(warpM * 16 + gid + 8) * 68 + kk + tig];
            uint32_t a2 = AS[(warpM * 16 + gid) * 68 + kk + tig + 4];
            uint32_t a3 = AS[(warpM * 16 + gid + 8) * 68 + kk + tig + 4];
#pragma unroll
            for (int j = 0; j < 2; j++) {
                int nb = warpN * 16 + j * 8;
                uint32_t b0 = BS[(kk + tig) * 36 + nb + gid];
                uint32_t b1 = BS[(kk + tig + 4) * 36 + nb + gid];
                mma_tf32(acc[j], a0, a1, a2, a3, b0, b1);
            }
        }
    }
    __syncthreads();
    float* SK = (float*)BS;
#pragma unroll
    for (int j = 0; j < 2; j++) {
        int cb = warpN * 16 + j * 8 + tig * 2;
        float b0 = kb[cb], b1 = kb[cb + 1];
#pragma unroll
        for (int h = 0; h < 2; h++) {
            int r = warpM * 16 + gid + h * 8;
            SK[r * 33 + cb] = acc[j][h * 2] + b0;
            SK[r * 33 + cb + 1] = acc[j][h * 2 + 1] + b1;
        }
    }
    __syncthreads();
    if (t < 32) {
        int sn = selnum[b];
        float sum = 0.f;
        int cnt = 0;
        for (int j = 0; j < SEQN; j++) {
            if (inc[j]) {
                sum += SK[j * 33 + t];
                cnt++;
            }
            float denom = (sn != 0 && cnt > 0) ? (float)cnt : 1.f;
            g_selemb[((size_t)j * BSZ + b) * DK + t] = sum / denom;
        }
    }
}

// --------------- tiny converters / gram ----------------------------------------
__global__ void k_cvt(const float* __restrict__ e1w, const float* __restrict__ q2w,
                      const float* __restrict__ wih) {
    int i = blockIdx.x * 256 + threadIdx.x;
    if (i < 8192) g_e1t[i] = f2tf(e1w[i]);
    else if (i < 16384) g_q2t[i - 8192] = f2tf(q2w[i - 8192]);
    else if (i < 20480) g_wiht[i - 16384] = f2tf(wih[i - 16384]);
}

// Gram = whh @ whh^T (32x32) and rowmean/128 (32) of whh [32,128]
__global__ void k_gram(const float* __restrict__ whh) {
    __shared__ float wsh[4096];
    int t = threadIdx.x;
    for (int i = t; i < 4096; i += 256) wsh[i] = whh[i];
    __syncthreads();
    for (int e = t; e < 1024; e += 256) {
        int k = e >> 5, l = e & 31;
        float s = 0.f;
#pragma unroll 8
        for (int g = 0; g < 128; g++) s += wsh[k * 128 + g] * wsh[l * 128 + g];
        g_gram[e] = s;
    }
    if (t < 32) {
        float s = 0.f;
#pragma unroll 8
        for (int g = 0; g < 128; g++) s += wsh[t * 128 + g];
        g_rm[t] = s * (1.f / 128.f);
    }
}

// c2 = e2_b @ q1_w (8 blocks x 8 k-slices)
__global__ void k_c2(const float* __restrict__ e2b, const float* __restrict__ q1w) {
    __shared__ float part[8][32];
    int t = threadIdx.x;
    int col = blockIdx.x * 32 + (t & 31);
    int ks = t >> 5;
    float acc = 0.f;
    for (int k = ks * 128; k < ks * 128 + 128; k++) acc += e2b[k] * q1w[(size_t)k * DF + col];
    part[ks][t & 31] = acc;
    __syncthreads();
    if (t < 32) {
        float s = 0.f;
#pragma unroll
        for (int p = 0; p < 8; p++) s += part[p][t];
        g_c2[blockIdx.x * 32 + t] = s;
    }
}

// --------------- mega-fused (BM=128): u -> P -> relu -> x -> MMA gates -> LN ---
#define SMF_FLOATS 52224
__global__ void __launch_bounds__(256, 1)
k_fused(const float* __restrict__ e1b, const float* __restrict__ q2b,
        const float* __restrict__ ln_ig, const float* __restrict__ ln_ib) {
    extern __shared__ float sm[];
    uint32_t* U = (uint32_t*)sm;
    uint32_t* BS = (uint32_t*)(sm + 33280);
    uint32_t* SEL = (uint32_t*)(sm + 43520);
    uint32_t* XT = (uint32_t*)sm;          // [128][36] tf32 x
    float* GT = sm + 8192;                 // [128][132] fp32 gates

    const int t = threadIdx.x;
    const int wid = t >> 5, lane = t & 31;
    const int gid = lane >> 2, tig = lane & 3;
    const int warpM = wid & 3, warpN = wid >> 2;
    const int m0 = blockIdx.x * 128;
    const int step = m0 >> 9;
    const int b0 = m0 & 511;

    if (step == 0) {
#pragma unroll 4
        for (int p = 0; p < 32; p++) {
            int idx = t + p * 256;
            int r = idx >> 6, c4 = (idx & 63) * 4;
            float4 v = *(const float4*)&g_base[(size_t)(b0 + r) * 256 + c4];
            uint4 q;
            q.x = f2tf(fmaxf(v.x, 0.f)); q.y = f2tf(fmaxf(v.y, 0.f));
            q.z = f2tf(fmaxf(v.z, 0.f)); q.w = f2tf(fmaxf(v.w, 0.f));
            *(uint4*)&U[r * 260 + c4] = q;
        }
    } else {
#pragma unroll
        for (int p = 0; p < 4; p++) {
            int idx = t + p * 256;
            int r = idx >> 3, c4 = (idx & 7) * 4;
            float4 v = *(const float4*)&g_selemb[(size_t)(m0 - 512 + r) * 32 + c4];
            uint4 q;
            q.x = f2tf(v.x); q.y = f2tf(v.y); q.z = f2tf(v.z); q.w = f2tf(v.w);
            *(uint4*)&SEL[r * 36 + c4] = q;
        }
#pragma unroll
        for (int p = 0; p < 8; p++) {
            int q = t + p * 256;
            int r = q >> 6, c4 = (q & 63) * 4;
            *(uint4*)&BS[r * 264 + c4] = ((const uint4*)g_e1t)[q];
        }
        __syncthreads();

        float acc[2][16][4];
#pragma unroll
        for (int mt = 0; mt < 2; mt++)
#pragma unroll
            for (int j = 0; j < 16; j++) {
                acc[mt][j][0] = 0.f; acc[mt][j][1] = 0.f;
                acc[mt][j][2] = 0.f; acc[mt][j][3] = 0.f;
            }
#pragma unroll
        for (int kk = 0; kk < 32; kk += 8) {
#pragma unroll
            for (int mt = 0; mt < 2; mt++) {
                int rbase = warpM * 32 + mt * 16 + gid;
                uint32_t a0 = SEL[rbase * 36 + kk + tig];
                uint32_t a1 = SEL[(rbase + 8) * 36 + kk + tig];
                uint32_t a2 = SEL[rbase * 36 + kk + tig + 4];
                uint32_t a3 = SEL[(rbase + 8) * 36 + kk + tig + 4];
#pragma unroll
                for (int j = 0; j < 16; j++) {
                    int nb = warpN * 128 + j * 8;
                    uint32_t b0 = BS[(kk + tig) * 264 + nb + gid];
                    uint32_t b1 = BS[(kk + tig + 4) * 264 + nb + gid];
                    mma_tf32(acc[mt][j], a0, a1, a2, a3, b0, b1);
                }
            }
        }
#pragma unroll
        for (int mt = 0; mt < 2; mt++)
#pragma unroll
            for (int j = 0; j < 16; j++) {
                int cb = warpN * 128 + j * 8 + tig * 2;
                float bb0 = e1b[cb], bb1 = e1b[cb + 1];
#pragma unroll
                for (int h = 0; h < 2; h++) {
                    int r = warpM * 32 + mt * 16 + gid + h * 8;
                    U[r * 260 + cb] = f2tf(fmaxf(acc[mt][j][h * 2] + bb0, 0.f));
                    U[r * 260 + cb + 1] = f2tf(fmaxf(acc[mt][j][h * 2 + 1] + bb1, 0.f));
                }
            }
#pragma unroll
        for (int mt = 0; mt < 2; mt++)
#pragma unroll
            for (int j = 0; j < 16; j++) {
                acc[mt][j][0] = 0.f; acc[mt][j][1] = 0.f;
                acc[mt][j][2] = 0.f; acc[mt][j][3] = 0.f;
            }
        uint4 pw[8];
        const uint4* W2v = (const uint4*)g_W2;
#pragma unroll
        for (int p = 0; p < 8; p++) pw[p] = W2v[t + p * 256];
        for (int ch = 0; ch < 8; ch++) {
            __syncthreads();
#pragma unroll
            for (int p = 0; p < 8; p++) {
                int q = t + p * 256;
                int r = q >> 6, c4 = (q & 63) * 4;
                *(uint4*)&BS[r * 264 + c4] = pw[p];
            }
            if (ch + 1 < 8) {
#pragma unroll
                for (int p = 0; p < 8; p++) pw[p] = W2v[(ch + 1) * 2048 + t + p * 256];
            }
            __syncthreads();
#pragma unroll
            for (int kk = 0; kk < 32; kk += 8) {
                int kg = ch * 32 + kk;
#pragma unroll
                for (int mt = 0; mt < 2; mt++) {
                    int rbase = warpM * 32 + mt * 16 + gid;
                    uint32_t a0 = U[rbase * 260 + kg + tig];
                    uint32_t a1 = U[(rbase + 8) * 260 + kg + tig];
                    uint32_t a2 = U[rbase * 260 + kg + tig + 4];
                    uint32_t a3 = U[(rbase + 8) * 260 + kg + tig + 4];
#pragma unroll
                    for (int j = 0; j < 16; j++) {
                        int nb = warpN * 128 + j * 8;
                        uint32_t b0 = BS[(kk + tig) * 264 + nb + gid];
                        uint32_t b1 = BS[(kk + tig + 4) * 264 + nb + gid];
                        mma_tf32(acc[mt][j], a0, a1, a2, a3, b0, b1);
                    }
                }
            }
        }
        __syncthreads();
#pragma unroll
        for (int mt = 0; mt < 2; mt++)
#pragma unroll
            for (int j = 0; j < 16; j++) {
                int cb = warpN * 128 + j * 8 + tig * 2;
#pragma unroll
                for (int h = 0; h < 2; h++) {
                    int r = warpM * 32 + mt * 16 + gid + h * 8;
                    float2 bc = *(const float2*)&g_basec[(size_t)(b0 + r) * 256 + cb];
                    U[r * 260 + cb] = f2tf(fmaxf(acc[mt][j][h * 2] + bc.x, 0.f));
                    U[r * 260 + cb + 1] =
                        f2tf(fmaxf(acc[mt][j][h * 2 + 1] + bc.y, 0.f));
                }
            }
    }
    __syncthreads();

    // stage q2 (tf32 copy)
#pragma unroll
    for (int p = 0; p < 8; p++) {
        int q = t + p * 256;
        int r = q >> 3, c4 = (q & 7) * 4;
        *(uint4*)&BS[r * 40 + c4] = ((const uint4*)g_q2t)[q];
    }
    __syncthreads();

    // x = U @ q2 -> registers
    float ax[2][2][4];
#pragma unroll
    for (int mt = 0; mt < 2; mt++)
#pragma unroll
        for (int j = 0; j < 2; j++) {
            ax[mt][j][0] = 0.f; ax[mt][j][1] = 0.f;
            ax[mt][j][2] = 0.f; ax[mt][j][3] = 0.f;
        }
#pragma unroll 4
    for (int kk = 0; kk < 256; kk += 8) {
#pragma unroll
        for (int mt = 0; mt < 2; mt++) {
            int rbase = warpM * 32 + mt * 16 + gid;
            uint32_t a0 = U[rbase * 260 + kk + tig];
            uint32_t a1 = U[(rbase + 8) * 260 + kk + tig];
            uint32_t a2 = U[rbase * 260 + kk + tig + 4];
            uint32_t a3 = U[(rbase + 8) * 260 + kk + tig + 4];
#pragma unroll
            for (int j = 0; j < 2; j++) {
                int nb = warpN * 16 + j * 8;
                uint32_t b0 = BS[(kk + tig) * 40 + nb + gid];
                uint32_t b1 = BS[(kk + tig + 4) * 40 + nb + gid];
                mma_tf32(ax[mt][j], a0, a1, a2, a3, b0, b1);
            }
        }
    }
    __syncthreads();

    // XT = tf32(x + q2b); stage wih tf32 into BS [32][132]
#pragma unroll
    for (int mt = 0; mt < 2; mt++)
#pragma unroll
        for (int j = 0; j < 2; j++) {
            int cb = warpN * 16 + j * 8 + tig * 2;
            float qb0 = q2b[cb], qb1 = q2b[cb + 1];
#pragma unroll
            for (int h = 0; h < 2; h++) {
                int r = warpM * 32 + mt * 16 + gid + h * 8;
                XT[r * 36 + cb] = f2tf(ax[mt][j][h * 2] + qb0);
                XT[r * 36 + cb + 1] = f2tf(ax[mt][j][h * 2 + 1] + qb1);
            }
        }
#pragma unroll
    for (int p = 0; p < 16; p++) {
        int q = t + p * 256;
        int r = q >> 7, n = q & 127;
        BS[r * 132 + n] = g_wiht[q];
    }
    __syncthreads();

    // gates = XT @ wih  (M=128, N=128, K=32) via MMA -> GT fp32
    {
        float ag[2][8][4];
#pragma unroll
        for (int mt = 0; mt < 2; mt++)
#pragma unroll
            for (int j = 0; j < 8; j++) {
                ag[mt][j][0] = 0.f; ag[mt][j][1] = 0.f;
                ag[mt][j][2] = 0.f; ag[mt][j][3] = 0.f;
            }
#pragma unroll
        for (int kk = 0; kk < 32; kk += 8) {
#pragma unroll
            for (int mt = 0; mt < 2; mt++) {
                int rbase = warpM * 32 + mt * 16 + gid;
                uint32_t a0 = XT[rbase * 36 + kk + tig];
                uint32_t a1 = XT[(rbase + 8) * 36 + kk + tig];
                uint32_t a2 = XT[rbase * 36 + kk + tig + 4];
                uint32_t a3 = XT[(rbase + 8) * 36 + kk + tig + 4];
#pragma unroll
                for (int j = 0; j < 8; j++) {
                    int nb = warpN * 64 + j * 8;
                    uint32_t b0 = BS[(kk + tig) * 132 + nb + gid];
                    uint32_t b1 = BS[(kk + tig + 4) * 132 + nb + gid];
                    mma_tf32(ag[mt][j], a0, a1, a2, a3, b0, b1);
                }
            }
        }
#pragma unroll
        for (int mt = 0; mt < 2; mt++)
#pragma unroll
            for (int j = 0; j < 8; j++) {
                int cb = warpN * 64 + j * 8 + tig * 2;
#pragma unroll
                for (int h = 0; h < 2; h++) {
                    int r = warpM * 32 + mt * 16 + gid + h * 8;
                    GT[r * 132 + cb] = ag[mt][j][h * 2];
                    GT[r * 132 + cb + 1] = ag[mt][j][h * 2 + 1];
                }
            }
    }
    __syncthreads();

    // LN over GT rows -> g_gx (paired E/E^2 reduction)
    {
        float lg[4], lb[4];
#pragma unroll
        for (int g = 0; g < 4; g++) {
            lg[g] = ln_ig[g * 32 + lane];
            lb[g] = ln_ib[g * 32 + lane];
        }
        for (int rr = 0; rr < 16; rr++) {
            int row = wid * 16 + rr;
            float acg[4];
#pragma unroll
            for (int g = 0; g < 4; g++) acg[g] = GT[row * 132 + g * 32 + lane];
            float s1 = acg[0] + acg[1] + acg[2] + acg[3];
            float s2 = acg[0] * acg[0] + acg[1] * acg[1] + acg[2] * acg[2] +
                       acg[3] * acg[3];
#pragma unroll
            for (int o = 16; o; o >>= 1) {
                s1 += __shfl_xor_sync(0xffffffffu, s1, o);
                s2 += __shfl_xor_sync(0xffffffffu, s2, o);
            }
            float m = s1 * (1.f / 128.f);
            float v = fmaxf(s2 * (1.f / 128.f) - m * m, 0.f);
            float rs = rsqrtf(v + 1e-5f);
#pragma unroll
            for (int g = 0; g < 4; g++)
                g_gx[(size_t)(m0 + row) * 128 + g * 32 + lane] =
                    (acg[g] - m) * rs * lg[g] + lb[g];
        }
    }
}

// ------------------- sequential LN-LSTM (warp/batch, Gram-LN) -------------------
__global__ void k_lstm(const float* __restrict__ whh, const float* __restrict__ ln_hg,
                       const float* __restrict__ ln_hb, const float* __restrict__ ln_cg,
                       const float* __restrict__ ln_cb) {
    __shared__ float wsh[32 * 128];
    __shared__ float gsh[32 * 32];
    __shared__ float rmsh[32];
    int t = threadIdx.x;
    for (int idx = t; idx < 4096; idx += 256) wsh[idx] = whh[idx];
    for (int idx = t; idx < 1024; idx += 256) gsh[idx] = g_gram[idx];
    if (t < 32) rmsh[t] = g_rm[t];
    __syncthreads();
    int lane = t & 31, w = t >> 5;
    int b = blockIdx.x * 8 + w;
    float h = 0.f, c = 0.f;
    float hg[4], hb[4];
#pragma unroll
    for (int g = 0; g < 4; g++) {
        int cc = g * 32 + lane;
        hg[g] = ln_hg[cc];
        hb[g] = ln_hb[cc];
    }
    float cgm = ln_cg[lane], cbm = ln_cb[lane];
    float gxr[4];
#pragma unroll
    for (int g = 0; g < 4; g++) gxr[g] = g_gx[(size_t)b * 128 + g * 32 + lane];
    for (int i = 0; i < SEQN; i++) {
        float gxn[4];
        if (i + 1 < SEQN) {
            size_t rn = (size_t)(i + 1) * BSZ + b;
#pragma unroll
            for (int g = 0; g < 4; g++) gxn[g] = g_gx[rn * 128 + g * 32 + lane];
        }
        float acc[4] = {0.f, 0.f, 0.f, 0.f};
        float accM = 0.f, wv = 0.f;
#pragma unroll
        for (int k = 0; k < 32; k++) {
            float hk = __shfl_sync(0xffffffffu, h, k);
#pragma unroll
            for (int g = 0; g < 4; g++) acc[g] += hk * wsh[k * 128 + g * 32 + lane];
            accM = fmaf(hk, rmsh[k], accM);
            wv = fmaf(hk, gsh[k * 32 + lane], wv);
        }
        float m = accM;
        float q = wredsum(h * wv);
        float v = fmaxf(q * (1.f / 128.f) - m * m, 0.f);
        float rs = rsqrtf(v + 1e-5f);
        float gate[4];
#pragma unroll
        for (int g = 0; g < 4; g++) gate[g] = gxr[g] + (acc[g] - m) * rs * hg[g] + hb[g];
        float ii = siga(gate[0]);
        float ff = siga(gate[1]);
        float gg = tanha(gate[2]);
        float oo = siga(gate[3]);
        float cn = ff * c + ii * gg;
        float s1 = cn, s2 = cn * cn;
#pragma unroll
        for (int o = 16; o; o >>= 1) {
            s1 += __shfl_xor_sync(0xffffffffu, s1, o);
            s2 += __shfl_xor_sync(0xffffffffu, s2, o);
        }
        float mc = s1 * (1.f / 32.f);
        float vc = fmaxf(s2 * (1.f / 32.f) - mc * mc, 0.f);
        c = (cn - mc) * rsqrtf(vc + 1e-5f) * cgm + cbm;
        h = oo * tanha(c);
        g_q[((size_t)i * BSZ + b) * DK + lane] = h;
#pragma unroll
        for (int g = 0; g < 4; g++) gxr[g] = gxn[g];
    }
}

// ------------------- logits + mask (bf16 keys, grid BSZ x 2) --------------------
__global__ void k_logits(const int* __restrict__ en_arr, float* __restrict__ out) {
    __shared__ float Qsh[64 * 32];
    __shared__ float Ksh[256 * 34];
    __shared__ int rsh[256];
    int t = threadIdx.x;
    int b = blockIdx.x;
    int tile = blockIdx.y;
    int en = en_arr[b];
    for (int idx = t; idx < 2048; idx += 256) {
        int s = idx >> 5, k = idx & 31;
        Qsh[idx] = g_q[((size_t)s * BSZ + b) * 32 + k];
    }
    const u64* Q2 = (const u64*)Qsh;
    int n0 = tile * 256;
    const __nv_bfloat162* keyv = (const __nv_bfloat162*)g_key;
    for (int idx = t; idx < 4096; idx += 256) {
        int n = idx >> 4, k2 = idx & 15;
        __nv_bfloat162 kv = keyv[((size_t)b * ENT + n0 + n) * 16 + k2];
        float2 f = __bfloat1622float2(kv);
        Ksh[n * 34 + k2 * 2] = f.x;
        Ksh[n * 34 + k2 * 2 + 1] = f.y;
    }
    rsh[t] = g_removed[(size_t)b * ENP1 + n0 + t];
    __syncthreads();
    u64 kreg[16];
#pragma unroll
    for (int kp = 0; kp < 16; kp++) {
        float2 kk = *(const float2*)&Ksh[t * 34 + kp * 2];
        asm("mov.b64 %0,{%1,%2};" : "=l"(kreg[kp]) : "f"(kk.x), "f"(kk.y));
    }
    int rstep = rsh[t];
    int n = n0 + t;
    for (int s = 0; s < SEQN; s++) {
        u64 a0 = 0ull, a1 = 0ull;
#pragma unroll
        for (int kp = 0; kp < 16; kp += 2) {
            fma2(a0, kreg[kp], Q2[s * 16 + kp]);
            fma2(a1, kreg[kp + 1], Q2[s * 16 + kp + 1]);
        }
        float2 f0 = up2(a0), f1 = up2(a1);
        float dot = (f0.x + f0.y) + (f1.x + f1.y);
        bool keep = (n < en) ? (rstep > s) : ((n == en) ? (s >= 1 && rstep > s) : false);
        out[((size_t)b * SEQN + s) * ENP1 + n] = keep ? dot : -1e9f;
    }
    if (tile == 1 && t < SEQN) out[((size_t)b * SEQN + t) * ENP1 + 512] = -1e9f;
}

// ------------------------------- launch ----------------------------------------
extern "C" void kernel_launch(void* const* d_in, const int* in_sizes, int n_in,
                              void* d_out, int out_size) {
    const float* ent = (const float*)d_in[0];
    const float* ar = (const float*)d_in[1];
    const int* entity_num = (const int*)d_in[2];
    const int* sel = (const int*)d_in[3];
    const int* selnum = (const int*)d_in[4];
    const float* key_w = (const float*)d_in[5];
    const float* key_b = (const float*)d_in[6];
    const float* q1w = (const float*)d_in[7];
    const float* q1b = (const float*)d_in[8];
    const float* q2w = (const float*)d_in[9];
    const float* q2b = (const float*)d_in[10];
    const float* e1w = (const float*)d_in[11];
    const float* e1b = (const float*)d_in[12];
    const float* e2w = (const float*)d_in[13];
    const float* e2b = (const float*)d_in[14];
    const float* endv = (const float*)d_in[15];
    const float* wih = (const float*)d_in[16];
    const float* whh = (const float*)d_in[17];
    const float* ln_ig = (const float*)d_in[18];
    const float* ln_ib = (const float*)d_in[19];
    const float* ln_hg = (const float*)d_in[20];
    const float* ln_hb = (const float*)d_in[21];
    const float* ln_cg = (const float*)d_in[22];
    const float* ln_cb = (const float*)d_in[23];
    float* out = (float*)d_out;

    void *pKey, *pBase, *pBasec, *pW2, *pC2;
    cudaGetSymbolAddress(&pKey, g_key);
    cudaGetSymbolAddress(&pBase, g_base);
    cudaGetSymbolAddress(&pBasec, g_basec);
    cudaGetSymbolAddress(&pW2, g_W2);
    cudaGetSymbolAddress(&pC2, g_c2);

    static cudaStream_t sB = 0, sC = 0, sD = 0;
    static cudaEvent_t eFork = 0, eB = 0, eW2 = 0, eKey = 0, eGr = 0;
    if (!sB) {
        int lo, hi;
        cudaDeviceGetStreamPriorityRange(&lo, &hi);
        cudaStreamCreateWithFlags(&sB, cudaStreamNonBlocking);
        cudaStreamCreateWithFlags(&sC, cudaStreamNonBlocking);
        cudaStreamCreateWithPriority(&sD, cudaStreamNonBlocking, lo);
        cudaEventCreateWithFlags(&eFork, cudaEventDisableTiming);
        cudaEventCreateWithFlags(&eB, cudaEventDisableTiming);
        cudaEventCreateWithFlags(&eW2, cudaEventDisableTiming);
        cudaEventCreateWithFlags(&eKey, cudaEventDisableTiming);
        cudaEventCreateWithFlags(&eGr, cudaEventDisableTiming);
        cudaFuncSetAttribute(k_fused, cudaFuncAttributeMaxDynamicSharedMemorySize,
                             SMF_FLOATS * 4);
    }

    cudaEventRecord(eFork, 0);
    cudaStreamWaitEvent(sB, eFork, 0);
    cudaStreamWaitEvent(sC, eFork, 0);
    cudaStreamWaitEvent(sD, eFork, 0);

    k_selkey<<<BSZ, 256>>>(ent, key_w, key_b, sel, entity_num, selnum);
    k_c2<<<8, 256, 0, sB>>>(e2b, q1w);
    k_mma<32, 7><<<dim3(BSZ / 64, DF / 32), 256, 0, sB>>>(
        ar, q1w, q1b, (float*)pBase, DIN, DF, (const float*)pC2, nullptr, (float*)pBasec);
    cudaEventRecord(eB, sB);
    k_cvt<<<80, 256, 0, sC>>>(e1w, q2w, wih);
    k_mma<32, 6><<<dim3(DF / 64, DF / 32), 256, 0, sC>>>(
        e2w, q1w, nullptr, (float*)pW2, DIN, DF, nullptr, nullptr, nullptr);
    cudaEventRecord(eW2, sC);

    cudaStreamWaitEvent(0, eB, 0);
    cudaStreamWaitEvent(0, eW2, 0);
    k_fused<<<SEQN * BSZ / 128, 256, SMF_FLOATS * 4>>>(e1b, q2b, ln_ig, ln_ib);

    k_gram<<<1, 256, 0, sC>>>(whh);
    cudaEventRecord(eGr, sC);
    k_mma<32, 2><<<dim3(BSZ * ENT / 64, 1), 256, 0, sD>>>(
        ent, key_w, key_b, (float*)pKey, DF, DK, endv, entity_num, nullptr);
    cudaEventRecord(eKey, sD);

    cudaStreamWaitEvent(0, eGr, 0);
    k_lstm<<<BSZ / 8, 256>>>(whh, ln_hg, ln_hb, ln_cg, ln_cb);
    cudaStreamWaitEvent(0, eKey, 0);
    k_logits<<<dim3(BSZ, 2), 256>>>(entity_num, out);
    (void)in_sizes;
    (void)n_in;
    (void)out_size;
}

// round 16
// speedup vs baseline: 1.9455x; 1.0564x over previous
#include <cuda_runtime.h>
#include <cuda_bf16.h>
#include <math.h>
#include <stdint.h>

#define BSZ 512
#define ENT 512
#define SEQN 64
#define DK 32
#define DF 256
#define DIN 1024
#define NGATE 128
#define ENP1 513

typedef unsigned long long u64;

// ----------------------------- static scratch --------------------------------
__device__ __nv_bfloat16 g_key[(size_t)BSZ * ENT * DK];   // keys in bf16
__device__ int   g_removed[(size_t)BSZ * ENP1];
__device__ float g_selemb[(size_t)SEQN * BSZ * DK];
__device__ float g_base[(size_t)BSZ * DF];
__device__ float g_basec[(size_t)BSZ * DF];   // base + c2
__device__ uint32_t g_W2b[128 * 256];         // W2 bf16, k-pair packed words
__device__ float g_c2[DF];
__device__ uint32_t g_e1t[16 * 256];          // e1w bf16 packed [k/2][n]
__device__ uint32_t g_q2t[128 * 32];          // q2w bf16 packed
__device__ uint32_t g_wiht[16 * 128];         // wih bf16 packed
__device__ float g_gram[32 * 32];             // whh @ whh^T
__device__ float g_rm[32];                    // row-mean of whh (/128 folded)
__device__ float g_gx[(size_t)SEQN * BSZ * NGATE];
__device__ float g_q[(size_t)SEQN * BSZ * DK];

// ----------------------------- helpers ---------------------------------------
__device__ __forceinline__ float wredsum(float v) {
#pragma unroll
    for (int o = 16; o; o >>= 1) v += __shfl_xor_sync(0xffffffffu, v, o);
    return v;
}
__device__ __forceinline__ void fma2(u64& d, u64 a, u64 b) {
    asm("fma.rn.f32x2 %0,%1,%2,%0;" : "+l"(d) : "l"(a), "l"(b));
}
__device__ __forceinline__ float2 up2(u64 v) {
    float2 f;
    asm("mov.b64 {%0,%1},%2;" : "=f"(f.x), "=f"(f.y) : "l"(v));
    return f;
}
__device__ __forceinline__ uint32_t f2tf(float f) {
    uint32_t r;
    asm("cvt.rna.tf32.f32 %0, %1;" : "=r"(r) : "f"(f));
    return r;
}
__device__ __forceinline__ uint32_t pkbf(float a, float b) {
    __nv_bfloat162 v = __floats2bfloat162_rn(a, b);
    return *(uint32_t*)&v;
}
__device__ __forceinline__ float tanha(float x) {
    float y;
    asm("tanh.approx.f32 %0, %1;" : "=f"(y) : "f"(x));
    return y;
}
__device__ __forceinline__ float siga(float x) {
    return 0.5f * tanha(0.5f * x) + 0.5f;
}
__device__ __forceinline__ void mma_tf32(float* c, uint32_t a0, uint32_t a1, uint32_t a2,
                                         uint32_t a3, uint32_t b0, uint32_t b1) {
    asm volatile(
        "mma.sync.aligned.m16n8k8.row.col.f32.tf32.tf32.f32 "
        "{%0,%1,%2,%3},{%4,%5,%6,%7},{%8,%9},{%0,%1,%2,%3};"
        : "+f"(c[0]), "+f"(c[1]), "+f"(c[2]), "+f"(c[3])
        : "r"(a0), "r"(a1), "r"(a2), "r"(a3), "r"(b0), "r"(b1));
}
__device__ __forceinline__ void mma_bf16(float* c, uint32_t a0, uint32_t a1, uint32_t a2,
                                         uint32_t a3, uint32_t b0, uint32_t b1) {
    asm volatile(
        "mma.sync.aligned.m16n8k16.row.col.f32.bf16.bf16.f32 "
        "{%0,%1,%2,%3},{%4,%5,%6,%7},{%8,%9},{%0,%1,%2,%3};"
        : "+f"(c[0]), "+f"(c[1]), "+f"(c[2]), "+f"(c[3])
        : "r"(a0), "r"(a1), "r"(a2), "r"(a3), "r"(b0), "r"(b1));
}

// --------------- tf32 tensor-core GEMM (standalone) ---------------------------
// EPI: 2 +bias & end-scatter -> bf16 C (key) | 6 -> bf16 k-pair packed (W2)
//      7 +bias -> C, +xb -> C2
template <int BN, int EPI>
__global__ void k_mma(const float* __restrict__ A, const float* __restrict__ B,
                      const float* __restrict__ bias, float* __restrict__ C,
                      int K, int N, const float* __restrict__ xb,
                      const int* __restrict__ xi, float* __restrict__ C2) {
    constexpr int BM = 64, KC = 32;
    constexpr int NBLD = (KC * BN) / 1024;
    constexpr int NT = BN / 16;
    __shared__ uint32_t As[BM][KC + 4];
    __shared__ uint32_t Bs[KC][BN + 4];
    const int t = threadIdx.x;
    const int wid = t >> 5, lane = t & 31;
    const int gid = lane >> 2, tig = lane & 3;
    const int warpM = wid & 3, warpN = wid >> 2;
    const int m0 = blockIdx.x * BM;
    const int n0 = blockIdx.y * BN;

    float cr[NT][4];
#pragma unroll
    for (int j = 0; j < NT; j++) {
        cr[j][0] = 0.f; cr[j][1] = 0.f; cr[j][2] = 0.f; cr[j][3] = 0.f;
    }

    const int ar0 = t >> 3;
    const int ak = (t & 7) * 4;
    constexpr int BQ = BN / 4;
    const int br0 = t / BQ;
    const int bn = (t % BQ) * 4;

    float4 pa0, pa1, pb[NBLD];
    pa0 = *(const float4*)&A[(size_t)(m0 + ar0) * K + ak];
    pa1 = *(const float4*)&A[(size_t)(m0 + ar0 + 32) * K + ak];
#pragma unroll
    for (int i = 0; i < NBLD; i++) {
        int kr = br0 + i * (256 / BQ);
        pb[i] = *(const float4*)&B[(size_t)kr * N + n0 + bn];
    }

    const int nch = K / KC;
    for (int ch = 0; ch < nch; ch++) {
        __syncthreads();
        {
            uint4 q;
            q.x = f2tf(pa0.x); q.y = f2tf(pa0.y); q.z = f2tf(pa0.z); q.w = f2tf(pa0.w);
            *(uint4*)&As[ar0][ak] = q;
            q.x = f2tf(pa1.x); q.y = f2tf(pa1.y); q.z = f2tf(pa1.z); q.w = f2tf(pa1.w);
            *(uint4*)&As[ar0 + 32][ak] = q;
#pragma unroll
            for (int i = 0; i < NBLD; i++) {
                int kr = br0 + i * (256 / BQ);
                q.x = f2tf(pb[i].x); q.y = f2tf(pb[i].y);
                q.z = f2tf(pb[i].z); q.w = f2tf(pb[i].w);
                *(uint4*)&Bs[kr][bn] = q;
            }
        }
        if (ch + 1 < nch) {
            int k0 = (ch + 1) * KC;
            pa0 = *(const float4*)&A[(size_t)(m0 + ar0) * K + k0 + ak];
            pa1 = *(const float4*)&A[(size_t)(m0 + ar0 + 32) * K + k0 + ak];
#pragma unroll
            for (int i = 0; i < NBLD; i++) {
                int kr = k0 + br0 + i * (256 / BQ);
                pb[i] = *(const float4*)&B[(size_t)kr * N + n0 + bn];
            }
        }
        __syncthreads();
#pragma unroll
        for (int kk = 0; kk < KC; kk += 8) {
            uint32_t a0 = As[warpM * 16 + gid][kk + tig];
            uint32_t a1 = As[warpM * 16 + gid + 8][kk + tig];
            uint32_t a2 = As[warpM * 16 + gid][kk + tig + 4];
            uint32_t a3 = As[warpM * 16 + gid + 8][kk + tig + 4];
#pragma unroll
            for (int j = 0; j < NT; j++) {
                int nb = warpN * (BN / 2) + j * 8;
                uint32_t b0 = Bs[kk + tig][nb + gid];
                uint32_t b1 = Bs[kk + tig + 4][nb + gid];
                mma_tf32(cr[j], a0, a1, a2, a3, b0, b1);
            }
        }
    }

    const int rb = m0 + warpM * 16 + gid;
#pragma unroll
    for (int j = 0; j < NT; j++) {
        int cb = n0 + warpN * (BN / 2) + j * 8 + tig * 2;
#pragma unroll
        for (int h = 0; h < 2; h++) {
            int m = rb + h * 8;
            float v0 = cr[j][h * 2 + 0];
            float v1 = cr[j][h * 2 + 1];
            if (EPI == 2) {
                int en = xi[m0 >> 9];
                float o0, o1;
                if ((m & 511) == en) {
                    o0 = xb[cb];
                    o1 = xb[cb + 1];
                } else {
                    o0 = v0 + bias[cb];
                    o1 = v1 + bias[cb + 1];
                }
                __nv_bfloat16* kp = (__nv_bfloat16*)C;
                *(__nv_bfloat162*)&kp[(size_t)m * N + cb] =
                    __floats2bfloat162_rn(o0, o1);
            } else if (EPI == 6) {
                // W2 bf16 k-pair packed: element ((m>>1)*256 + n)*2 + (m&1)
                __nv_bfloat16* W = (__nv_bfloat16*)C;
                W[((size_t)(m >> 1) * 256 + cb) * 2 + (m & 1)] = __float2bfloat16(v0);
                W[((size_t)(m >> 1) * 256 + cb + 1) * 2 + (m & 1)] = __float2bfloat16(v1);
            } else if (EPI == 7) {
                float o0 = v0 + bias[cb], o1 = v1 + bias[cb + 1];
                C[(size_t)m * N + cb] = o0;
                C[(size_t)m * N + cb + 1] = o1;
                C2[(size_t)m * N + cb] = o0 + xb[cb];
                C2[(size_t)m * N + cb + 1] = o1 + xb[cb + 1];
            }
        }
    }
}

// --------------- selkey gathered GEMM + removed scatter + pooled-emb scan ------
__global__ void __launch_bounds__(256) k_selkey(const float* __restrict__ ent,
                                                const float* __restrict__ kw,
                                                const float* __restrict__ kb,
                                                const int* __restrict__ sel,
                                                const int* __restrict__ en_arr,
                                                const int* __restrict__ selnum) {
    __shared__ uint32_t AS[64 * 68];
    __shared__ uint32_t BS[64 * 36];
    __shared__ int ssh[64];
    __shared__ int inc[64];
    const int t = threadIdx.x;
    const int b = blockIdx.x;
    const int wid = t >> 5, lane = t & 31;
    const int gid = lane >> 2, tig = lane & 3;
    const int warpM = wid & 3, warpN = wid >> 2;
    const int en = en_arr[b];

    if (t < 64) ssh[t] = sel[b * SEQN + t];
    for (int n = t; n < ENP1; n += 256) g_removed[(size_t)b * ENP1 + n] = 65;
    __syncthreads();
    if (t < 64) atomicMin(&g_removed[(size_t)b * ENP1 + ssh[t]], t + 1);
    if (t < 64) {
        int sj = ssh[t];
        bool first = true, endf = (sj == en);
        for (int k = 0; k < t; k++) {
            int sk = ssh[k];
            if (sk == sj) first = false;
            if (sk == en) endf = true;
        }
        inc[t] = (first && !endf) ? 1 : 0;
    }

    float4 pa[4], pb[2];
#pragma unroll
    for (int p = 0; p < 4; p++) {
        int idx = t + p * 256;
        int r = idx >> 4, c4 = (idx & 15) * 4;
        pa[p] = *(const float4*)&ent[((size_t)b * ENT + ssh[r]) * 256 + c4];
    }
#pragma unroll
    for (int p = 0; p < 2; p++) {
        int idx = t + p * 256;
        int r = idx >> 3, c4 = (idx & 7) * 4;
        pb[p] = *(const float4*)&kw[(size_t)r * 32 + c4];
    }

    float acc[2][4];
    acc[0][0] = acc[0][1] = acc[0][2] = acc[0][3] = 0.f;
    acc[1][0] = acc[1][1] = acc[1][2] = acc[1][3] = 0.f;

    for (int ch = 0; ch < 4; ch++) {
        __syncthreads();
#pragma unroll
        for (int p = 0; p < 4; p++) {
            int idx = t + p * 256;
            int r = idx >> 4, c4 = (idx & 15) * 4;
            AS[r * 68 + c4 + 0] = f2tf(pa[p].x);
            AS[r * 68 + c4 + 1] = f2tf(pa[p].y);
            AS[r * 68 + c4 + 2] = f2tf(pa[p].z);
            AS[r * 68 + c4 + 3] = f2tf(pa[p].w);
        }
#pragma unroll
        for (int p = 0; p < 2; p++) {
            int idx = t + p * 256;
            int r = idx >> 3, c4 = (idx & 7) * 4;
            BS[r * 36 + c4 + 0] = f2tf(pb[p].x);
            BS[r * 36 + c4 + 1] = f2tf(pb[p].y);
            BS[r * 36 + c4 + 2] = f2tf(pb[p].z);
            BS[r * 36 + c4 + 3] = f2tf(pb[p].w);
        }
        if (ch + 1 < 4) {
            int k0 = (ch + 1) * 64;
#pragma unroll
            for (int p = 0; p < 4; p++) {
                int idx = t + p * 256;
                int r = idx >> 4, c4 = (idx & 15) * 4;
                pa[p] = *(const float4*)&ent[((size_t)b * ENT + ssh[r]) * 256 + k0 + c4];
            }
#pragma unroll
            for (int p = 0; p < 2; p++) {
                int idx = t + p * 256;
                int r = idx >> 3, c4 = (idx & 7) * 4;
                pb[p] = *(const float4*)&kw[(size_t)(k0 + r) * 32 + c4];
            }
        }
        __syncthreads();
#pragma unroll
        for (int kk = 0; kk < 64; kk += 8) {
            uint32_t a0 = AS[(warpM * 16 + gid) * 68 + kk + tig];
            uint32_t a1 = AS[(warpM * 16 + gid + 8) * 68 + kk + tig];
            uint32_t a2 = AS[(warpM * 16 + gid) * 68 + kk + tig + 4];
            uint32_t a3 = AS[(warpM * 16 + gid + 8) * 68 + kk + tig + 4];
#pragma unroll
            for (int j = 0; j < 2; j++) {
                int nb = warpN * 16 + j * 8;
                uint32_t b0 = BS[(kk + tig) * 36 + nb + gid];
                uint32_t b1 = BS[(kk + tig + 4) * 36 + nb + gid];
                mma_tf32(acc[j], a0, a1, a2, a3, b0, b1);
            }
        }
    }
    __syncthreads();
    float* SK = (float*)BS;
#pragma unroll
    for (int j = 0; j < 2; j++) {
        int cb = warpN * 16 + j * 8 + tig * 2;
        float b0 = kb[cb], b1 = kb[cb + 1];
#pragma unroll
        for (int h = 0; h < 2; h++) {
            int r = warpM * 16 + gid + h * 8;
            SK[r * 33 + cb] = acc[j][h * 2] + b0;
            SK[r * 33 + cb + 1] = acc[j][h * 2 + 1] + b1;
        }
    }
    __syncthreads();
    if (t < 32) {
        int sn = selnum[b];
        float sum = 0.f;
        int cnt = 0;
        for (int j = 0; j < SEQN; j++) {
            if (inc[j]) {
                sum += SK[j * 33 + t];
                cnt++;
            }
            float denom = (sn != 0 && cnt > 0) ? (float)cnt : 1.f;
            g_selemb[((size_t)j * BSZ + b) * DK + t] = sum / denom;
        }
    }
}

// --------------- bf16 pack converters / gram ------------------------------------
__global__ void k_cvt(const float* __restrict__ e1w, const float* __restrict__ q2w,
                      const float* __restrict__ wih) {
    int i = blockIdx.x * 256 + threadIdx.x;
    if (i < 4096) {
        int kp = i >> 8, n = i & 255;
        g_e1t[i] = pkbf(e1w[(size_t)(2 * kp) * 256 + n], e1w[(size_t)(2 * kp + 1) * 256 + n]);
    } else if (i < 8192) {
        int j = i - 4096;
        int kp = j >> 5, n = j & 31;
        g_q2t[j] = pkbf(q2w[(size_t)(2 * kp) * 32 + n], q2w[(size_t)(2 * kp + 1) * 32 + n]);
    } else if (i < 10240) {
        int j = i - 8192;
        int kp = j >> 7, n = j & 127;
        g_wiht[j] = pkbf(wih[(size_t)(2 * kp) * 128 + n], wih[(size_t)(2 * kp + 1) * 128 + n]);
    }
}

// Gram = whh @ whh^T (32x32) and rowmean/128 (32) of whh [32,128]
__global__ void k_gram(const float* __restrict__ whh) {
    __shared__ float wsh[4096];
    int t = threadIdx.x;
    for (int i = t; i < 4096; i += 256) wsh[i] = whh[i];
    __syncthreads();
    for (int e = t; e < 1024; e += 256) {
        int k = e >> 5, l = e & 31;
        float s = 0.f;
#pragma unroll 8
        for (int g = 0; g < 128; g++) s += wsh[k * 128 + g] * wsh[l * 128 + g];
        g_gram[e] = s;
    }
    if (t < 32) {
        float s = 0.f;
#pragma unroll 8
        for (int g = 0; g < 128; g++) s += wsh[t * 128 + g];
        g_rm[t] = s * (1.f / 128.f);
    }
}

// c2 = e2_b @ q1_w (8 blocks x 8 k-slices)
__global__ void k_c2(const float* __restrict__ e2b, const float* __restrict__ q1w) {
    __shared__ float part[8][32];
    int t = threadIdx.x;
    int col = blockIdx.x * 32 + (t & 31);
    int ks = t >> 5;
    float acc = 0.f;
    for (int k = ks * 128; k < ks * 128 + 128; k++) acc += e2b[k] * q1w[(size_t)k * DF + col];
    part[ks][t & 31] = acc;
    __syncthreads();
    if (t < 32) {
        float s = 0.f;
#pragma unroll
        for (int p = 0; p < 8; p++) s += part[p][t];
        g_c2[blockIdx.x * 32 + t] = s;
    }
}

// --------------- mega-fused bf16 (BM=128): u -> P -> relu -> x -> gates -> LN --
// smem words: U2 [128][132] @0 (16896) | BS @16896 (4640) | SEL2/XT [128][20] @21536
//             WH [16][132] @24096 ; GT fp32 aliases U2.   total 26208 w = 104832 B
#define SMF_BYTES 104832
__global__ void __launch_bounds__(256, 1)
k_fused(const float* __restrict__ e1b, const float* __restrict__ q2b,
        const float* __restrict__ ln_ig, const float* __restrict__ ln_ib) {
    extern __shared__ float sm[];
    uint32_t* U2 = (uint32_t*)sm;              // [128][132] bf16-pair words
    float* GT = sm;                            // [128][132] fp32 gates (alias)
    uint32_t* BS = (uint32_t*)sm + 16896;      // staging (e1/W2: [16][264]; q2: [128][36])
    uint32_t* SEL2 = (uint32_t*)sm + 21536;    // [128][20]
    uint32_t* XT = SEL2;                       // alias
    uint32_t* WH = (uint32_t*)sm + 24096;      // [16][132]

    const int t = threadIdx.x;
    const int wid = t >> 5, lane = t & 31;
    const int gid = lane >> 2, tig = lane & 3;
    const int warpM = wid & 3, warpN = wid >> 2;
    const int m0 = blockIdx.x * 128;
    const int step = m0 >> 9;
    const int b0 = m0 & 511;

    if (step == 0) {
        // U2 = bf16(relu(base))
#pragma unroll 4
        for (int p = 0; p < 32; p++) {
            int idx = t + p * 256;
            int r = idx >> 6, c4 = (idx & 63) * 4;
            float4 v = *(const float4*)&g_base[(size_t)(b0 + r) * 256 + c4];
            U2[r * 132 + (c4 >> 1)] = pkbf(fmaxf(v.x, 0.f), fmaxf(v.y, 0.f));
            U2[r * 132 + (c4 >> 1) + 1] = pkbf(fmaxf(v.z, 0.f), fmaxf(v.w, 0.f));
        }
    } else {
        // stage SEL (bf16 pack) + e1 (copy)
#pragma unroll
        for (int p = 0; p < 4; p++) {
            int idx = t + p * 256;
            int r = idx >> 3, c4 = (idx & 7) * 4;
            float4 v = *(const float4*)&g_selemb[(size_t)(m0 - 512 + r) * 32 + c4];
            SEL2[r * 20 + (c4 >> 1)] = pkbf(v.x, v.y);
            SEL2[r * 20 + (c4 >> 1) + 1] = pkbf(v.z, v.w);
        }
#pragma unroll
        for (int p = 0; p < 4; p++) {
            int idx4 = t + p * 256;
            int r = idx4 >> 6, c4 = (idx4 & 63) * 4;
            *(uint4*)&BS[r * 264 + c4] = ((const uint4*)g_e1t)[idx4];
        }
        __syncthreads();

        float acc[2][16][4];
#pragma unroll
        for (int mt = 0; mt < 2; mt++)
#pragma unroll
            for (int j = 0; j < 16; j++) {
                acc[mt][j][0] = 0.f; acc[mt][j][1] = 0.f;
                acc[mt][j][2] = 0.f; acc[mt][j][3] = 0.f;
            }
        // u = selemb @ e1  (K=32 -> 2 k16 steps)
#pragma unroll
        for (int kk2 = 0; kk2 < 16; kk2 += 8) {
#pragma unroll
            for (int mt = 0; mt < 2; mt++) {
                int rbase = warpM * 32 + mt * 16 + gid;
                uint32_t a0 = SEL2[rbase * 20 + kk2 + tig];
                uint32_t a1 = SEL2[(rbase + 8) * 20 + kk2 + tig];
                uint32_t a2 = SEL2[rbase * 20 + kk2 + tig + 4];
                uint32_t a3 = SEL2[(rbase + 8) * 20 + kk2 + tig + 4];
#pragma unroll
                for (int j = 0; j < 16; j++) {
                    int nb = warpN * 128 + j * 8;
                    uint32_t b0 = BS[(kk2 + tig) * 264 + nb + gid];
                    uint32_t b1 = BS[(kk2 + tig + 4) * 264 + nb + gid];
                    mma_bf16(acc[mt][j], a0, a1, a2, a3, b0, b1);
                }
            }
        }
        // U2 = bf16(relu(u + e1b))
#pragma unroll
        for (int mt = 0; mt < 2; mt++)
#pragma unroll
            for (int j = 0; j < 16; j++) {
                int cb = warpN * 128 + j * 8 + tig * 2;
                float bb0 = e1b[cb], bb1 = e1b[cb + 1];
#pragma unroll
                for (int h = 0; h < 2; h++) {
                    int r = warpM * 32 + mt * 16 + gid + h * 8;
                    U2[r * 132 + (cb >> 1)] = pkbf(fmaxf(acc[mt][j][h * 2] + bb0, 0.f),
                                                   fmaxf(acc[mt][j][h * 2 + 1] + bb1, 0.f));
                }
            }
#pragma unroll
        for (int mt = 0; mt < 2; mt++)
#pragma unroll
            for (int j = 0; j < 16; j++) {
                acc[mt][j][0] = 0.f; acc[mt][j][1] = 0.f;
                acc[mt][j][2] = 0.f; acc[mt][j][3] = 0.f;
            }
        // P = U @ W2 (K=256, 8 chunks of k32, reg-prefetched bf16)
        uint4 pw[4];
#pragma unroll
        for (int p = 0; p < 4; p++) pw[p] = ((const uint4*)g_W2b)[t + p * 256];
        for (int ch = 0; ch < 8; ch++) {
            __syncthreads();
#pragma unroll
            for (int p = 0; p < 4; p++) {
                int idx4 = t + p * 256;
                int r = idx4 >> 6, c4 = (idx4 & 63) * 4;
                *(uint4*)&BS[r * 264 + c4] = pw[p];
            }
            if (ch + 1 < 8) {
#pragma unroll
                for (int p = 0; p < 4; p++)
                    pw[p] = ((const uint4*)g_W2b)[(ch + 1) * 1024 + t + p * 256];
            }
            __syncthreads();
#pragma unroll
            for (int kk2 = 0; kk2 < 16; kk2 += 8) {
                int kg = ch * 16 + kk2;
#pragma unroll
                for (int mt = 0; mt < 2; mt++) {
                    int rbase = warpM * 32 + mt * 16 + gid;
                    uint32_t a0 = U2[rbase * 132 + kg + tig];
                    uint32_t a1 = U2[(rbase + 8) * 132 + kg + tig];
                    uint32_t a2 = U2[rbase * 132 + kg + tig + 4];
                    uint32_t a3 = U2[(rbase + 8) * 132 + kg + tig + 4];
#pragma unroll
                    for (int j = 0; j < 16; j++) {
                        int nb = warpN * 128 + j * 8;
                        uint32_t b0 = BS[(kk2 + tig) * 264 + nb + gid];
                        uint32_t b1 = BS[(kk2 + tig + 4) * 264 + nb + gid];
                        mma_bf16(acc[mt][j], a0, a1, a2, a3, b0, b1);
                    }
                }
            }
        }
        __syncthreads();
        // U2 = bf16(relu(P + basec))
#pragma unroll
        for (int mt = 0; mt < 2; mt++)
#pragma unroll
            for (int j = 0; j < 16; j++) {
                int cb = warpN * 128 + j * 8 + tig * 2;
#pragma unroll
                for (int h = 0; h < 2; h++) {
                    int r = warpM * 32 + mt * 16 + gid + h * 8;
                    float2 bc = *(const float2*)&g_basec[(size_t)(b0 + r) * 256 + cb];
                    U2[r * 132 + (cb >> 1)] =
                        pkbf(fmaxf(acc[mt][j][h * 2] + bc.x, 0.f),
                             fmaxf(acc[mt][j][h * 2 + 1] + bc.y, 0.f));
                }
            }
    }
    __syncthreads();

    // stage q2 (copy packed bf16) into BS [128][36]
#pragma unroll
    for (int p = 0; p < 4; p++) {
        int idx4 = t + p * 256;
        int r = idx4 >> 3, c4 = (idx4 & 7) * 4;
        *(uint4*)&BS[r * 36 + c4] = ((const uint4*)g_q2t)[idx4];
    }
    __syncthreads();

    // x = U @ q2 (K=256 -> 16 k16 steps) -> registers
    float ax[2][2][4];
#pragma unroll
    for (int mt = 0; mt < 2; mt++)
#pragma unroll
        for (int j = 0; j < 2; j++) {
            ax[mt][j][0] = 0.f; ax[mt][j][1] = 0.f;
            ax[mt][j][2] = 0.f; ax[mt][j][3] = 0.f;
        }
#pragma unroll 4
    for (int kk2 = 0; kk2 < 128; kk2 += 8) {
#pragma unroll
        for (int mt = 0; mt < 2; mt++) {
            int rbase = warpM * 32 + mt * 16 + gid;
            uint32_t a0 = U2[rbase * 132 + kk2 + tig];
            uint32_t a1 = U2[(rbase + 8) * 132 + kk2 + tig];
            uint32_t a2 = U2[rbase * 132 + kk2 + tig + 4];
            uint32_t a3 = U2[(rbase + 8) * 132 + kk2 + tig + 4];
#pragma unroll
            for (int j = 0; j < 2; j++) {
                int nb = warpN * 16 + j * 8;
                uint32_t b0 = BS[(kk2 + tig) * 36 + nb + gid];
                uint32_t b1 = BS[(kk2 + tig + 4) * 36 + nb + gid];
                mma_bf16(ax[mt][j], a0, a1, a2, a3, b0, b1);
            }
        }
    }
    __syncthreads();   // all U2 reads done (XT aliases SEL2, GT aliases U2)

    // XT = bf16(x + q2b); stage wih packed into WH [16][132]
#pragma unroll
    for (int mt = 0; mt < 2; mt++)
#pragma unroll
        for (int j = 0; j < 2; j++) {
            int cb = warpN * 16 + j * 8 + tig * 2;
            float qb0 = q2b[cb], qb1 = q2b[cb + 1];
#pragma unroll
            for (int h = 0; h < 2; h++) {
                int r = warpM * 32 + mt * 16 + gid + h * 8;
                XT[r * 20 + (cb >> 1)] =
                    pkbf(ax[mt][j][h * 2] + qb0, ax[mt][j][h * 2 + 1] + qb1);
            }
        }
#pragma unroll
    for (int p = 0; p < 2; p++) {
        int idx4 = t + p * 256;
        int r = idx4 >> 5, c4 = (idx4 & 31) * 4;
        *(uint4*)&WH[r * 132 + c4] = ((const uint4*)g_wiht)[idx4];
    }
    __syncthreads();

    // gates = XT @ wih (M=128,N=128,K=32 -> 2 k16 steps) -> GT fp32
    {
        float ag[2][8][4];
#pragma unroll
        for (int mt = 0; mt < 2; mt++)
#pragma unroll
            for (int j = 0; j < 8; j++) {
                ag[mt][j][0] = 0.f; ag[mt][j][1] = 0.f;
                ag[mt][j][2] = 0.f; ag[mt][j][3] = 0.f;
            }
#pragma unroll
        for (int kk2 = 0; kk2 < 16; kk2 += 8) {
#pragma unroll
            for (int mt = 0; mt < 2; mt++) {
                int rbase = warpM * 32 + mt * 16 + gid;
                uint32_t a0 = XT[rbase * 20 + kk2 + tig];
                uint32_t a1 = XT[(rbase + 8) * 20 + kk2 + tig];
                uint32_t a2 = XT[rbase * 20 + kk2 + tig + 4];
                uint32_t a3 = XT[(rbase + 8) * 20 + kk2 + tig + 4];
#pragma unroll
                for (int j = 0; j < 8; j++) {
                    int nb = warpN * 64 + j * 8;
                    uint32_t b0 = WH[(kk2 + tig) * 132 + nb + gid];
                    uint32_t b1 = WH[(kk2 + tig + 4) * 132 + nb + gid];
                    mma_bf16(ag[mt][j], a0, a1, a2, a3, b0, b1);
                }
            }
        }
#pragma unroll
        for (int mt = 0; mt < 2; mt++)
#pragma unroll
            for (int j = 0; j < 8; j++) {
                int cb = warpN * 64 + j * 8 + tig * 2;
#pragma unroll
                for (int h = 0; h < 2; h++) {
                    int r = warpM * 32 + mt * 16 + gid + h * 8;
                    GT[r * 132 + cb] = ag[mt][j][h * 2];
                    GT[r * 132 + cb + 1] = ag[mt][j][h * 2 + 1];
                }
            }
    }
    __syncthreads();

    // LN over GT rows -> g_gx (paired E/E^2 reduction)
    {
        float lg[4], lb[4];
#pragma unroll
        for (int g = 0; g < 4; g++) {
            lg[g] = ln_ig[g * 32 + lane];
            lb[g] = ln_ib[g * 32 + lane];
        }
        for (int rr = 0; rr < 16; rr++) {
            int row = wid * 16 + rr;
            float acg[4];
#pragma unroll
            for (int g = 0; g < 4; g++) acg[g] = GT[row * 132 + g * 32 + lane];
            float s1 = acg[0] + acg[1] + acg[2] + acg[3];
            float s2 = acg[0] * acg[0] + acg[1] * acg[1] + acg[2] * acg[2] +
                       acg[3] * acg[3];
#pragma unroll
            for (int o = 16; o; o >>= 1) {
                s1 += __shfl_xor_sync(0xffffffffu, s1, o);
                s2 += __shfl_xor_sync(0xffffffffu, s2, o);
            }
            float m = s1 * (1.f / 128.f);
            float v = fmaxf(s2 * (1.f / 128.f) - m * m, 0.f);
            float rs = rsqrtf(v + 1e-5f);
#pragma unroll
            for (int g = 0; g < 4; g++)
                g_gx[(size_t)(m0 + row) * 128 + g * 32 + lane] =
                    (acg[g] - m) * rs * lg[g] + lb[g];
        }
    }
}

// ------------------- sequential LN-LSTM (warp/batch, Gram-LN) -------------------
__global__ void k_lstm(const float* __restrict__ whh, const float* __restrict__ ln_hg,
                       const float* __restrict__ ln_hb, const float* __restrict__ ln_cg,
                       const float* __restrict__ ln_cb) {
    __shared__ float wsh[32 * 128];
    __shared__ float gsh[32 * 32];
    __shared__ float rmsh[32];
    int t = threadIdx.x;
    for (int idx = t; idx < 4096; idx += 256) wsh[idx] = whh[idx];
    for (int idx = t; idx < 1024; idx += 256) gsh[idx] = g_gram[idx];
    if (t < 32) rmsh[t] = g_rm[t];
    __syncthreads();
    int lane = t & 31, w = t >> 5;
    int b = blockIdx.x * 8 + w;
    float h = 0.f, c = 0.f;
    float hg[4], hb[4];
#pragma unroll
    for (int g = 0; g < 4; g++) {
        int cc = g * 32 + lane;
        hg[g] = ln_hg[cc];
        hb[g] = ln_hb[cc];
    }
    float cgm = ln_cg[lane], cbm = ln_cb[lane];
    float gxr[4];
#pragma unroll
    for (int g = 0; g < 4; g++) gxr[g] = g_gx[(size_t)b * 128 + g * 32 + lane];
    for (int i = 0; i < SEQN; i++) {
        float gxn[4];
        if (i + 1 < SEQN) {
            size_t rn = (size_t)(i + 1) * BSZ + b;
#pragma unroll
            for (int g = 0; g < 4; g++) gxn[g] = g_gx[rn * 128 + g * 32 + lane];
        }
        float acc[4] = {0.f, 0.f, 0.f, 0.f};
        float accM = 0.f, wv = 0.f;
#pragma unroll
        for (int k = 0; k < 32; k++) {
            float hk = __shfl_sync(0xffffffffu, h, k);
#pragma unroll
            for (int g = 0; g < 4; g++) acc[g] += hk * wsh[k * 128 + g * 32 + lane];
            accM = fmaf(hk, rmsh[k], accM);
            wv = fmaf(hk, gsh[k * 32 + lane], wv);
        }
        float m = accM;
        float q = wredsum(h * wv);
        float v = fmaxf(q * (1.f / 128.f) - m * m, 0.f);
        float rs = rsqrtf(v + 1e-5f);
        float gate[4];
#pragma unroll
        for (int g = 0; g < 4; g++) gate[g] = gxr[g] + (acc[g] - m) * rs * hg[g] + hb[g];
        float ii = siga(gate[0]);
        float ff = siga(gate[1]);
        float gg = tanha(gate[2]);
        float oo = siga(gate[3]);
        float cn = ff * c + ii * gg;
        float s1 = cn, s2 = cn * cn;
#pragma unroll
        for (int o = 16; o; o >>= 1) {
            s1 += __shfl_xor_sync(0xffffffffu, s1, o);
            s2 += __shfl_xor_sync(0xffffffffu, s2, o);
        }
        float mc = s1 * (1.f / 32.f);
        float vc = fmaxf(s2 * (1.f / 32.f) - mc * mc, 0.f);
        c = (cn - mc) * rsqrtf(vc + 1e-5f) * cgm + cbm;
        h = oo * tanha(c);
        g_q[((size_t)i * BSZ + b) * DK + lane] = h;
#pragma unroll
        for (int g = 0; g < 4; g++) gxr[g] = gxn[g];
    }
}

// ------------------- logits + mask (bf16 keys, grid BSZ x 2) --------------------
__global__ void k_logits(const int* __restrict__ en_arr, float* __restrict__ out) {
    __shared__ float Qsh[64 * 32];
    __shared__ float Ksh[256 * 34];
    __shared__ int rsh[256];
    int t = threadIdx.x;
    int b = blockIdx.x;
    int tile = blockIdx.y;
    int en = en_arr[b];
    for (int idx = t; idx < 2048; idx += 256) {
        int s = idx >> 5, k = idx & 31;
        Qsh[idx] = g_q[((size_t)s * BSZ + b) * 32 + k];
    }
    const u64* Q2 = (const u64*)Qsh;
    int n0 = tile * 256;
    const __nv_bfloat162* keyv = (const __nv_bfloat162*)g_key;
    for (int idx = t; idx < 4096; idx += 256) {
        int n = idx >> 4, k2 = idx & 15;
        __nv_bfloat162 kv = keyv[((size_t)b * ENT + n0 + n) * 16 + k2];
        float2 f = __bfloat1622float2(kv);
        Ksh[n * 34 + k2 * 2] = f.x;
        Ksh[n * 34 + k2 * 2 + 1] = f.y;
    }
    rsh[t] = g_removed[(size_t)b * ENP1 + n0 + t];
    __syncthreads();
    u64 kreg[16];
#pragma unroll
    for (int kp = 0; kp < 16; kp++) {
        float2 kk = *(const float2*)&Ksh[t * 34 + kp * 2];
        asm("mov.b64 %0,{%1,%2};" : "=l"(kreg[kp]) : "f"(kk.x), "f"(kk.y));
    }
    int rstep = rsh[t];
    int n = n0 + t;
    for (int s = 0; s < SEQN; s++) {
        u64 a0 = 0ull, a1 = 0ull;
#pragma unroll
        for (int kp = 0; kp < 16; kp += 2) {
            fma2(a0, kreg[kp], Q2[s * 16 + kp]);
            fma2(a1, kreg[kp + 1], Q2[s * 16 + kp + 1]);
        }
        float2 f0 = up2(a0), f1 = up2(a1);
        float dot = (f0.x + f0.y) + (f1.x + f1.y);
        bool keep = (n < en) ? (rstep > s) : ((n == en) ? (s >= 1 && rstep > s) : false);
        out[((size_t)b * SEQN + s) * ENP1 + n] = keep ? dot : -1e9f;
    }
    if (tile == 1 && t < SEQN) out[((size_t)b * SEQN + t) * ENP1 + 512] = -1e9f;
}

// ------------------------------- launch ----------------------------------------
extern "C" void kernel_launch(void* const* d_in, const int* in_sizes, int n_in,
                              void* d_out, int out_size) {
    const float* ent = (const float*)d_in[0];
    const float* ar = (const float*)d_in[1];
    const int* entity_num = (const int*)d_in[2];
    const int* sel = (const int*)d_in[3];
    const int* selnum = (const int*)d_in[4];
    const float* key_w = (const float*)d_in[5];
    const float* key_b = (const float*)d_in[6];
    const float* q1w = (const float*)d_in[7];
    const float* q1b = (const float*)d_in[8];
    const float* q2w = (const float*)d_in[9];
    const float* q2b = (const float*)d_in[10];
    const float* e1w = (const float*)d_in[11];
    const float* e1b = (const float*)d_in[12];
    const float* e2w = (const float*)d_in[13];
    const float* e2b = (const float*)d_in[14];
    const float* endv = (const float*)d_in[15];
    const float* wih = (const float*)d_in[16];
    const float* whh = (const float*)d_in[17];
    const float* ln_ig = (const float*)d_in[18];
    const float* ln_ib = (const float*)d_in[19];
    const float* ln_hg = (const float*)d_in[20];
    const float* ln_hb = (const float*)d_in[21];
    const float* ln_cg = (const float*)d_in[22];
    const float* ln_cb = (const float*)d_in[23];
    float* out = (float*)d_out;

    void *pKey, *pBase, *pBasec, *pW2, *pC2;
    cudaGetSymbolAddress(&pKey, g_key);
    cudaGetSymbolAddress(&pBase, g_base);
    cudaGetSymbolAddress(&pBasec, g_basec);
    cudaGetSymbolAddress(&pW2, g_W2b);
    cudaGetSymbolAddress(&pC2, g_c2);

    static cudaStream_t sB = 0, sC = 0, sD = 0;
    static cudaEvent_t eFork = 0, eB = 0, eW2 = 0, eKey = 0, eGr = 0;
    if (!sB) {
        int lo, hi;
        cudaDeviceGetStreamPriorityRange(&lo, &hi);
        cudaStreamCreateWithFlags(&sB, cudaStreamNonBlocking);
        cudaStreamCreateWithFlags(&sC, cudaStreamNonBlocking);
        cudaStreamCreateWithPriority(&sD, cudaStreamNonBlocking, lo);
        cudaEventCreateWithFlags(&eFork, cudaEventDisableTiming);
        cudaEventCreateWithFlags(&eB, cudaEventDisableTiming);
        cudaEventCreateWithFlags(&eW2, cudaEventDisableTiming);
        cudaEventCreateWithFlags(&eKey, cudaEventDisableTiming);
        cudaEventCreateWithFlags(&eGr, cudaEventDisableTiming);
        cudaFuncSetAttribute(k_fused, cudaFuncAttributeMaxDynamicSharedMemorySize,
                             SMF_BYTES);
    }

    cudaEventRecord(eFork, 0);
    cudaStreamWaitEvent(sB, eFork, 0);
    cudaStreamWaitEvent(sC, eFork, 0);
    cudaStreamWaitEvent(sD, eFork, 0);

    k_selkey<<<BSZ, 256>>>(ent, key_w, key_b, sel, entity_num, selnum);
    k_c2<<<8, 256, 0, sB>>>(e2b, q1w);
    k_mma<32, 7><<<dim3(BSZ / 64, DF / 32), 256, 0, sB>>>(
        ar, q1w, q1b, (float*)pBase, DIN, DF, (const float*)pC2, nullptr, (float*)pBasec);
    cudaEventRecord(eB, sB);
    k_cvt<<<40, 256, 0, sC>>>(e1w, q2w, wih);
    k_mma<32, 6><<<dim3(DF / 64, DF / 32), 256, 0, sC>>>(
        e2w, q1w, nullptr, (float*)pW2, DIN, DF, nullptr, nullptr, nullptr);
    cudaEventRecord(eW2, sC);

    cudaStreamWaitEvent(0, eB, 0);
    cudaStreamWaitEvent(0, eW2, 0);
    k_fused<<<SEQN * BSZ / 128, 256, SMF_BYTES>>>(e1b, q2b, ln_ig, ln_ib);

    k_gram<<<1, 256, 0, sC>>>(whh);
    cudaEventRecord(eGr, sC);
    k_mma<32, 2><<<dim3(BSZ * ENT / 64, 1), 256, 0, sD>>>(
        ent, key_w, key_b, (float*)pKey, DF, DK, endv, entity_num, nullptr);
    cudaEventRecord(eKey, sD);

    cudaStreamWaitEvent(0, eGr, 0);
    k_lstm<<<BSZ / 8, 256>>>(whh, ln_hg, ln_hb, ln_cg, ln_cb);
    cudaStreamWaitEvent(0, eKey, 0);
    k_logits<<<dim3(BSZ, 2), 256>>>(entity_num, out);
    (void)in_sizes;
    (void)n_in;
    (void)out_size;
}